// round 10
// baseline (speedup 1.0000x reference)
#include <cuda_runtime.h>
#include <cuda_fp16.h>
#include <cstdint>

#define NDIM 4096
#define NB   32
#define BSZ  128
#define LAT  64
#define NCOL (NB * LAT)   // 2048
#define MAXIT (NDIM * NB)

// Static device scratch.
__device__ __half g_Wh[2][(size_t)NDIM * NDIM];       // W fp16 hi/lo split
__device__ __half g_Mt[2][(size_t)NCOL * NDIM];       // Mt[n,k]=M[k,n]; hi/lo fp16
__device__ __half g_WeTh[2][LAT * BSZ];               // WeT[t,c]=We[c,t]; hi/lo
__device__ float g_Y[(size_t)NDIM * NCOL];
__device__ float g_H[(size_t)NB * NB * LAT * LAT];    // H[jb][jj][u][t] (jj>jb valid)
__device__ float g_What[(size_t)NDIM * NDIM];         // valid only where flag set
__device__ unsigned char g_flags[NDIM * NB];
__device__ int g_cnt;
__device__ int g_items[MAXIT];
__device__ float g_yhl[(size_t)MAXIT * LAT];

// ---------------------------------------------------------------------------
// Base-target helpers (sm_80+)
// ---------------------------------------------------------------------------
__device__ __forceinline__ uint32_t smem_u32(const void* p) {
    uint32_t a;
    asm("{ .reg .u64 t; cvta.to.shared.u64 t, %1; cvt.u32.u64 %0, t; }" : "=r"(a) : "l"(p));
    return a;
}
#define CP_ASYNC16(s, g) asm volatile("cp.async.cg.shared.global [%0], [%1], 16;" :: "r"(s), "l"(g))
#define CP_COMMIT()      asm volatile("cp.async.commit_group;" ::: "memory")
#define CP_WAIT(n)       asm volatile("cp.async.wait_group %0;" :: "n"(n) : "memory")

__device__ __forceinline__ void ldm_x4(uint32_t addr, uint32_t r[4]) {
    asm volatile("ldmatrix.sync.aligned.m8n8.x4.shared.b16 {%0,%1,%2,%3}, [%4];"
                 : "=r"(r[0]), "=r"(r[1]), "=r"(r[2]), "=r"(r[3]) : "r"(addr));
}
__device__ __forceinline__ void mma_f16(float* c, const uint32_t a[4], uint32_t b0, uint32_t b1) {
    asm volatile(
        "mma.sync.aligned.m16n8k16.row.col.f32.f16.f16.f32 "
        "{%0,%1,%2,%3}, {%4,%5,%6,%7}, {%8,%9}, {%0,%1,%2,%3};"
        : "+f"(c[0]), "+f"(c[1]), "+f"(c[2]), "+f"(c[3])
        : "r"(a[0]), "r"(a[1]), "r"(a[2]), "r"(a[3]), "r"(b0), "r"(b1));
}
__device__ __forceinline__ void split2h(float v, __half& hi, __half& lo) {
    hi = __float2half_rn(v);
    lo = __float2half_rn(v - __half2float(hi));
}

#define RS 80   // smem row stride: 32 fp16 (64B) + 16B pad

// ---------------------------------------------------------------------------
// kernPrep: W fp32 -> fp16 hi/lo (blocks 0..8191), WeT split (8192..8223).
// ---------------------------------------------------------------------------
__global__ void kernPrep(const float* __restrict__ W, const float* __restrict__ We) {
    int b = blockIdx.x;
    if (b < 8192) {
        size_t idx = (size_t)b * 256 + threadIdx.x;   // per 8 elems
        const float4* s = reinterpret_cast<const float4*>(W) + idx * 2;
        float4 a = s[0], c = s[1];
        float v[8] = {a.x, a.y, a.z, a.w, c.x, c.y, c.z, c.w};
        __half h[8], l[8];
#pragma unroll
        for (int q = 0; q < 8; ++q) split2h(v[q], h[q], l[q]);
        *reinterpret_cast<uint4*>(g_Wh[0] + idx * 8) = *reinterpret_cast<uint4*>(h);
        *reinterpret_cast<uint4*>(g_Wh[1] + idx * 8) = *reinterpret_cast<uint4*>(l);
    } else {
        int idx = (b - 8192) * 256 + threadIdx.x;     // 0..8191
        int t = idx >> 7, c = idx & 127;
        __half h, l;
        split2h(We[c * LAT + t], h, l);
        g_WeTh[0][idx] = h;
        g_WeTh[1][idx] = l;
    }
}

// ---------------------------------------------------------------------------
// kernG: builds the FULL Mt (fp16 hi+lo).
//   kt > j : G block via 3-term split fp16 HMMA;  kt == j: diag We;  kt < j: 0
// Grid (32 kt, 32 j), 128 threads, smem 30720 B.
// ---------------------------------------------------------------------------
__global__ void __launch_bounds__(128, 4) kernG(const float* __restrict__ L,
                                                const float* __restrict__ We) {
    int kt = blockIdx.x, j = blockIdx.y;
    int tid = threadIdx.x;
    int jn = j * LAT, s = j * BSZ;

    if (kt < j) {
        uint4 z = make_uint4(0, 0, 0, 0);
        for (int i = tid; i < 64 * 16; i += 128) {
            int rr = i >> 4, c = i & 15;
            size_t o = (size_t)(jn + rr) * NDIM + kt * BSZ + c * 8;
            *reinterpret_cast<uint4*>(g_Mt[0] + o) = z;
            *reinterpret_cast<uint4*>(g_Mt[1] + o) = z;
        }
        return;
    }
    if (kt == j) {
        for (int n = 0; n < LAT; ++n) {
            __half h, l;
            split2h(We[tid * LAT + n], h, l);
            size_t o = (size_t)(jn + n) * NDIM + s + tid;
            g_Mt[0][o] = h;
            g_Mt[1][o] = l;
        }
        return;
    }

    extern __shared__ __align__(128) char sm[];
    uint32_t sb = smem_u32(sm);
    uint32_t sA[2] = {sb, sb + 5120};
    uint32_t sB[2] = {sb + 10240, sb + 20480};
    int wid = tid >> 5, lane = tid & 31;
    int k0g = kt * BSZ;
    int wm = (wid & 1) * 32, wn = (wid >> 1) * 64;

    float acc[2][8][4];
#pragma unroll
    for (int i = 0; i < 2; ++i)
#pragma unroll
        for (int q = 0; q < 8; ++q)
#pragma unroll
            for (int z = 0; z < 4; ++z) acc[i][q][z] = 0.f;

    for (int it = 0; it < 4; ++it) {            // K=128, BK=32
        int kk = it * 32;
#pragma unroll
        for (int q = 0; q < 4; ++q) {
            int id = tid + q * 128;
            int prec = id >> 8, rem = id & 255, row = rem >> 2, ch = rem & 3;
            CP_ASYNC16(sA[prec] + row * RS + ch * 16,
                       g_WeTh[prec] + row * BSZ + kk + ch * 8);
        }
        CP_COMMIT();
#pragma unroll
        for (int q = 0; q < 8; ++q) {           // B: L fp32 -> split fp16 in-reg
            int id = tid + q * 128;
            int row = id >> 3, c = (id & 7) * 4;
            float4 v = *reinterpret_cast<const float4*>(
                L + (size_t)(k0g + row) * NDIM + s + kk + c);
            __half h0, l0, h1, l1, h2, l2, h3, l3;
            split2h(v.x, h0, l0); split2h(v.y, h1, l1);
            split2h(v.z, h2, l2); split2h(v.w, h3, l3);
            __half2 hA = __halves2half2(h0, h1), hB = __halves2half2(h2, h3);
            __half2 lA = __halves2half2(l0, l1), lB = __halves2half2(l2, l3);
            uint2 uh, ul;
            uh.x = *reinterpret_cast<uint32_t*>(&hA); uh.y = *reinterpret_cast<uint32_t*>(&hB);
            ul.x = *reinterpret_cast<uint32_t*>(&lA); ul.y = *reinterpret_cast<uint32_t*>(&lB);
            *reinterpret_cast<uint2*>(sm + 10240 + row * RS + c * 2) = uh;
            *reinterpret_cast<uint2*>(sm + 20480 + row * RS + c * 2) = ul;
        }
        CP_WAIT(0);
        __syncthreads();

#pragma unroll
        for (int ks = 0; ks < 2; ++ks) {
            uint32_t ah[2][4];
#pragma unroll
            for (int mf = 0; mf < 2; ++mf)
                ldm_x4(sA[0] + (wm + mf * 16 + (lane & 15)) * RS + ks * 32 + (lane >> 4) * 16, ah[mf]);
            uint32_t bh[8][2];
#pragma unroll
            for (int p = 0; p < 4; ++p) {
                uint32_t r[4];
                int g = lane >> 3;
                int row = wn + p * 16 + ((g >> 1) << 3) + (lane & 7);
                ldm_x4(sB[0] + row * RS + ks * 32 + (g & 1) * 16, r);
                bh[p * 2][0] = r[0]; bh[p * 2][1] = r[1];
                bh[p * 2 + 1][0] = r[2]; bh[p * 2 + 1][1] = r[3];
            }
#pragma unroll
            for (int mf = 0; mf < 2; ++mf)
#pragma unroll
                for (int nf = 0; nf < 8; ++nf)
                    mma_f16(acc[mf][nf], ah[mf], bh[nf][0], bh[nf][1]);
            uint32_t al[2][4];
#pragma unroll
            for (int mf = 0; mf < 2; ++mf)
                ldm_x4(sA[1] + (wm + mf * 16 + (lane & 15)) * RS + ks * 32 + (lane >> 4) * 16, al[mf]);
#pragma unroll
            for (int mf = 0; mf < 2; ++mf)
#pragma unroll
                for (int nf = 0; nf < 8; ++nf)
                    mma_f16(acc[mf][nf], al[mf], bh[nf][0], bh[nf][1]);
            uint32_t bl[8][2];
#pragma unroll
            for (int p = 0; p < 4; ++p) {
                uint32_t r[4];
                int g = lane >> 3;
                int row = wn + p * 16 + ((g >> 1) << 3) + (lane & 7);
                ldm_x4(sB[1] + row * RS + ks * 32 + (g & 1) * 16, r);
                bl[p * 2][0] = r[0]; bl[p * 2][1] = r[1];
                bl[p * 2 + 1][0] = r[2]; bl[p * 2 + 1][1] = r[3];
            }
#pragma unroll
            for (int mf = 0; mf < 2; ++mf)
#pragma unroll
                for (int nf = 0; nf < 8; ++nf)
                    mma_f16(acc[mf][nf], ah[mf], bl[nf][0], bl[nf][1]);
        }
        __syncthreads();
    }

#pragma unroll
    for (int mf = 0; mf < 2; ++mf) {
        int t0 = wm + mf * 16 + (lane >> 2);
#pragma unroll
        for (int nf = 0; nf < 8; ++nf) {
            int kr = wn + nf * 8 + 2 * (lane & 3);
            __half h0, l0, h1, l1, h2, l2, h3, l3;
            split2h(acc[mf][nf][0], h0, l0);
            split2h(acc[mf][nf][1], h1, l1);
            split2h(acc[mf][nf][2], h2, l2);
            split2h(acc[mf][nf][3], h3, l3);
            size_t o0 = (size_t)(jn + t0) * NDIM + k0g + kr;
            size_t o1 = (size_t)(jn + t0 + 8) * NDIM + k0g + kr;
            *reinterpret_cast<__half2*>(g_Mt[0] + o0) = __halves2half2(h0, h1);
            *reinterpret_cast<__half2*>(g_Mt[1] + o0) = __halves2half2(l0, l1);
            *reinterpret_cast<__half2*>(g_Mt[0] + o1) = __halves2half2(h2, h3);
            *reinterpret_cast<__half2*>(g_Mt[1] + o1) = __halves2half2(l2, l3);
        }
    }
}

// ---------------------------------------------------------------------------
// kernH v2: H[jb][jj] = Wd @ G_block, fully in shared memory.
// Grid (32 jj, 32 jb) active iff jj > jb. 256 threads, 4x4 register tile.
// smem: Gs[64][65] + Wds[64][65] fp32 (padded, conflict-free) = 33.3KB.
// c processed in 2 chunks of 64. Also resets g_cnt (block (0,0)).
// ---------------------------------------------------------------------------
__global__ void __launch_bounds__(256) kernH(const float* __restrict__ Wd) {
    int jj = blockIdx.x, jb = blockIdx.y;
    if (jj <= jb) {
        if (jj == 0 && jb == 0 && threadIdx.x == 0) g_cnt = 0;
        return;
    }
    __shared__ float Gs[64][65];    // Gs[c][t]
    __shared__ float Wds[64][65];   // Wds[u][c]
    int tid = threadIdx.x;
    int tu = tid >> 4, tt = tid & 15;   // u-group, t-group (4 each)

    float acc[4][4];
#pragma unroll
    for (int i = 0; i < 4; ++i)
#pragma unroll
        for (int q = 0; q < 4; ++q) acc[i][q] = 0.f;

    for (int cc = 0; cc < 2; ++cc) {
        __syncthreads();
#pragma unroll
        for (int i = 0; i < 16; ++i) {          // 64x64 / 256
            int idx = i * 256 + tid;
            int a = idx >> 6, c = idx & 63;     // a = t for Gs, a = u for Wds
            size_t o = (size_t)(jb * LAT + a) * NDIM + jj * BSZ + cc * 64 + c;
            Gs[c][a] = __half2float(g_Mt[0][o]) + __half2float(g_Mt[1][o]);
            Wds[a][c] = Wd[a * BSZ + cc * 64 + c];
        }
        __syncthreads();
#pragma unroll 4
        for (int c = 0; c < 64; ++c) {
            float w[4], g[4];
#pragma unroll
            for (int i = 0; i < 4; ++i) w[i] = Wds[tu * 4 + i][c];
#pragma unroll
            for (int q = 0; q < 4; ++q) g[q] = Gs[c][tt * 4 + q];
#pragma unroll
            for (int i = 0; i < 4; ++i)
#pragma unroll
                for (int q = 0; q < 4; ++q)
                    acc[i][q] = fmaf(w[i], g[q], acc[i][q]);
        }
    }

    size_t hb = (((size_t)jb * NB + jj) * LAT) * LAT;
#pragma unroll
    for (int i = 0; i < 4; ++i)
#pragma unroll
        for (int q = 0; q < 4; ++q)
            g_H[hb + (size_t)(tu * 4 + i) * LAT + tt * 4 + q] = acc[i][q];
}

// ---------------------------------------------------------------------------
// kernGemmY: Y = W @ M^T, 3-term split fp16 HMMA, DOUBLE-BUFFERED cp.async.
// BM=128 BN=128 BK=32, 256 thr. 2 stages x 40960 B = 81920 B dynamic smem
// (opt-in via cudaFuncSetAttribute). k starts at n0*2 (triangular M).
// ---------------------------------------------------------------------------
#define GY_STG 40960
__global__ void __launch_bounds__(256, 2) kernGemmY() {
    extern __shared__ __align__(128) char sm[];
    uint32_t sb = smem_u32(sm);
    int tid = threadIdx.x, wid = tid >> 5, lane = tid & 31;
    int m0 = blockIdx.x * 128, n0 = blockIdx.y * 128;
    int kst = n0 * 2;
    int niter = (NDIM - kst) / 32;
    int wm = (wid & 1) * 64, wn = (wid >> 1) * 32;

    float acc[4][4][4];
#pragma unroll
    for (int i = 0; i < 4; ++i)
#pragma unroll
        for (int q = 0; q < 4; ++q)
#pragma unroll
            for (int z = 0; z < 4; ++z) acc[i][q][z] = 0.f;

    auto issue = [&](int it) {
        int k0 = kst + it * 32;
        uint32_t base = sb + (it & 1) * GY_STG;
#pragma unroll
        for (int q = 0; q < 4; ++q) {
            int id = tid + q * 256;
            int prec = id >> 9, rem = id & 511, row = rem >> 2, ch = rem & 3;
            CP_ASYNC16(base + prec * 10240 + row * RS + ch * 16,
                       g_Wh[prec] + (size_t)(m0 + row) * NDIM + k0 + ch * 8);
            CP_ASYNC16(base + 20480 + prec * 10240 + row * RS + ch * 16,
                       g_Mt[prec] + (size_t)(n0 + row) * NDIM + k0 + ch * 8);
        }
        CP_COMMIT();
    };

    issue(0);
    for (int it = 0; it < niter; ++it) {
        if (it + 1 < niter) { issue(it + 1); CP_WAIT(1); }
        else                { CP_WAIT(0); }
        __syncthreads();
        uint32_t base = sb + (it & 1) * GY_STG;
        uint32_t sA0 = base, sA1 = base + 10240, sB0 = base + 20480, sB1 = base + 30720;
#pragma unroll
        for (int ks = 0; ks < 2; ++ks) {
            uint32_t ah[4][4];
#pragma unroll
            for (int mf = 0; mf < 4; ++mf)
                ldm_x4(sA0 + (wm + mf * 16 + (lane & 15)) * RS + ks * 32 + (lane >> 4) * 16, ah[mf]);
            uint32_t bh[4][2];
#pragma unroll
            for (int p = 0; p < 2; ++p) {
                uint32_t r[4];
                int g = lane >> 3;
                int row = wn + p * 16 + ((g >> 1) << 3) + (lane & 7);
                ldm_x4(sB0 + row * RS + ks * 32 + (g & 1) * 16, r);
                bh[p * 2][0] = r[0]; bh[p * 2][1] = r[1];
                bh[p * 2 + 1][0] = r[2]; bh[p * 2 + 1][1] = r[3];
            }
#pragma unroll
            for (int mf = 0; mf < 4; ++mf)
#pragma unroll
                for (int nf = 0; nf < 4; ++nf)
                    mma_f16(acc[mf][nf], ah[mf], bh[nf][0], bh[nf][1]);
            uint32_t al[4][4];
#pragma unroll
            for (int mf = 0; mf < 4; ++mf)
                ldm_x4(sA1 + (wm + mf * 16 + (lane & 15)) * RS + ks * 32 + (lane >> 4) * 16, al[mf]);
#pragma unroll
            for (int mf = 0; mf < 4; ++mf)
#pragma unroll
                for (int nf = 0; nf < 4; ++nf)
                    mma_f16(acc[mf][nf], al[mf], bh[nf][0], bh[nf][1]);
            uint32_t bl[4][2];
#pragma unroll
            for (int p = 0; p < 2; ++p) {
                uint32_t r[4];
                int g = lane >> 3;
                int row = wn + p * 16 + ((g >> 1) << 3) + (lane & 7);
                ldm_x4(sB1 + row * RS + ks * 32 + (g & 1) * 16, r);
                bl[p * 2][0] = r[0]; bl[p * 2][1] = r[1];
                bl[p * 2 + 1][0] = r[2]; bl[p * 2 + 1][1] = r[3];
            }
#pragma unroll
            for (int mf = 0; mf < 4; ++mf)
#pragma unroll
                for (int nf = 0; nf < 4; ++nf)
                    mma_f16(acc[mf][nf], ah[mf], bl[nf][0], bl[nf][1]);
        }
        __syncthreads();
    }

#pragma unroll
    for (int mf = 0; mf < 4; ++mf) {
        int row = m0 + wm + mf * 16 + (lane >> 2);
#pragma unroll
        for (int nf = 0; nf < 4; ++nf) {
            int col = n0 + wn + nf * 8 + 2 * (lane & 3);
            *reinterpret_cast<float2*>(g_Y + (size_t)row * NCOL + col) =
                make_float2(acc[mf][nf][0], acc[mf][nf][1]);
            *reinterpret_cast<float2*>(g_Y + (size_t)(row + 8) * NCOL + col) =
                make_float2(acc[mf][nf][2], acc[mf][nf][3]);
        }
    }
}

// ---------------------------------------------------------------------------
// kernSteps: 32 fused sequential steps, ENTIRELY in 64-dim latent space.
// Block = 4 rows x 64 threads. yhat in shared; feedback = yhat @ H.
// Emits flags + work items (r,jb) with yhat payload for kernWhat.
// ---------------------------------------------------------------------------
__global__ void kernSteps(const float* __restrict__ rn) {
    int rloc = threadIdx.x >> 6, t = threadIdx.x & 63;
    int r = blockIdx.x * 4 + rloc;

    __shared__ float yh[4][NB][LAT];    // 32KB
    __shared__ int s_nz[4], s_idx[4];
    __shared__ unsigned char fl[4][NB];

    float rnv = rn[r];
    if (t < NB) fl[rloc][t] = 0;

    for (int jb = NB - 1; jb >= 0; --jb) {
        __syncthreads();
        if (t == 0) { s_nz[rloc] = 0; s_idx[rloc] = -1; }
        __syncthreads();

        float y = g_Y[(size_t)r * NCOL + jb * LAT + t];
        for (int jj = jb + 1; jj < NB; ++jj) {
            if (fl[rloc][jj]) {
                const float* hp = g_H + (((size_t)jb * NB + jj) * LAT) * LAT + t;
                const float* yv = yh[rloc][jj];
#pragma unroll 8
                for (int u = 0; u < LAT; ++u)
                    y -= yv[u] * hp[(size_t)u * LAT];
            }
        }
        float yhv = rintf(y / rnv);
        yh[rloc][jb][t] = yhv;
        if (yhv != 0.f) s_nz[rloc] = 1;       // benign race
        __syncthreads();

        int nz = s_nz[rloc];
        if (t == 0) {
            fl[rloc][jb] = (unsigned char)nz;
            g_flags[r * NB + jb] = (unsigned char)nz;
            if (nz) s_idx[rloc] = atomicAdd(&g_cnt, 1);
        }
        __syncthreads();
        if (nz) {
            int idx = s_idx[rloc];
            if (t == 0) g_items[idx] = (r << 5) | jb;
            g_yhl[(size_t)idx * LAT + t] = yhv;
        }
    }
}

// ---------------------------------------------------------------------------
// kernWhat: materialize W_hat blocks for flagged items only.
// ---------------------------------------------------------------------------
__global__ void kernWhat(const float* __restrict__ Wd) {
    __shared__ float s_y[LAT];
    int tid = threadIdx.x;
    int cnt = g_cnt;
    for (int i = blockIdx.x; i < cnt; i += gridDim.x) {
        int item = g_items[i];
        int r = item >> 5, jb = item & 31;
        if (tid < LAT) s_y[tid] = g_yhl[(size_t)i * LAT + tid];
        __syncthreads();
        float x = 0.f;
#pragma unroll 8
        for (int u = 0; u < LAT; ++u)
            x = fmaf(s_y[u], Wd[u * BSZ + tid], x);
        g_What[(size_t)r * NDIM + jb * BSZ + tid] = x;
        __syncthreads();
    }
}

// ---------------------------------------------------------------------------
// kernOut: out = bias + x @ (W_hat * rn)^T, skipping exactly-zero k-blocks.
// ---------------------------------------------------------------------------
__global__ void kernOut(const float* __restrict__ x, const float* __restrict__ rn,
                        const float* __restrict__ bias, float* __restrict__ out) {
    __shared__ __align__(16) float xs[16][64];
    __shared__ __align__(16) float ws[16][64];
    __shared__ unsigned char shf[NB];

    int b0 = blockIdx.x * 64;
    int m0 = blockIdx.y * 64;
    int tid = threadIdx.x;

    if (tid < NB) {
        unsigned char f = 0;
        for (int mm = 0; mm < 64; ++mm) f |= g_flags[(m0 + mm) * NB + tid];
        shf[tid] = f;
    }
    __syncthreads();

    int tr = tid >> 4, tc = tid & 15;
    int l_r = tid >> 2, l_q = (tid & 3) * 4;

    float acc[4][4];
#pragma unroll
    for (int i = 0; i < 4; ++i)
#pragma unroll
        for (int q = 0; q < 4; ++q) acc[i][q] = 0.f;

    float rnm = rn[m0 + l_r];

    for (int jj = 0; jj < NB; ++jj) {
        if (!shf[jj]) continue;
        for (int k0 = 0; k0 < BSZ; k0 += 16) {
            float4 xv = *reinterpret_cast<const float4*>(x + (size_t)(b0 + l_r) * NDIM + jj * BSZ + k0 + l_q);
            xs[l_q + 0][l_r] = xv.x; xs[l_q + 1][l_r] = xv.y;
            xs[l_q + 2][l_r] = xv.z; xs[l_q + 3][l_r] = xv.w;
            float4 wv = make_float4(0.f, 0.f, 0.f, 0.f);
            if (g_flags[(m0 + l_r) * NB + jj])
                wv = *reinterpret_cast<const float4*>(g_What + (size_t)(m0 + l_r) * NDIM + jj * BSZ + k0 + l_q);
            ws[l_q + 0][l_r] = wv.x * rnm; ws[l_q + 1][l_r] = wv.y * rnm;
            ws[l_q + 2][l_r] = wv.z * rnm; ws[l_q + 3][l_r] = wv.w * rnm;
            __syncthreads();
#pragma unroll
            for (int kk = 0; kk < 16; ++kk) {
                float4 a4 = *reinterpret_cast<const float4*>(&xs[kk][tr * 4]);
                float4 b4 = *reinterpret_cast<const float4*>(&ws[kk][tc * 4]);
                float a[4] = {a4.x, a4.y, a4.z, a4.w};
                float b[4] = {b4.x, b4.y, b4.z, b4.w};
#pragma unroll
                for (int i = 0; i < 4; ++i)
#pragma unroll
                    for (int q = 0; q < 4; ++q)
                        acc[i][q] = fmaf(a[i], b[q], acc[i][q]);
            }
            __syncthreads();
        }
    }

#pragma unroll
    for (int i = 0; i < 4; ++i) {
        int b = b0 + tr * 4 + i;
#pragma unroll
        for (int q = 0; q < 4; ++q) {
            int m = m0 + tc * 4 + q;
            out[(size_t)b * NDIM + m] = bias[m] + acc[i][q];
        }
    }
}

// ---------------------------------------------------------------------------
// kernel_launch: inputs (metadata order): x, weight, bias, row_norm, L, We, Wd
// ---------------------------------------------------------------------------
extern "C" void kernel_launch(void* const* d_in, const int* in_sizes, int n_in,
                              void* d_out, int out_size) {
    (void)in_sizes; (void)n_in; (void)out_size;
    const float* x      = (const float*)d_in[0];
    const float* weight = (const float*)d_in[1];
    const float* bias   = (const float*)d_in[2];
    const float* rn     = (const float*)d_in[3];
    const float* L      = (const float*)d_in[4];
    const float* We     = (const float*)d_in[5];
    const float* Wd     = (const float*)d_in[6];
    float* out          = (float*)d_out;

    static bool attr_set = false;
    if (!attr_set) {
        cudaFuncSetAttribute(kernGemmY, cudaFuncAttributeMaxDynamicSharedMemorySize, 2 * GY_STG);
        attr_set = true;
    }

    kernPrep<<<8224, 256>>>(weight, We);                  // [0] W split, WeT split
    kernG<<<dim3(32, 32), 128, 30720>>>(L, We);           // [1] full Mt
    kernH<<<dim3(32, 32), 256>>>(Wd);                     // [2] latent feedback H (smem-tiled)
    kernGemmY<<<dim3(32, 16), 256, 2 * GY_STG>>>();       // [3] Y (double-buffered) <- profiled
    kernSteps<<<1024, 256>>>(rn);                         // [4] 32 steps in latent space
    kernWhat<<<1024, 128>>>(Wd);                          // [5] sparse W_hat blocks
    kernOut<<<dim3(64, 64), 256>>>(x, rn, bias, out);     // [6] output GEMM
}

// round 11
// speedup vs baseline: 1.6916x; 1.6916x over previous
#include <cuda_runtime.h>
#include <cuda_fp16.h>
#include <cstdint>

#define NDIM 4096
#define NB   32
#define BSZ  128
#define LAT  64
#define NCOL (NB * LAT)   // 2048
#define MAXIT (NDIM * NB)

// Static device scratch.
__device__ __half g_Wh[(size_t)NDIM * NDIM];          // W fp16 hi (GEMM operand)
__device__ __half g_Mt[2][(size_t)NCOL * NDIM];       // Mt[n,k]=M[k,n]; hi/lo fp16
__device__ __half g_WeTh[2][LAT * BSZ];               // WeT[t,c]=We[c,t]; hi/lo
__device__ float g_Y[(size_t)NDIM * NCOL];
__device__ float g_H[(size_t)NB * NB * LAT * LAT];    // H[jb][jj][u][t] (jj>jb valid)
__device__ float g_What[(size_t)NDIM * NDIM];         // valid only where flag set
__device__ unsigned char g_flags[NDIM * NB];
__device__ int g_cnt;
__device__ int g_items[MAXIT];
__device__ float g_yhl[(size_t)MAXIT * LAT];

// ---------------------------------------------------------------------------
// Base-target helpers (sm_80+)
// ---------------------------------------------------------------------------
__device__ __forceinline__ uint32_t smem_u32(const void* p) {
    uint32_t a;
    asm("{ .reg .u64 t; cvta.to.shared.u64 t, %1; cvt.u32.u64 %0, t; }" : "=r"(a) : "l"(p));
    return a;
}
#define CP_ASYNC16(s, g) asm volatile("cp.async.cg.shared.global [%0], [%1], 16;" :: "r"(s), "l"(g))
#define CP_COMMIT()      asm volatile("cp.async.commit_group;" ::: "memory")
#define CP_WAIT(n)       asm volatile("cp.async.wait_group %0;" :: "n"(n) : "memory")

__device__ __forceinline__ void ldm_x4(uint32_t addr, uint32_t r[4]) {
    asm volatile("ldmatrix.sync.aligned.m8n8.x4.shared.b16 {%0,%1,%2,%3}, [%4];"
                 : "=r"(r[0]), "=r"(r[1]), "=r"(r[2]), "=r"(r[3]) : "r"(addr));
}
__device__ __forceinline__ void mma_f16(float* c, const uint32_t a[4], uint32_t b0, uint32_t b1) {
    asm volatile(
        "mma.sync.aligned.m16n8k16.row.col.f32.f16.f16.f32 "
        "{%0,%1,%2,%3}, {%4,%5,%6,%7}, {%8,%9}, {%0,%1,%2,%3};"
        : "+f"(c[0]), "+f"(c[1]), "+f"(c[2]), "+f"(c[3])
        : "r"(a[0]), "r"(a[1]), "r"(a[2]), "r"(a[3]), "r"(b0), "r"(b1));
}
__device__ __forceinline__ void split2h(float v, __half& hi, __half& lo) {
    hi = __float2half_rn(v);
    lo = __float2half_rn(v - __half2float(hi));
}

#define RS 80   // smem row stride: 32 fp16 (64B) + 16B pad

// ---------------------------------------------------------------------------
// kernPrep: W fp32 -> fp16 hi (blocks 0..8191), WeT split (8192..8223).
// ---------------------------------------------------------------------------
__global__ void kernPrep(const float* __restrict__ W, const float* __restrict__ We) {
    int b = blockIdx.x;
    if (b < 8192) {
        size_t idx = (size_t)b * 256 + threadIdx.x;   // per 8 elems
        const float4* s = reinterpret_cast<const float4*>(W) + idx * 2;
        float4 a = s[0], c = s[1];
        float v[8] = {a.x, a.y, a.z, a.w, c.x, c.y, c.z, c.w};
        __half h[8];
#pragma unroll
        for (int q = 0; q < 8; ++q) h[q] = __float2half_rn(v[q]);
        *reinterpret_cast<uint4*>(g_Wh + idx * 8) = *reinterpret_cast<uint4*>(h);
    } else {
        int idx = (b - 8192) * 256 + threadIdx.x;     // 0..8191
        int t = idx >> 7, c = idx & 127;
        __half h, l;
        split2h(We[c * LAT + t], h, l);
        g_WeTh[0][idx] = h;
        g_WeTh[1][idx] = l;
    }
}

// ---------------------------------------------------------------------------
// kernG: builds the FULL Mt (fp16 hi+lo).
//   kt > j : G block via 3-term split fp16 HMMA;  kt == j: diag We;  kt < j: 0
// Grid (32 kt, 32 j), 128 threads, smem 30720 B.
// ---------------------------------------------------------------------------
__global__ void __launch_bounds__(128, 4) kernG(const float* __restrict__ L,
                                                const float* __restrict__ We) {
    int kt = blockIdx.x, j = blockIdx.y;
    int tid = threadIdx.x;
    int jn = j * LAT, s = j * BSZ;

    if (kt < j) {
        uint4 z = make_uint4(0, 0, 0, 0);
        for (int i = tid; i < 64 * 16; i += 128) {
            int rr = i >> 4, c = i & 15;
            size_t o = (size_t)(jn + rr) * NDIM + kt * BSZ + c * 8;
            *reinterpret_cast<uint4*>(g_Mt[0] + o) = z;
            *reinterpret_cast<uint4*>(g_Mt[1] + o) = z;
        }
        return;
    }
    if (kt == j) {
        for (int n = 0; n < LAT; ++n) {
            __half h, l;
            split2h(We[tid * LAT + n], h, l);
            size_t o = (size_t)(jn + n) * NDIM + s + tid;
            g_Mt[0][o] = h;
            g_Mt[1][o] = l;
        }
        return;
    }

    extern __shared__ __align__(128) char sm[];
    uint32_t sb = smem_u32(sm);
    uint32_t sA[2] = {sb, sb + 5120};
    uint32_t sB[2] = {sb + 10240, sb + 20480};
    int wid = tid >> 5, lane = tid & 31;
    int k0g = kt * BSZ;
    int wm = (wid & 1) * 32, wn = (wid >> 1) * 64;

    float acc[2][8][4];
#pragma unroll
    for (int i = 0; i < 2; ++i)
#pragma unroll
        for (int q = 0; q < 8; ++q)
#pragma unroll
            for (int z = 0; z < 4; ++z) acc[i][q][z] = 0.f;

    for (int it = 0; it < 4; ++it) {            // K=128, BK=32
        int kk = it * 32;
#pragma unroll
        for (int q = 0; q < 4; ++q) {
            int id = tid + q * 128;
            int prec = id >> 8, rem = id & 255, row = rem >> 2, ch = rem & 3;
            CP_ASYNC16(sA[prec] + row * RS + ch * 16,
                       g_WeTh[prec] + row * BSZ + kk + ch * 8);
        }
        CP_COMMIT();
#pragma unroll
        for (int q = 0; q < 8; ++q) {           // B: L fp32 -> split fp16 in-reg
            int id = tid + q * 128;
            int row = id >> 3, c = (id & 7) * 4;
            float4 v = *reinterpret_cast<const float4*>(
                L + (size_t)(k0g + row) * NDIM + s + kk + c);
            __half h0, l0, h1, l1, h2, l2, h3, l3;
            split2h(v.x, h0, l0); split2h(v.y, h1, l1);
            split2h(v.z, h2, l2); split2h(v.w, h3, l3);
            __half2 hA = __halves2half2(h0, h1), hB = __halves2half2(h2, h3);
            __half2 lA = __halves2half2(l0, l1), lB = __halves2half2(l2, l3);
            uint2 uh, ul;
            uh.x = *reinterpret_cast<uint32_t*>(&hA); uh.y = *reinterpret_cast<uint32_t*>(&hB);
            ul.x = *reinterpret_cast<uint32_t*>(&lA); ul.y = *reinterpret_cast<uint32_t*>(&lB);
            *reinterpret_cast<uint2*>(sm + 10240 + row * RS + c * 2) = uh;
            *reinterpret_cast<uint2*>(sm + 20480 + row * RS + c * 2) = ul;
        }
        CP_WAIT(0);
        __syncthreads();

#pragma unroll
        for (int ks = 0; ks < 2; ++ks) {
            uint32_t ah[2][4];
#pragma unroll
            for (int mf = 0; mf < 2; ++mf)
                ldm_x4(sA[0] + (wm + mf * 16 + (lane & 15)) * RS + ks * 32 + (lane >> 4) * 16, ah[mf]);
            uint32_t bh[8][2];
#pragma unroll
            for (int p = 0; p < 4; ++p) {
                uint32_t r[4];
                int g = lane >> 3;
                int row = wn + p * 16 + ((g >> 1) << 3) + (lane & 7);
                ldm_x4(sB[0] + row * RS + ks * 32 + (g & 1) * 16, r);
                bh[p * 2][0] = r[0]; bh[p * 2][1] = r[1];
                bh[p * 2 + 1][0] = r[2]; bh[p * 2 + 1][1] = r[3];
            }
#pragma unroll
            for (int mf = 0; mf < 2; ++mf)
#pragma unroll
                for (int nf = 0; nf < 8; ++nf)
                    mma_f16(acc[mf][nf], ah[mf], bh[nf][0], bh[nf][1]);
            uint32_t al[2][4];
#pragma unroll
            for (int mf = 0; mf < 2; ++mf)
                ldm_x4(sA[1] + (wm + mf * 16 + (lane & 15)) * RS + ks * 32 + (lane >> 4) * 16, al[mf]);
#pragma unroll
            for (int mf = 0; mf < 2; ++mf)
#pragma unroll
                for (int nf = 0; nf < 8; ++nf)
                    mma_f16(acc[mf][nf], al[mf], bh[nf][0], bh[nf][1]);
            uint32_t bl[8][2];
#pragma unroll
            for (int p = 0; p < 4; ++p) {
                uint32_t r[4];
                int g = lane >> 3;
                int row = wn + p * 16 + ((g >> 1) << 3) + (lane & 7);
                ldm_x4(sB[1] + row * RS + ks * 32 + (g & 1) * 16, r);
                bl[p * 2][0] = r[0]; bl[p * 2][1] = r[1];
                bl[p * 2 + 1][0] = r[2]; bl[p * 2 + 1][1] = r[3];
            }
#pragma unroll
            for (int mf = 0; mf < 2; ++mf)
#pragma unroll
                for (int nf = 0; nf < 8; ++nf)
                    mma_f16(acc[mf][nf], ah[mf], bl[nf][0], bl[nf][1]);
        }
        __syncthreads();
    }

#pragma unroll
    for (int mf = 0; mf < 2; ++mf) {
        int t0 = wm + mf * 16 + (lane >> 2);
#pragma unroll
        for (int nf = 0; nf < 8; ++nf) {
            int kr = wn + nf * 8 + 2 * (lane & 3);
            __half h0, l0, h1, l1, h2, l2, h3, l3;
            split2h(acc[mf][nf][0], h0, l0);
            split2h(acc[mf][nf][1], h1, l1);
            split2h(acc[mf][nf][2], h2, l2);
            split2h(acc[mf][nf][3], h3, l3);
            size_t o0 = (size_t)(jn + t0) * NDIM + k0g + kr;
            size_t o1 = (size_t)(jn + t0 + 8) * NDIM + k0g + kr;
            *reinterpret_cast<__half2*>(g_Mt[0] + o0) = __halves2half2(h0, h1);
            *reinterpret_cast<__half2*>(g_Mt[1] + o0) = __halves2half2(l0, l1);
            *reinterpret_cast<__half2*>(g_Mt[0] + o1) = __halves2half2(h2, h3);
            *reinterpret_cast<__half2*>(g_Mt[1] + o1) = __halves2half2(l2, l3);
        }
    }
}

// ---------------------------------------------------------------------------
// kernGemmY: Y = W @ M^T, SINGLE fp16 hh HMMA pass, fp32 accum.
// Precision guarded by the boundary-recompute in kernSteps (window 1e-3,
// hh error max ~1.3e-4). BM=128 BN=128 BK=32, 256 thr, double-buffered
// cp.async (2 x 20480 B = 40960, under 48KB). k starts at n0*2.
// ---------------------------------------------------------------------------
__global__ void __launch_bounds__(256, 2) kernGemmY() {
    extern __shared__ __align__(128) char sm[];
    const int TSZ = 128 * RS;                 // 10240
    const int STG = 2 * TSZ;                  // 20480 per stage (A + B)
    uint32_t sb = smem_u32(sm);
    int tid = threadIdx.x, wid = tid >> 5, lane = tid & 31;
    int m0 = blockIdx.x * 128, n0 = blockIdx.y * 128;
    int kst = n0 * 2;
    int niter = (NDIM - kst) / 32;
    int wm = (wid & 1) * 64, wn = (wid >> 1) * 32;

    float acc[4][4][4];
#pragma unroll
    for (int i = 0; i < 4; ++i)
#pragma unroll
        for (int q = 0; q < 4; ++q)
#pragma unroll
            for (int z = 0; z < 4; ++z) acc[i][q][z] = 0.f;

    {
        uint32_t s_a = sb, s_b = sb + TSZ;
#pragma unroll
        for (int q = 0; q < 2; ++q) {
            int id = tid + q * 256, row = id >> 2, ch = id & 3;
            CP_ASYNC16(s_a + row * RS + ch * 16, g_Wh + (size_t)(m0 + row) * NDIM + kst + ch * 8);
            CP_ASYNC16(s_b + row * RS + ch * 16, g_Mt[0] + (size_t)(n0 + row) * NDIM + kst + ch * 8);
        }
        CP_COMMIT();
    }

    for (int it = 0; it < niter; ++it) {
        if (it + 1 < niter) {
            int k0 = kst + (it + 1) * 32;
            uint32_t s_a = sb + ((it + 1) & 1) * STG, s_b = s_a + TSZ;
#pragma unroll
            for (int q = 0; q < 2; ++q) {
                int id = tid + q * 256, row = id >> 2, ch = id & 3;
                CP_ASYNC16(s_a + row * RS + ch * 16, g_Wh + (size_t)(m0 + row) * NDIM + k0 + ch * 8);
                CP_ASYNC16(s_b + row * RS + ch * 16, g_Mt[0] + (size_t)(n0 + row) * NDIM + k0 + ch * 8);
            }
            CP_COMMIT();
            CP_WAIT(1);
        } else {
            CP_WAIT(0);
        }
        __syncthreads();
        uint32_t s_a = sb + (it & 1) * STG, s_b = s_a + TSZ;
#pragma unroll
        for (int ks = 0; ks < 2; ++ks) {
            uint32_t a[4][4];
#pragma unroll
            for (int mf = 0; mf < 4; ++mf)
                ldm_x4(s_a + (wm + mf * 16 + (lane & 15)) * RS + ks * 32 + (lane >> 4) * 16, a[mf]);
            uint32_t b[4][2];
#pragma unroll
            for (int p = 0; p < 2; ++p) {
                uint32_t r[4];
                int g = lane >> 3;
                int row = wn + p * 16 + ((g >> 1) << 3) + (lane & 7);
                ldm_x4(s_b + row * RS + ks * 32 + (g & 1) * 16, r);
                b[p * 2][0] = r[0]; b[p * 2][1] = r[1];
                b[p * 2 + 1][0] = r[2]; b[p * 2 + 1][1] = r[3];
            }
#pragma unroll
            for (int mf = 0; mf < 4; ++mf)
#pragma unroll
                for (int nf = 0; nf < 4; ++nf)
                    mma_f16(acc[mf][nf], a[mf], b[nf][0], b[nf][1]);
        }
        __syncthreads();
    }

#pragma unroll
    for (int mf = 0; mf < 4; ++mf) {
        int row = m0 + wm + mf * 16 + (lane >> 2);
#pragma unroll
        for (int nf = 0; nf < 4; ++nf) {
            int col = n0 + wn + nf * 8 + 2 * (lane & 3);
            *reinterpret_cast<float2*>(g_Y + (size_t)row * NCOL + col) =
                make_float2(acc[mf][nf][0], acc[mf][nf][1]);
            *reinterpret_cast<float2*>(g_Y + (size_t)(row + 8) * NCOL + col) =
                make_float2(acc[mf][nf][2], acc[mf][nf][3]);
        }
    }
}

// ---------------------------------------------------------------------------
// kernH v2: H[jb][jj] = Wd @ G_block, smem-tiled (4x4 register tile).
// Grid (32 jj, 32 jb) active iff jj > jb. Also resets g_cnt (block (0,0)).
// ---------------------------------------------------------------------------
__global__ void __launch_bounds__(256) kernH(const float* __restrict__ Wd) {
    int jj = blockIdx.x, jb = blockIdx.y;
    if (jj <= jb) {
        if (jj == 0 && jb == 0 && threadIdx.x == 0) g_cnt = 0;
        return;
    }
    __shared__ float Gs[64][65];    // Gs[c][t]
    __shared__ float Wds[64][65];   // Wds[u][c]
    int tid = threadIdx.x;
    int tu = tid >> 4, tt = tid & 15;

    float acc[4][4];
#pragma unroll
    for (int i = 0; i < 4; ++i)
#pragma unroll
        for (int q = 0; q < 4; ++q) acc[i][q] = 0.f;

    for (int cc = 0; cc < 2; ++cc) {
        __syncthreads();
#pragma unroll
        for (int i = 0; i < 16; ++i) {
            int idx = i * 256 + tid;
            int a = idx >> 6, c = idx & 63;
            size_t o = (size_t)(jb * LAT + a) * NDIM + jj * BSZ + cc * 64 + c;
            Gs[c][a] = __half2float(g_Mt[0][o]) + __half2float(g_Mt[1][o]);
            Wds[a][c] = Wd[a * BSZ + cc * 64 + c];
        }
        __syncthreads();
#pragma unroll 4
        for (int c = 0; c < 64; ++c) {
            float w[4], g[4];
#pragma unroll
            for (int i = 0; i < 4; ++i) w[i] = Wds[tu * 4 + i][c];
#pragma unroll
            for (int q = 0; q < 4; ++q) g[q] = Gs[c][tt * 4 + q];
#pragma unroll
            for (int i = 0; i < 4; ++i)
#pragma unroll
                for (int q = 0; q < 4; ++q)
                    acc[i][q] = fmaf(w[i], g[q], acc[i][q]);
        }
    }

    size_t hb = (((size_t)jb * NB + jj) * LAT) * LAT;
#pragma unroll
    for (int i = 0; i < 4; ++i)
#pragma unroll
        for (int q = 0; q < 4; ++q)
            g_H[hb + (size_t)(tu * 4 + i) * LAT + tt * 4 + q] = acc[i][q];
}

// ---------------------------------------------------------------------------
// kernSteps v3: 32 fused sequential steps in latent space.
//  - feedback reads ONLY the nonzero rows of H (ballot masks): ~64x less traffic
//  - boundary guard (window 1e-3) with exact fp64 block-cooperative recompute
// Block = 4 rows x 64 threads, grid 1024.
// ---------------------------------------------------------------------------
__global__ void kernSteps(const float* __restrict__ rn, const float* __restrict__ W) {
    int tid = threadIdx.x;
    int rloc = tid >> 6, t = tid & 63;
    int r = blockIdx.x * 4 + rloc;

    __shared__ float yh[4][NB][LAT];          // 32KB
    __shared__ uint32_t msk[4][NB][2];        // nonzero-u masks
    __shared__ unsigned char fl[4][NB];
    __shared__ int s_nz[4], s_idx[4];
    __shared__ int ntrigB;
    __shared__ short s_trig[256];
    __shared__ double redd[256];              // 2KB

    float rnv = rn[r];
    if (t < NB) fl[rloc][t] = 0;

    for (int jb = NB - 1; jb >= 0; --jb) {
        __syncthreads();
        if (tid == 0) ntrigB = 0;
        if (t == 0) { s_nz[rloc] = 0; s_idx[rloc] = -1; }
        __syncthreads();

        float y0 = g_Y[(size_t)r * NCOL + jb * LAT + t];
        float fb = 0.f;
        for (int jj = jb + 1; jj < NB; ++jj) {
            if (fl[rloc][jj]) {
                const float* hb = g_H + ((size_t)(jb * NB + jj) * LAT) * LAT + t;
                const float* yv = yh[rloc][jj];
                uint32_t m = msk[rloc][jj][0];
                while (m) { int u = __ffs(m) - 1; m &= m - 1; fb = fmaf(yv[u], hb[(size_t)u * LAT], fb); }
                m = msk[rloc][jj][1];
                while (m) { int u = __ffs(m) + 31; m &= m - 1; fb = fmaf(yv[u], hb[(size_t)u * LAT], fb); }
            }
        }
        float y = (y0 - fb) / rnv;
        // Boundary guard: fp16-hh GEMM error on y0 is < ~1.5e-4; window 1e-3.
        if (fabsf(fabsf(y - rintf(y)) - 0.5f) < 1e-3f) {
            int slot = atomicAdd(&ntrigB, 1);
            s_trig[slot] = (short)tid;
        }
        __syncthreads();
        int nt = ntrigB;
        for (int i = 0; i < nt; ++i) {        // block-uniform trigger loop
            int who = s_trig[i];
            int rr = blockIdx.x * 4 + (who >> 6);
            int n = jb * LAT + (who & 63);
            const float* wr = W + (size_t)rr * NDIM;
            size_t mo = (size_t)n * NDIM;
            double part = 0.0;
            for (int k = jb * BSZ + tid; k < NDIM; k += 256) {
                float mv = __half2float(g_Mt[0][mo + k]) + __half2float(g_Mt[1][mo + k]);
                part += (double)wr[k] * (double)mv;
            }
            redd[tid] = part;
            __syncthreads();
            for (int s2 = 128; s2 > 0; s2 >>= 1) {
                if (tid < s2) redd[tid] += redd[tid + s2];
                __syncthreads();
            }
            if (tid == who) y0 = (float)redd[0];
            __syncthreads();
        }
        if (nt) y = (y0 - fb) / rnv;
        float yhv = rintf(y);
        yh[rloc][jb][t] = yhv;
        uint32_t bal = __ballot_sync(0xFFFFFFFFu, yhv != 0.f);
        if ((t & 31) == 0) {
            msk[rloc][jb][t >> 5] = bal;
            if (bal) s_nz[rloc] = 1;          // benign race between half-warps
        }
        __syncthreads();

        int nz = s_nz[rloc];
        if (t == 0) {
            fl[rloc][jb] = (unsigned char)nz;
            g_flags[r * NB + jb] = (unsigned char)nz;
            if (nz) s_idx[rloc] = atomicAdd(&g_cnt, 1);
        }
        __syncthreads();
        if (nz) {
            int idx = s_idx[rloc];
            if (t == 0) g_items[idx] = (r << 5) | jb;
            g_yhl[(size_t)idx * LAT + t] = yhv;
        }
    }
}

// ---------------------------------------------------------------------------
// kernWhat: materialize W_hat blocks for flagged items only.
// ---------------------------------------------------------------------------
__global__ void kernWhat(const float* __restrict__ Wd) {
    __shared__ float s_y[LAT];
    int tid = threadIdx.x;
    int cnt = g_cnt;
    for (int i = blockIdx.x; i < cnt; i += gridDim.x) {
        int item = g_items[i];
        int r = item >> 5, jb = item & 31;
        if (tid < LAT) s_y[tid] = g_yhl[(size_t)i * LAT + tid];
        __syncthreads();
        float x = 0.f;
#pragma unroll 8
        for (int u = 0; u < LAT; ++u)
            x = fmaf(s_y[u], Wd[u * BSZ + tid], x);
        g_What[(size_t)r * NDIM + jb * BSZ + tid] = x;
        __syncthreads();
    }
}

// ---------------------------------------------------------------------------
// kernOut: out = bias + x @ (W_hat * rn)^T, skipping exactly-zero k-blocks.
// ---------------------------------------------------------------------------
__global__ void kernOut(const float* __restrict__ x, const float* __restrict__ rn,
                        const float* __restrict__ bias, float* __restrict__ out) {
    __shared__ __align__(16) float xs[16][64];
    __shared__ __align__(16) float ws[16][64];
    __shared__ unsigned char shf[NB];

    int b0 = blockIdx.x * 64;
    int m0 = blockIdx.y * 64;
    int tid = threadIdx.x;

    if (tid < NB) {
        unsigned char f = 0;
        for (int mm = 0; mm < 64; ++mm) f |= g_flags[(m0 + mm) * NB + tid];
        shf[tid] = f;
    }
    __syncthreads();

    int tr = tid >> 4, tc = tid & 15;
    int l_r = tid >> 2, l_q = (tid & 3) * 4;

    float acc[4][4];
#pragma unroll
    for (int i = 0; i < 4; ++i)
#pragma unroll
        for (int q = 0; q < 4; ++q) acc[i][q] = 0.f;

    float rnm = rn[m0 + l_r];

    for (int jj = 0; jj < NB; ++jj) {
        if (!shf[jj]) continue;
        for (int k0 = 0; k0 < BSZ; k0 += 16) {
            float4 xv = *reinterpret_cast<const float4*>(x + (size_t)(b0 + l_r) * NDIM + jj * BSZ + k0 + l_q);
            xs[l_q + 0][l_r] = xv.x; xs[l_q + 1][l_r] = xv.y;
            xs[l_q + 2][l_r] = xv.z; xs[l_q + 3][l_r] = xv.w;
            float4 wv = make_float4(0.f, 0.f, 0.f, 0.f);
            if (g_flags[(m0 + l_r) * NB + jj])
                wv = *reinterpret_cast<const float4*>(g_What + (size_t)(m0 + l_r) * NDIM + jj * BSZ + k0 + l_q);
            ws[l_q + 0][l_r] = wv.x * rnm; ws[l_q + 1][l_r] = wv.y * rnm;
            ws[l_q + 2][l_r] = wv.z * rnm; ws[l_q + 3][l_r] = wv.w * rnm;
            __syncthreads();
#pragma unroll
            for (int kk = 0; kk < 16; ++kk) {
                float4 a4 = *reinterpret_cast<const float4*>(&xs[kk][tr * 4]);
                float4 b4 = *reinterpret_cast<const float4*>(&ws[kk][tc * 4]);
                float a[4] = {a4.x, a4.y, a4.z, a4.w};
                float b[4] = {b4.x, b4.y, b4.z, b4.w};
#pragma unroll
                for (int i = 0; i < 4; ++i)
#pragma unroll
                    for (int q = 0; q < 4; ++q)
                        acc[i][q] = fmaf(a[i], b[q], acc[i][q]);
            }
            __syncthreads();
        }
    }

#pragma unroll
    for (int i = 0; i < 4; ++i) {
        int b = b0 + tr * 4 + i;
#pragma unroll
        for (int q = 0; q < 4; ++q) {
            int m = m0 + tc * 4 + q;
            out[(size_t)b * NDIM + m] = bias[m] + acc[i][q];
        }
    }
}

// ---------------------------------------------------------------------------
// kernel_launch: inputs (metadata order): x, weight, bias, row_norm, L, We, Wd
// ---------------------------------------------------------------------------
extern "C" void kernel_launch(void* const* d_in, const int* in_sizes, int n_in,
                              void* d_out, int out_size) {
    (void)in_sizes; (void)n_in; (void)out_size;
    const float* x      = (const float*)d_in[0];
    const float* weight = (const float*)d_in[1];
    const float* bias   = (const float*)d_in[2];
    const float* rn     = (const float*)d_in[3];
    const float* L      = (const float*)d_in[4];
    const float* We     = (const float*)d_in[5];
    const float* Wd     = (const float*)d_in[6];
    float* out          = (float*)d_out;

    kernPrep<<<8224, 256>>>(weight, We);                  // [0] W->fp16 hi, WeT split
    kernG<<<dim3(32, 32), 128, 30720>>>(L, We);           // [1] full Mt (split fp16 HMMA)
    kernGemmY<<<dim3(32, 16), 256, 40960>>>();            // [2] Y = W @ M (1-pass hh)
    kernH<<<dim3(32, 32), 256>>>(Wd);                     // [3] latent H  <- profiled
    kernSteps<<<1024, 256>>>(rn, weight);                 // [4] latent steps + guard
    kernWhat<<<1024, 128>>>(Wd);                          // [5] sparse W_hat blocks
    kernOut<<<dim3(64, 64), 256>>>(x, rn, bias, out);     // [6] output GEMM
}

// round 12
// speedup vs baseline: 2.1093x; 1.2469x over previous
#include <cuda_runtime.h>
#include <cuda_fp16.h>
#include <cstdint>

#define NDIM 4096
#define NB   32
#define BSZ  128
#define LAT  64
#define NCOL (NB * LAT)   // 2048
#define MAXIT (NDIM * NB)

// Static device scratch.
__device__ __half g_Wh[(size_t)NDIM * NDIM];          // W fp16 hi (GEMM operand)
__device__ __half g_Mt[2][(size_t)NCOL * NDIM];       // Mt[n,k]=M[k,n]; hi/lo fp16
__device__ __half g_WeTh[2][LAT * BSZ];               // WeT[t,c]=We[c,t]; hi/lo
__device__ float g_Y[(size_t)NDIM * NCOL];
__device__ float g_H[(size_t)NB * NB * LAT * LAT];    // H[jb][jj][u][t] (jj>jb valid)
__device__ float g_What[(size_t)NDIM * NDIM];         // valid only where flag set
__device__ unsigned char g_flags[NDIM * NB];
__device__ int g_cnt;
__device__ int g_items[MAXIT];
__device__ float g_yhl[(size_t)MAXIT * LAT];

// ---------------------------------------------------------------------------
// Base-target helpers (sm_80+)
// ---------------------------------------------------------------------------
__device__ __forceinline__ uint32_t smem_u32(const void* p) {
    uint32_t a;
    asm("{ .reg .u64 t; cvta.to.shared.u64 t, %1; cvt.u32.u64 %0, t; }" : "=r"(a) : "l"(p));
    return a;
}
#define CP_ASYNC16(s, g) asm volatile("cp.async.cg.shared.global [%0], [%1], 16;" :: "r"(s), "l"(g))
#define CP_COMMIT()      asm volatile("cp.async.commit_group;" ::: "memory")
#define CP_WAIT(n)       asm volatile("cp.async.wait_group %0;" :: "n"(n) : "memory")

__device__ __forceinline__ void ldm_x4(uint32_t addr, uint32_t r[4]) {
    asm volatile("ldmatrix.sync.aligned.m8n8.x4.shared.b16 {%0,%1,%2,%3}, [%4];"
                 : "=r"(r[0]), "=r"(r[1]), "=r"(r[2]), "=r"(r[3]) : "r"(addr));
}
__device__ __forceinline__ void mma_f16(float* c, const uint32_t a[4], uint32_t b0, uint32_t b1) {
    asm volatile(
        "mma.sync.aligned.m16n8k16.row.col.f32.f16.f16.f32 "
        "{%0,%1,%2,%3}, {%4,%5,%6,%7}, {%8,%9}, {%0,%1,%2,%3};"
        : "+f"(c[0]), "+f"(c[1]), "+f"(c[2]), "+f"(c[3])
        : "r"(a[0]), "r"(a[1]), "r"(a[2]), "r"(a[3]), "r"(b0), "r"(b1));
}
__device__ __forceinline__ void split2h(float v, __half& hi, __half& lo) {
    hi = __float2half_rn(v);
    lo = __float2half_rn(v - __half2float(hi));
}

#define RS 80   // smem row stride: 32 fp16 (64B) + 16B pad

// ---------------------------------------------------------------------------
// kernPrep: W fp32 -> fp16 hi (blocks 0..8191), WeT split (8192..8223).
// ---------------------------------------------------------------------------
__global__ void kernPrep(const float* __restrict__ W, const float* __restrict__ We) {
    int b = blockIdx.x;
    if (b < 8192) {
        size_t idx = (size_t)b * 256 + threadIdx.x;   // per 8 elems
        const float4* s = reinterpret_cast<const float4*>(W) + idx * 2;
        float4 a = s[0], c = s[1];
        float v[8] = {a.x, a.y, a.z, a.w, c.x, c.y, c.z, c.w};
        __half h[8];
#pragma unroll
        for (int q = 0; q < 8; ++q) h[q] = __float2half_rn(v[q]);
        *reinterpret_cast<uint4*>(g_Wh + idx * 8) = *reinterpret_cast<uint4*>(h);
    } else {
        int idx = (b - 8192) * 256 + threadIdx.x;     // 0..8191
        int t = idx >> 7, c = idx & 127;
        __half h, l;
        split2h(We[c * LAT + t], h, l);
        g_WeTh[0][idx] = h;
        g_WeTh[1][idx] = l;
    }
}

// ---------------------------------------------------------------------------
// kernG: builds the FULL Mt (fp16 hi+lo).
//   kt > j : G block via 3-term split fp16 HMMA;  kt == j: diag We;  kt < j: 0
// Grid (32 kt, 32 j), 128 threads, smem 30720 B.
// ---------------------------------------------------------------------------
__global__ void __launch_bounds__(128, 4) kernG(const float* __restrict__ L,
                                                const float* __restrict__ We) {
    int kt = blockIdx.x, j = blockIdx.y;
    int tid = threadIdx.x;
    int jn = j * LAT, s = j * BSZ;

    if (kt < j) {
        uint4 z = make_uint4(0, 0, 0, 0);
        for (int i = tid; i < 64 * 16; i += 128) {
            int rr = i >> 4, c = i & 15;
            size_t o = (size_t)(jn + rr) * NDIM + kt * BSZ + c * 8;
            *reinterpret_cast<uint4*>(g_Mt[0] + o) = z;
            *reinterpret_cast<uint4*>(g_Mt[1] + o) = z;
        }
        return;
    }
    if (kt == j) {
        for (int n = 0; n < LAT; ++n) {
            __half h, l;
            split2h(We[tid * LAT + n], h, l);
            size_t o = (size_t)(jn + n) * NDIM + s + tid;
            g_Mt[0][o] = h;
            g_Mt[1][o] = l;
        }
        return;
    }

    extern __shared__ __align__(128) char sm[];
    uint32_t sb = smem_u32(sm);
    uint32_t sA[2] = {sb, sb + 5120};
    uint32_t sB[2] = {sb + 10240, sb + 20480};
    int wid = tid >> 5, lane = tid & 31;
    int k0g = kt * BSZ;
    int wm = (wid & 1) * 32, wn = (wid >> 1) * 64;

    float acc[2][8][4];
#pragma unroll
    for (int i = 0; i < 2; ++i)
#pragma unroll
        for (int q = 0; q < 8; ++q)
#pragma unroll
            for (int z = 0; z < 4; ++z) acc[i][q][z] = 0.f;

    for (int it = 0; it < 4; ++it) {            // K=128, BK=32
        int kk = it * 32;
#pragma unroll
        for (int q = 0; q < 4; ++q) {
            int id = tid + q * 128;
            int prec = id >> 8, rem = id & 255, row = rem >> 2, ch = rem & 3;
            CP_ASYNC16(sA[prec] + row * RS + ch * 16,
                       g_WeTh[prec] + row * BSZ + kk + ch * 8);
        }
        CP_COMMIT();
#pragma unroll
        for (int q = 0; q < 8; ++q) {           // B: L fp32 -> split fp16 in-reg
            int id = tid + q * 128;
            int row = id >> 3, c = (id & 7) * 4;
            float4 v = *reinterpret_cast<const float4*>(
                L + (size_t)(k0g + row) * NDIM + s + kk + c);
            __half h0, l0, h1, l1, h2, l2, h3, l3;
            split2h(v.x, h0, l0); split2h(v.y, h1, l1);
            split2h(v.z, h2, l2); split2h(v.w, h3, l3);
            __half2 hA = __halves2half2(h0, h1), hB = __halves2half2(h2, h3);
            __half2 lA = __halves2half2(l0, l1), lB = __halves2half2(l2, l3);
            uint2 uh, ul;
            uh.x = *reinterpret_cast<uint32_t*>(&hA); uh.y = *reinterpret_cast<uint32_t*>(&hB);
            ul.x = *reinterpret_cast<uint32_t*>(&lA); ul.y = *reinterpret_cast<uint32_t*>(&lB);
            *reinterpret_cast<uint2*>(sm + 10240 + row * RS + c * 2) = uh;
            *reinterpret_cast<uint2*>(sm + 20480 + row * RS + c * 2) = ul;
        }
        CP_WAIT(0);
        __syncthreads();

#pragma unroll
        for (int ks = 0; ks < 2; ++ks) {
            uint32_t ah[2][4];
#pragma unroll
            for (int mf = 0; mf < 2; ++mf)
                ldm_x4(sA[0] + (wm + mf * 16 + (lane & 15)) * RS + ks * 32 + (lane >> 4) * 16, ah[mf]);
            uint32_t bh[8][2];
#pragma unroll
            for (int p = 0; p < 4; ++p) {
                uint32_t r[4];
                int g = lane >> 3;
                int row = wn + p * 16 + ((g >> 1) << 3) + (lane & 7);
                ldm_x4(sB[0] + row * RS + ks * 32 + (g & 1) * 16, r);
                bh[p * 2][0] = r[0]; bh[p * 2][1] = r[1];
                bh[p * 2 + 1][0] = r[2]; bh[p * 2 + 1][1] = r[3];
            }
#pragma unroll
            for (int mf = 0; mf < 2; ++mf)
#pragma unroll
                for (int nf = 0; nf < 8; ++nf)
                    mma_f16(acc[mf][nf], ah[mf], bh[nf][0], bh[nf][1]);
            uint32_t al[2][4];
#pragma unroll
            for (int mf = 0; mf < 2; ++mf)
                ldm_x4(sA[1] + (wm + mf * 16 + (lane & 15)) * RS + ks * 32 + (lane >> 4) * 16, al[mf]);
#pragma unroll
            for (int mf = 0; mf < 2; ++mf)
#pragma unroll
                for (int nf = 0; nf < 8; ++nf)
                    mma_f16(acc[mf][nf], al[mf], bh[nf][0], bh[nf][1]);
            uint32_t bl[8][2];
#pragma unroll
            for (int p = 0; p < 4; ++p) {
                uint32_t r[4];
                int g = lane >> 3;
                int row = wn + p * 16 + ((g >> 1) << 3) + (lane & 7);
                ldm_x4(sB[1] + row * RS + ks * 32 + (g & 1) * 16, r);
                bl[p * 2][0] = r[0]; bl[p * 2][1] = r[1];
                bl[p * 2 + 1][0] = r[2]; bl[p * 2 + 1][1] = r[3];
            }
#pragma unroll
            for (int mf = 0; mf < 2; ++mf)
#pragma unroll
                for (int nf = 0; nf < 8; ++nf)
                    mma_f16(acc[mf][nf], ah[mf], bl[nf][0], bl[nf][1]);
        }
        __syncthreads();
    }

#pragma unroll
    for (int mf = 0; mf < 2; ++mf) {
        int t0 = wm + mf * 16 + (lane >> 2);
#pragma unroll
        for (int nf = 0; nf < 8; ++nf) {
            int kr = wn + nf * 8 + 2 * (lane & 3);
            __half h0, l0, h1, l1, h2, l2, h3, l3;
            split2h(acc[mf][nf][0], h0, l0);
            split2h(acc[mf][nf][1], h1, l1);
            split2h(acc[mf][nf][2], h2, l2);
            split2h(acc[mf][nf][3], h3, l3);
            size_t o0 = (size_t)(jn + t0) * NDIM + k0g + kr;
            size_t o1 = (size_t)(jn + t0 + 8) * NDIM + k0g + kr;
            *reinterpret_cast<__half2*>(g_Mt[0] + o0) = __halves2half2(h0, h1);
            *reinterpret_cast<__half2*>(g_Mt[1] + o0) = __halves2half2(l0, l1);
            *reinterpret_cast<__half2*>(g_Mt[0] + o1) = __halves2half2(h2, h3);
            *reinterpret_cast<__half2*>(g_Mt[1] + o1) = __halves2half2(l2, l3);
        }
    }
}

// ---------------------------------------------------------------------------
// kernH: H[jb][jj] = Wd @ G_block, smem-tiled (4x4 register tile).
// Grid (32 jj, 32 jb) active iff jj > jb. Also resets g_cnt (block (0,0)).
// ---------------------------------------------------------------------------
__global__ void __launch_bounds__(256) kernH(const float* __restrict__ Wd) {
    int jj = blockIdx.x, jb = blockIdx.y;
    if (jj <= jb) {
        if (jj == 0 && jb == 0 && threadIdx.x == 0) g_cnt = 0;
        return;
    }
    __shared__ float Gs[64][65];    // Gs[c][t]
    __shared__ float Wds[64][65];   // Wds[u][c]
    int tid = threadIdx.x;
    int tu = tid >> 4, tt = tid & 15;

    float acc[4][4];
#pragma unroll
    for (int i = 0; i < 4; ++i)
#pragma unroll
        for (int q = 0; q < 4; ++q) acc[i][q] = 0.f;

    for (int cc = 0; cc < 2; ++cc) {
        __syncthreads();
#pragma unroll
        for (int i = 0; i < 16; ++i) {
            int idx = i * 256 + tid;
            int a = idx >> 6, c = idx & 63;
            size_t o = (size_t)(jb * LAT + a) * NDIM + jj * BSZ + cc * 64 + c;
            Gs[c][a] = __half2float(g_Mt[0][o]) + __half2float(g_Mt[1][o]);
            Wds[a][c] = Wd[a * BSZ + cc * 64 + c];
        }
        __syncthreads();
#pragma unroll 4
        for (int c = 0; c < 64; ++c) {
            float w[4], g[4];
#pragma unroll
            for (int i = 0; i < 4; ++i) w[i] = Wds[tu * 4 + i][c];
#pragma unroll
            for (int q = 0; q < 4; ++q) g[q] = Gs[c][tt * 4 + q];
#pragma unroll
            for (int i = 0; i < 4; ++i)
#pragma unroll
                for (int q = 0; q < 4; ++q)
                    acc[i][q] = fmaf(w[i], g[q], acc[i][q]);
        }
    }

    size_t hb = (((size_t)jb * NB + jj) * LAT) * LAT;
#pragma unroll
    for (int i = 0; i < 4; ++i)
#pragma unroll
        for (int q = 0; q < 4; ++q)
            g_H[hb + (size_t)(tu * 4 + i) * LAT + tt * 4 + q] = acc[i][q];
}

// ---------------------------------------------------------------------------
// kernGemmY: Y = W @ M^T, SINGLE fp16 hh HMMA pass, fp32 accum.
// Precision guarded by the boundary-recompute in kernSteps (window 1e-3,
// hh error max ~1.5e-4). BM=128 BN=128 BK=32, 256 thr, double-buffered
// cp.async (2 x 20480 B = 40960, under 48KB). k starts at n0*2.
// ---------------------------------------------------------------------------
__global__ void __launch_bounds__(256, 2) kernGemmY() {
    extern __shared__ __align__(128) char sm[];
    const int TSZ = 128 * RS;                 // 10240
    const int STG = 2 * TSZ;                  // 20480 per stage (A + B)
    uint32_t sb = smem_u32(sm);
    int tid = threadIdx.x, wid = tid >> 5, lane = tid & 31;
    int m0 = blockIdx.x * 128, n0 = blockIdx.y * 128;
    int kst = n0 * 2;
    int niter = (NDIM - kst) / 32;
    int wm = (wid & 1) * 64, wn = (wid >> 1) * 32;

    float acc[4][4][4];
#pragma unroll
    for (int i = 0; i < 4; ++i)
#pragma unroll
        for (int q = 0; q < 4; ++q)
#pragma unroll
            for (int z = 0; z < 4; ++z) acc[i][q][z] = 0.f;

    {
        uint32_t s_a = sb, s_b = sb + TSZ;
#pragma unroll
        for (int q = 0; q < 2; ++q) {
            int id = tid + q * 256, row = id >> 2, ch = id & 3;
            CP_ASYNC16(s_a + row * RS + ch * 16, g_Wh + (size_t)(m0 + row) * NDIM + kst + ch * 8);
            CP_ASYNC16(s_b + row * RS + ch * 16, g_Mt[0] + (size_t)(n0 + row) * NDIM + kst + ch * 8);
        }
        CP_COMMIT();
    }

    for (int it = 0; it < niter; ++it) {
        if (it + 1 < niter) {
            int k0 = kst + (it + 1) * 32;
            uint32_t s_a = sb + ((it + 1) & 1) * STG, s_b = s_a + TSZ;
#pragma unroll
            for (int q = 0; q < 2; ++q) {
                int id = tid + q * 256, row = id >> 2, ch = id & 3;
                CP_ASYNC16(s_a + row * RS + ch * 16, g_Wh + (size_t)(m0 + row) * NDIM + k0 + ch * 8);
                CP_ASYNC16(s_b + row * RS + ch * 16, g_Mt[0] + (size_t)(n0 + row) * NDIM + k0 + ch * 8);
            }
            CP_COMMIT();
            CP_WAIT(1);
        } else {
            CP_WAIT(0);
        }
        __syncthreads();
        uint32_t s_a = sb + (it & 1) * STG, s_b = s_a + TSZ;
#pragma unroll
        for (int ks = 0; ks < 2; ++ks) {
            uint32_t a[4][4];
#pragma unroll
            for (int mf = 0; mf < 4; ++mf)
                ldm_x4(s_a + (wm + mf * 16 + (lane & 15)) * RS + ks * 32 + (lane >> 4) * 16, a[mf]);
            uint32_t b[4][2];
#pragma unroll
            for (int p = 0; p < 2; ++p) {
                uint32_t r[4];
                int g = lane >> 3;
                int row = wn + p * 16 + ((g >> 1) << 3) + (lane & 7);
                ldm_x4(s_b + row * RS + ks * 32 + (g & 1) * 16, r);
                b[p * 2][0] = r[0]; b[p * 2][1] = r[1];
                b[p * 2 + 1][0] = r[2]; b[p * 2 + 1][1] = r[3];
            }
#pragma unroll
            for (int mf = 0; mf < 4; ++mf)
#pragma unroll
                for (int nf = 0; nf < 4; ++nf)
                    mma_f16(acc[mf][nf], a[mf], b[nf][0], b[nf][1]);
        }
        __syncthreads();
    }

#pragma unroll
    for (int mf = 0; mf < 4; ++mf) {
        int row = m0 + wm + mf * 16 + (lane >> 2);
#pragma unroll
        for (int nf = 0; nf < 4; ++nf) {
            int col = n0 + wn + nf * 8 + 2 * (lane & 3);
            *reinterpret_cast<float2*>(g_Y + (size_t)row * NCOL + col) =
                make_float2(acc[mf][nf][0], acc[mf][nf][1]);
            *reinterpret_cast<float2*>(g_Y + (size_t)(row + 8) * NCOL + col) =
                make_float2(acc[mf][nf][2], acc[mf][nf][3]);
        }
    }
}

// ---------------------------------------------------------------------------
// kernSteps: 32 fused sequential steps in latent space.
//  - feedback reads ONLY the nonzero rows of H (ballot masks)
//  - boundary guard (window 1e-3) with exact fp64 block-cooperative recompute
// Block = 4 rows x 64 threads, grid 1024.
// ---------------------------------------------------------------------------
__global__ void kernSteps(const float* __restrict__ rn, const float* __restrict__ W) {
    int tid = threadIdx.x;
    int rloc = tid >> 6, t = tid & 63;
    int r = blockIdx.x * 4 + rloc;

    __shared__ float yh[4][NB][LAT];          // 32KB
    __shared__ uint32_t msk[4][NB][2];        // nonzero-u masks
    __shared__ unsigned char fl[4][NB];
    __shared__ int s_nz[4], s_idx[4];
    __shared__ int ntrigB;
    __shared__ short s_trig[256];
    __shared__ double redd[256];              // 2KB

    float rnv = rn[r];
    if (t < NB) fl[rloc][t] = 0;

    for (int jb = NB - 1; jb >= 0; --jb) {
        __syncthreads();
        if (tid == 0) ntrigB = 0;
        if (t == 0) { s_nz[rloc] = 0; s_idx[rloc] = -1; }
        __syncthreads();

        float y0 = g_Y[(size_t)r * NCOL + jb * LAT + t];
        float fb = 0.f;
        for (int jj = jb + 1; jj < NB; ++jj) {
            if (fl[rloc][jj]) {
                const float* hb = g_H + ((size_t)(jb * NB + jj) * LAT) * LAT + t;
                const float* yv = yh[rloc][jj];
                uint32_t m = msk[rloc][jj][0];
                while (m) { int u = __ffs(m) - 1; m &= m - 1; fb = fmaf(yv[u], hb[(size_t)u * LAT], fb); }
                m = msk[rloc][jj][1];
                while (m) { int u = __ffs(m) + 31; m &= m - 1; fb = fmaf(yv[u], hb[(size_t)u * LAT], fb); }
            }
        }
        float y = (y0 - fb) / rnv;
        if (fabsf(fabsf(y - rintf(y)) - 0.5f) < 1e-3f) {
            int slot = atomicAdd(&ntrigB, 1);
            s_trig[slot] = (short)tid;
        }
        __syncthreads();
        int nt = ntrigB;
        for (int i = 0; i < nt; ++i) {
            int who = s_trig[i];
            int rr = blockIdx.x * 4 + (who >> 6);
            int n = jb * LAT + (who & 63);
            const float* wr = W + (size_t)rr * NDIM;
            size_t mo = (size_t)n * NDIM;
            double part = 0.0;
            for (int k = jb * BSZ + tid; k < NDIM; k += 256) {
                float mv = __half2float(g_Mt[0][mo + k]) + __half2float(g_Mt[1][mo + k]);
                part += (double)wr[k] * (double)mv;
            }
            redd[tid] = part;
            __syncthreads();
            for (int s2 = 128; s2 > 0; s2 >>= 1) {
                if (tid < s2) redd[tid] += redd[tid + s2];
                __syncthreads();
            }
            if (tid == who) y0 = (float)redd[0];
            __syncthreads();
        }
        if (nt) y = (y0 - fb) / rnv;
        float yhv = rintf(y);
        yh[rloc][jb][t] = yhv;
        uint32_t bal = __ballot_sync(0xFFFFFFFFu, yhv != 0.f);
        if ((t & 31) == 0) {
            msk[rloc][jb][t >> 5] = bal;
            if (bal) s_nz[rloc] = 1;
        }
        __syncthreads();

        int nz = s_nz[rloc];
        if (t == 0) {
            fl[rloc][jb] = (unsigned char)nz;
            g_flags[r * NB + jb] = (unsigned char)nz;
            if (nz) s_idx[rloc] = atomicAdd(&g_cnt, 1);
        }
        __syncthreads();
        if (nz) {
            int idx = s_idx[rloc];
            if (t == 0) g_items[idx] = (r << 5) | jb;
            g_yhl[(size_t)idx * LAT + t] = yhv;
        }
    }
}

// ---------------------------------------------------------------------------
// kernWhat: materialize W_hat blocks for flagged items only.
// ---------------------------------------------------------------------------
__global__ void kernWhat(const float* __restrict__ Wd) {
    __shared__ float s_y[LAT];
    int tid = threadIdx.x;
    int cnt = g_cnt;
    for (int i = blockIdx.x; i < cnt; i += gridDim.x) {
        int item = g_items[i];
        int r = item >> 5, jb = item & 31;
        if (tid < LAT) s_y[tid] = g_yhl[(size_t)i * LAT + tid];
        __syncthreads();
        float x = 0.f;
#pragma unroll 8
        for (int u = 0; u < LAT; ++u)
            x = fmaf(s_y[u], Wd[u * BSZ + tid], x);
        g_What[(size_t)r * NDIM + jb * BSZ + tid] = x;
        __syncthreads();
    }
}

// ---------------------------------------------------------------------------
// kernFillOut: out[b, m] = bias[m].  Grid 16384, 256 thr, float4 per thread.
// ---------------------------------------------------------------------------
__global__ void kernFillOut(const float* __restrict__ bias, float* __restrict__ out) {
    size_t idx = ((size_t)blockIdx.x * 256 + threadIdx.x) * 4;
    int m = (int)(idx & (NDIM - 1));
    float4 bv = *reinterpret_cast<const float4*>(bias + m);
    *reinterpret_cast<float4*>(out + idx) = bv;
}

// ---------------------------------------------------------------------------
// kernSparse: out[:, r] += x[:, jb-block] @ (What[r, jb-block] * rn[r])
// for every flagged item, grouped by jb so each x tile loads once per block.
// Grid (32 jb, 64 b-tiles of 64), 128 threads. atomicAdd into out (bias-filled).
// ---------------------------------------------------------------------------
__global__ void __launch_bounds__(128) kernSparse(const float* __restrict__ x,
                                                  const float* __restrict__ rn,
                                                  float* __restrict__ out) {
    int jb = blockIdx.x;
    int b0 = blockIdx.y * 64;
    int tid = threadIdx.x;
    __shared__ float xs[64][129];   // 33KB, conflict-free scalar reads
    __shared__ float ws[128];
    __shared__ int s_any;

    int cnt = g_cnt;
    bool any = false;
    for (int i = tid; i < cnt; i += 128)
        if ((g_items[i] & 31) == jb) any = true;
    if (tid == 0) s_any = 0;
    __syncthreads();
    if (any) s_any = 1;
    __syncthreads();
    if (!s_any) return;

    // x tile: 64 b-rows x 128 k, coalesced per row.
    for (int rr = 0; rr < 64; ++rr)
        xs[rr][tid] = x[(size_t)(b0 + rr) * NDIM + jb * BSZ + tid];
    __syncthreads();

    for (int i = 0; i < cnt; ++i) {
        int item = g_items[i];
        if ((item & 31) != jb) continue;
        int r = item >> 5;
        ws[tid] = g_What[(size_t)r * NDIM + jb * BSZ + tid] * rn[r];
        __syncthreads();
        if (tid < 64) {
            float acc = 0.f;
#pragma unroll 16
            for (int k = 0; k < BSZ; ++k)
                acc = fmaf(xs[tid][k], ws[k], acc);
            atomicAdd(&out[(size_t)(b0 + tid) * NDIM + r], acc);
        }
        __syncthreads();
    }
}

// ---------------------------------------------------------------------------
// kernel_launch: inputs (metadata order): x, weight, bias, row_norm, L, We, Wd
// ---------------------------------------------------------------------------
extern "C" void kernel_launch(void* const* d_in, const int* in_sizes, int n_in,
                              void* d_out, int out_size) {
    (void)in_sizes; (void)n_in; (void)out_size;
    const float* x      = (const float*)d_in[0];
    const float* weight = (const float*)d_in[1];
    const float* bias   = (const float*)d_in[2];
    const float* rn     = (const float*)d_in[3];
    const float* L      = (const float*)d_in[4];
    const float* We     = (const float*)d_in[5];
    const float* Wd     = (const float*)d_in[6];
    float* out          = (float*)d_out;

    kernPrep<<<8224, 256>>>(weight, We);                  // [0] W->fp16 hi, WeT split
    kernG<<<dim3(32, 32), 128, 30720>>>(L, We);           // [1] full Mt (split fp16 HMMA)
    kernH<<<dim3(32, 32), 256>>>(Wd);                     // [2] latent H + cnt reset
    kernGemmY<<<dim3(32, 16), 256, 40960>>>();            // [3] Y (1-pass hh)  <- profiled
    kernSteps<<<1024, 256>>>(rn, weight);                 // [4] latent steps + guard
    kernWhat<<<1024, 128>>>(Wd);                          // [5] sparse W_hat blocks
    kernFillOut<<<16384, 256>>>(bias, out);               // [6] out = bias
    kernSparse<<<dim3(32, 64), 128>>>(x, rn, out);        // [7] sparse rank-updates
}

// round 13
// speedup vs baseline: 2.1307x; 1.0102x over previous
#include <cuda_runtime.h>
#include <cuda_fp16.h>
#include <cstdint>

#define NDIM 4096
#define NB   32
#define BSZ  128
#define LAT  64
#define NCOL (NB * LAT)   // 2048
#define MAXIT (NDIM * NB)

// Static device scratch.
__device__ __half g_Wh[(size_t)NDIM * NDIM];          // W fp16 hi (GEMM operand)
__device__ __half g_Mt[2][(size_t)NCOL * NDIM];       // Mt[n,k]=M[k,n]; hi/lo fp16
__device__ __half g_WeTh[2][LAT * BSZ];               // WeT[t,c]=We[c,t]; hi/lo
__device__ float g_Y[(size_t)NDIM * NCOL];
__device__ float g_H[(size_t)NB * NB * LAT * LAT];    // H[jb][jj][u][t] (jj>jb valid)
__device__ float g_What[(size_t)NDIM * NDIM];         // valid only where flag set
__device__ unsigned char g_flags[NDIM * NB];
__device__ int g_cnt;
__device__ int g_items[MAXIT];
__device__ float g_yhl[(size_t)MAXIT * LAT];

// ---------------------------------------------------------------------------
// Base-target helpers (sm_80+)
// ---------------------------------------------------------------------------
__device__ __forceinline__ uint32_t smem_u32(const void* p) {
    uint32_t a;
    asm("{ .reg .u64 t; cvta.to.shared.u64 t, %1; cvt.u32.u64 %0, t; }" : "=r"(a) : "l"(p));
    return a;
}
#define CP_ASYNC16(s, g) asm volatile("cp.async.cg.shared.global [%0], [%1], 16;" :: "r"(s), "l"(g))
#define CP_COMMIT()      asm volatile("cp.async.commit_group;" ::: "memory")
#define CP_WAIT(n)       asm volatile("cp.async.wait_group %0;" :: "n"(n) : "memory")

__device__ __forceinline__ void ldm_x4(uint32_t addr, uint32_t r[4]) {
    asm volatile("ldmatrix.sync.aligned.m8n8.x4.shared.b16 {%0,%1,%2,%3}, [%4];"
                 : "=r"(r[0]), "=r"(r[1]), "=r"(r[2]), "=r"(r[3]) : "r"(addr));
}
__device__ __forceinline__ void mma_f16(float* c, const uint32_t a[4], uint32_t b0, uint32_t b1) {
    asm volatile(
        "mma.sync.aligned.m16n8k16.row.col.f32.f16.f16.f32 "
        "{%0,%1,%2,%3}, {%4,%5,%6,%7}, {%8,%9}, {%0,%1,%2,%3};"
        : "+f"(c[0]), "+f"(c[1]), "+f"(c[2]), "+f"(c[3])
        : "r"(a[0]), "r"(a[1]), "r"(a[2]), "r"(a[3]), "r"(b0), "r"(b1));
}
__device__ __forceinline__ void split2h(float v, __half& hi, __half& lo) {
    hi = __float2half_rn(v);
    lo = __float2half_rn(v - __half2float(hi));
}

#define RS 80   // smem row stride: 32 fp16 (64B) + 16B pad

// ---------------------------------------------------------------------------
// kernPrep: W fp32 -> fp16 hi (blocks 0..8191), WeT split (8192..8223).
// ---------------------------------------------------------------------------
__global__ void kernPrep(const float* __restrict__ W, const float* __restrict__ We) {
    int b = blockIdx.x;
    if (b < 8192) {
        size_t idx = (size_t)b * 256 + threadIdx.x;   // per 8 elems
        const float4* s = reinterpret_cast<const float4*>(W) + idx * 2;
        float4 a = s[0], c = s[1];
        float v[8] = {a.x, a.y, a.z, a.w, c.x, c.y, c.z, c.w};
        __half h[8];
#pragma unroll
        for (int q = 0; q < 8; ++q) h[q] = __float2half_rn(v[q]);
        *reinterpret_cast<uint4*>(g_Wh + idx * 8) = *reinterpret_cast<uint4*>(h);
    } else {
        int idx = (b - 8192) * 256 + threadIdx.x;     // 0..8191
        int t = idx >> 7, c = idx & 127;
        __half h, l;
        split2h(We[c * LAT + t], h, l);
        g_WeTh[0][idx] = h;
        g_WeTh[1][idx] = l;
    }
}

// ---------------------------------------------------------------------------
// kernG: builds the FULL Mt (fp16 hi+lo).
//   kt > j : G block via 3-term split fp16 HMMA;  kt == j: diag We;  kt < j: 0
// Grid (32 kt, 32 j), 128 threads, smem 30720 B.
// ---------------------------------------------------------------------------
__global__ void __launch_bounds__(128, 4) kernG(const float* __restrict__ L,
                                                const float* __restrict__ We) {
    int kt = blockIdx.x, j = blockIdx.y;
    int tid = threadIdx.x;
    int jn = j * LAT, s = j * BSZ;

    if (kt < j) {
        uint4 z = make_uint4(0, 0, 0, 0);
        for (int i = tid; i < 64 * 16; i += 128) {
            int rr = i >> 4, c = i & 15;
            size_t o = (size_t)(jn + rr) * NDIM + kt * BSZ + c * 8;
            *reinterpret_cast<uint4*>(g_Mt[0] + o) = z;
            *reinterpret_cast<uint4*>(g_Mt[1] + o) = z;
        }
        return;
    }
    if (kt == j) {
        for (int n = 0; n < LAT; ++n) {
            __half h, l;
            split2h(We[tid * LAT + n], h, l);
            size_t o = (size_t)(jn + n) * NDIM + s + tid;
            g_Mt[0][o] = h;
            g_Mt[1][o] = l;
        }
        return;
    }

    extern __shared__ __align__(128) char sm[];
    uint32_t sb = smem_u32(sm);
    uint32_t sA[2] = {sb, sb + 5120};
    uint32_t sB[2] = {sb + 10240, sb + 20480};
    int wid = tid >> 5, lane = tid & 31;
    int k0g = kt * BSZ;
    int wm = (wid & 1) * 32, wn = (wid >> 1) * 64;

    float acc[2][8][4];
#pragma unroll
    for (int i = 0; i < 2; ++i)
#pragma unroll
        for (int q = 0; q < 8; ++q)
#pragma unroll
            for (int z = 0; z < 4; ++z) acc[i][q][z] = 0.f;

    for (int it = 0; it < 4; ++it) {            // K=128, BK=32
        int kk = it * 32;
#pragma unroll
        for (int q = 0; q < 4; ++q) {
            int id = tid + q * 128;
            int prec = id >> 8, rem = id & 255, row = rem >> 2, ch = rem & 3;
            CP_ASYNC16(sA[prec] + row * RS + ch * 16,
                       g_WeTh[prec] + row * BSZ + kk + ch * 8);
        }
        CP_COMMIT();
#pragma unroll
        for (int q = 0; q < 8; ++q) {           // B: L fp32 -> split fp16 in-reg
            int id = tid + q * 128;
            int row = id >> 3, c = (id & 7) * 4;
            float4 v = *reinterpret_cast<const float4*>(
                L + (size_t)(k0g + row) * NDIM + s + kk + c);
            __half h0, l0, h1, l1, h2, l2, h3, l3;
            split2h(v.x, h0, l0); split2h(v.y, h1, l1);
            split2h(v.z, h2, l2); split2h(v.w, h3, l3);
            __half2 hA = __halves2half2(h0, h1), hB = __halves2half2(h2, h3);
            __half2 lA = __halves2half2(l0, l1), lB = __halves2half2(l2, l3);
            uint2 uh, ul;
            uh.x = *reinterpret_cast<uint32_t*>(&hA); uh.y = *reinterpret_cast<uint32_t*>(&hB);
            ul.x = *reinterpret_cast<uint32_t*>(&lA); ul.y = *reinterpret_cast<uint32_t*>(&lB);
            *reinterpret_cast<uint2*>(sm + 10240 + row * RS + c * 2) = uh;
            *reinterpret_cast<uint2*>(sm + 20480 + row * RS + c * 2) = ul;
        }
        CP_WAIT(0);
        __syncthreads();

#pragma unroll
        for (int ks = 0; ks < 2; ++ks) {
            uint32_t ah[2][4];
#pragma unroll
            for (int mf = 0; mf < 2; ++mf)
                ldm_x4(sA[0] + (wm + mf * 16 + (lane & 15)) * RS + ks * 32 + (lane >> 4) * 16, ah[mf]);
            uint32_t bh[8][2];
#pragma unroll
            for (int p = 0; p < 4; ++p) {
                uint32_t r[4];
                int g = lane >> 3;
                int row = wn + p * 16 + ((g >> 1) << 3) + (lane & 7);
                ldm_x4(sB[0] + row * RS + ks * 32 + (g & 1) * 16, r);
                bh[p * 2][0] = r[0]; bh[p * 2][1] = r[1];
                bh[p * 2 + 1][0] = r[2]; bh[p * 2 + 1][1] = r[3];
            }
#pragma unroll
            for (int mf = 0; mf < 2; ++mf)
#pragma unroll
                for (int nf = 0; nf < 8; ++nf)
                    mma_f16(acc[mf][nf], ah[mf], bh[nf][0], bh[nf][1]);
            uint32_t al[2][4];
#pragma unroll
            for (int mf = 0; mf < 2; ++mf)
                ldm_x4(sA[1] + (wm + mf * 16 + (lane & 15)) * RS + ks * 32 + (lane >> 4) * 16, al[mf]);
#pragma unroll
            for (int mf = 0; mf < 2; ++mf)
#pragma unroll
                for (int nf = 0; nf < 8; ++nf)
                    mma_f16(acc[mf][nf], al[mf], bh[nf][0], bh[nf][1]);
            uint32_t bl[8][2];
#pragma unroll
            for (int p = 0; p < 4; ++p) {
                uint32_t r[4];
                int g = lane >> 3;
                int row = wn + p * 16 + ((g >> 1) << 3) + (lane & 7);
                ldm_x4(sB[1] + row * RS + ks * 32 + (g & 1) * 16, r);
                bl[p * 2][0] = r[0]; bl[p * 2][1] = r[1];
                bl[p * 2 + 1][0] = r[2]; bl[p * 2 + 1][1] = r[3];
            }
#pragma unroll
            for (int mf = 0; mf < 2; ++mf)
#pragma unroll
                for (int nf = 0; nf < 8; ++nf)
                    mma_f16(acc[mf][nf], ah[mf], bl[nf][0], bl[nf][1]);
        }
        __syncthreads();
    }

#pragma unroll
    for (int mf = 0; mf < 2; ++mf) {
        int t0 = wm + mf * 16 + (lane >> 2);
#pragma unroll
        for (int nf = 0; nf < 8; ++nf) {
            int kr = wn + nf * 8 + 2 * (lane & 3);
            __half h0, l0, h1, l1, h2, l2, h3, l3;
            split2h(acc[mf][nf][0], h0, l0);
            split2h(acc[mf][nf][1], h1, l1);
            split2h(acc[mf][nf][2], h2, l2);
            split2h(acc[mf][nf][3], h3, l3);
            size_t o0 = (size_t)(jn + t0) * NDIM + k0g + kr;
            size_t o1 = (size_t)(jn + t0 + 8) * NDIM + k0g + kr;
            *reinterpret_cast<__half2*>(g_Mt[0] + o0) = __halves2half2(h0, h1);
            *reinterpret_cast<__half2*>(g_Mt[1] + o0) = __halves2half2(l0, l1);
            *reinterpret_cast<__half2*>(g_Mt[0] + o1) = __halves2half2(h2, h3);
            *reinterpret_cast<__half2*>(g_Mt[1] + o1) = __halves2half2(l2, l3);
        }
    }
}

// ---------------------------------------------------------------------------
// kernH v3: H[jb][jj] = Wd @ G_block, smem-tiled, VECTORIZED loads
// (uint2 = 4 halves per LDG instead of scalar __half loads).
// Grid (32 jj, 32 jb) active iff jj > jb. Also resets g_cnt (block (0,0)).
// ---------------------------------------------------------------------------
__global__ void __launch_bounds__(256) kernH(const float* __restrict__ Wd) {
    int jj = blockIdx.x, jb = blockIdx.y;
    if (jj <= jb) {
        if (jj == 0 && jb == 0 && threadIdx.x == 0) g_cnt = 0;
        return;
    }
    __shared__ float Gs[64][65];    // Gs[c][t]
    __shared__ float Wds[64][65];   // Wds[u][c]
    int tid = threadIdx.x;
    int tu = tid >> 4, tt = tid & 15;

    float acc[4][4];
#pragma unroll
    for (int i = 0; i < 4; ++i)
#pragma unroll
        for (int q = 0; q < 4; ++q) acc[i][q] = 0.f;

    for (int cc = 0; cc < 2; ++cc) {
        __syncthreads();
#pragma unroll
        for (int i = 0; i < 4; ++i) {           // 64 rows x 16 quad-chunks / 256
            int idx = i * 256 + tid;
            int a = idx >> 4, cq = (idx & 15) * 4;
            size_t o = (size_t)(jb * LAT + a) * NDIM + jj * BSZ + cc * 64 + cq;
            uint2 uh = *reinterpret_cast<const uint2*>(g_Mt[0] + o);
            uint2 ul = *reinterpret_cast<const uint2*>(g_Mt[1] + o);
            float2 h01 = __half22float2(*reinterpret_cast<__half2*>(&uh.x));
            float2 h23 = __half22float2(*reinterpret_cast<__half2*>(&uh.y));
            float2 l01 = __half22float2(*reinterpret_cast<__half2*>(&ul.x));
            float2 l23 = __half22float2(*reinterpret_cast<__half2*>(&ul.y));
            Gs[cq + 0][a] = h01.x + l01.x;
            Gs[cq + 1][a] = h01.y + l01.y;
            Gs[cq + 2][a] = h23.x + l23.x;
            Gs[cq + 3][a] = h23.y + l23.y;
            float4 wv = *reinterpret_cast<const float4*>(Wd + a * BSZ + cc * 64 + cq);
            Wds[a][cq + 0] = wv.x; Wds[a][cq + 1] = wv.y;
            Wds[a][cq + 2] = wv.z; Wds[a][cq + 3] = wv.w;
        }
        __syncthreads();
#pragma unroll 4
        for (int c = 0; c < 64; ++c) {
            float w[4], g[4];
#pragma unroll
            for (int i = 0; i < 4; ++i) w[i] = Wds[tu * 4 + i][c];
#pragma unroll
            for (int q = 0; q < 4; ++q) g[q] = Gs[c][tt * 4 + q];
#pragma unroll
            for (int i = 0; i < 4; ++i)
#pragma unroll
                for (int q = 0; q < 4; ++q)
                    acc[i][q] = fmaf(w[i], g[q], acc[i][q]);
        }
    }

    size_t hb = (((size_t)jb * NB + jj) * LAT) * LAT;
#pragma unroll
    for (int i = 0; i < 4; ++i)
#pragma unroll
        for (int q = 0; q < 4; ++q)
            g_H[hb + (size_t)(tu * 4 + i) * LAT + tt * 4 + q] = acc[i][q];
}

// ---------------------------------------------------------------------------
// kernGemmY: Y = W @ M^T, SINGLE fp16 hh HMMA pass, fp32 accum.
// 3-STAGE cp.async pipeline (3 x 20480 = 61440 B dyn smem, attr opt-in;
// 2 CTAs/SM = 122880 B < 228KB). Guarded by kernSteps boundary-recompute.
// BM=128 BN=128 BK=32, 256 thr. k starts at n0*2 (triangular M).
// ---------------------------------------------------------------------------
#define GY_STG 20480
__global__ void __launch_bounds__(256, 2) kernGemmY() {
    extern __shared__ __align__(128) char sm[];
    const int TSZ = 128 * RS;                 // 10240
    uint32_t sb = smem_u32(sm);
    int tid = threadIdx.x, wid = tid >> 5, lane = tid & 31;
    int m0 = blockIdx.x * 128, n0 = blockIdx.y * 128;
    int kst = n0 * 2;
    int niter = (NDIM - kst) / 32;            // >= 8
    int wm = (wid & 1) * 64, wn = (wid >> 1) * 32;

    float acc[4][4][4];
#pragma unroll
    for (int i = 0; i < 4; ++i)
#pragma unroll
        for (int q = 0; q < 4; ++q)
#pragma unroll
            for (int z = 0; z < 4; ++z) acc[i][q][z] = 0.f;

    auto issue = [&](int it) {
        int k0 = kst + it * 32;
        uint32_t s_a = sb + (it % 3) * GY_STG, s_b = s_a + TSZ;
#pragma unroll
        for (int q = 0; q < 2; ++q) {
            int id = tid + q * 256, row = id >> 2, ch = id & 3;
            CP_ASYNC16(s_a + row * RS + ch * 16, g_Wh + (size_t)(m0 + row) * NDIM + k0 + ch * 8);
            CP_ASYNC16(s_b + row * RS + ch * 16, g_Mt[0] + (size_t)(n0 + row) * NDIM + k0 + ch * 8);
        }
        CP_COMMIT();
    };

    issue(0);
    issue(1);
    for (int it = 0; it < niter; ++it) {
        if (it + 2 < niter) { issue(it + 2); CP_WAIT(2); }
        else if (it + 1 < niter) CP_WAIT(1);
        else CP_WAIT(0);
        __syncthreads();
        uint32_t s_a = sb + (it % 3) * GY_STG, s_b = s_a + TSZ;
#pragma unroll
        for (int ks = 0; ks < 2; ++ks) {
            uint32_t a[4][4];
#pragma unroll
            for (int mf = 0; mf < 4; ++mf)
                ldm_x4(s_a + (wm + mf * 16 + (lane & 15)) * RS + ks * 32 + (lane >> 4) * 16, a[mf]);
            uint32_t b[4][2];
#pragma unroll
            for (int p = 0; p < 2; ++p) {
                uint32_t r[4];
                int g = lane >> 3;
                int row = wn + p * 16 + ((g >> 1) << 3) + (lane & 7);
                ldm_x4(s_b + row * RS + ks * 32 + (g & 1) * 16, r);
                b[p * 2][0] = r[0]; b[p * 2][1] = r[1];
                b[p * 2 + 1][0] = r[2]; b[p * 2 + 1][1] = r[3];
            }
#pragma unroll
            for (int mf = 0; mf < 4; ++mf)
#pragma unroll
                for (int nf = 0; nf < 4; ++nf)
                    mma_f16(acc[mf][nf], a[mf], b[nf][0], b[nf][1]);
        }
        __syncthreads();
    }

#pragma unroll
    for (int mf = 0; mf < 4; ++mf) {
        int row = m0 + wm + mf * 16 + (lane >> 2);
#pragma unroll
        for (int nf = 0; nf < 4; ++nf) {
            int col = n0 + wn + nf * 8 + 2 * (lane & 3);
            *reinterpret_cast<float2*>(g_Y + (size_t)row * NCOL + col) =
                make_float2(acc[mf][nf][0], acc[mf][nf][1]);
            *reinterpret_cast<float2*>(g_Y + (size_t)(row + 8) * NCOL + col) =
                make_float2(acc[mf][nf][2], acc[mf][nf][3]);
        }
    }
}

// ---------------------------------------------------------------------------
// kernSteps: 32 fused sequential steps in latent space.
//  - feedback reads ONLY the nonzero rows of H (ballot masks)
//  - boundary guard (window 1e-3) with exact fp64 block-cooperative recompute
// Block = 4 rows x 64 threads, grid 1024.
// ---------------------------------------------------------------------------
__global__ void kernSteps(const float* __restrict__ rn, const float* __restrict__ W) {
    int tid = threadIdx.x;
    int rloc = tid >> 6, t = tid & 63;
    int r = blockIdx.x * 4 + rloc;

    __shared__ float yh[4][NB][LAT];          // 32KB
    __shared__ uint32_t msk[4][NB][2];        // nonzero-u masks
    __shared__ unsigned char fl[4][NB];
    __shared__ int s_nz[4], s_idx[4];
    __shared__ int ntrigB;
    __shared__ short s_trig[256];
    __shared__ double redd[256];              // 2KB

    float rnv = rn[r];
    if (t < NB) fl[rloc][t] = 0;

    for (int jb = NB - 1; jb >= 0; --jb) {
        __syncthreads();
        if (tid == 0) ntrigB = 0;
        if (t == 0) { s_nz[rloc] = 0; s_idx[rloc] = -1; }
        __syncthreads();

        float y0 = g_Y[(size_t)r * NCOL + jb * LAT + t];
        float fb = 0.f;
        for (int jj = jb + 1; jj < NB; ++jj) {
            if (fl[rloc][jj]) {
                const float* hb = g_H + ((size_t)(jb * NB + jj) * LAT) * LAT + t;
                const float* yv = yh[rloc][jj];
                uint32_t m = msk[rloc][jj][0];
                while (m) { int u = __ffs(m) - 1; m &= m - 1; fb = fmaf(yv[u], hb[(size_t)u * LAT], fb); }
                m = msk[rloc][jj][1];
                while (m) { int u = __ffs(m) + 31; m &= m - 1; fb = fmaf(yv[u], hb[(size_t)u * LAT], fb); }
            }
        }
        float y = (y0 - fb) / rnv;
        if (fabsf(fabsf(y - rintf(y)) - 0.5f) < 1e-3f) {
            int slot = atomicAdd(&ntrigB, 1);
            s_trig[slot] = (short)tid;
        }
        __syncthreads();
        int nt = ntrigB;
        for (int i = 0; i < nt; ++i) {
            int who = s_trig[i];
            int rr = blockIdx.x * 4 + (who >> 6);
            int n = jb * LAT + (who & 63);
            const float* wr = W + (size_t)rr * NDIM;
            size_t mo = (size_t)n * NDIM;
            double part = 0.0;
            for (int k = jb * BSZ + tid; k < NDIM; k += 256) {
                float mv = __half2float(g_Mt[0][mo + k]) + __half2float(g_Mt[1][mo + k]);
                part += (double)wr[k] * (double)mv;
            }
            redd[tid] = part;
            __syncthreads();
            for (int s2 = 128; s2 > 0; s2 >>= 1) {
                if (tid < s2) redd[tid] += redd[tid + s2];
                __syncthreads();
            }
            if (tid == who) y0 = (float)redd[0];
            __syncthreads();
        }
        if (nt) y = (y0 - fb) / rnv;
        float yhv = rintf(y);
        yh[rloc][jb][t] = yhv;
        uint32_t bal = __ballot_sync(0xFFFFFFFFu, yhv != 0.f);
        if ((t & 31) == 0) {
            msk[rloc][jb][t >> 5] = bal;
            if (bal) s_nz[rloc] = 1;
        }
        __syncthreads();

        int nz = s_nz[rloc];
        if (t == 0) {
            fl[rloc][jb] = (unsigned char)nz;
            g_flags[r * NB + jb] = (unsigned char)nz;
            if (nz) s_idx[rloc] = atomicAdd(&g_cnt, 1);
        }
        __syncthreads();
        if (nz) {
            int idx = s_idx[rloc];
            if (t == 0) g_items[idx] = (r << 5) | jb;
            g_yhl[(size_t)idx * LAT + t] = yhv;
        }
    }
}

// ---------------------------------------------------------------------------
// kernWhat: materialize W_hat blocks for flagged items only.
// ---------------------------------------------------------------------------
__global__ void kernWhat(const float* __restrict__ Wd) {
    __shared__ float s_y[LAT];
    int tid = threadIdx.x;
    int cnt = g_cnt;
    for (int i = blockIdx.x; i < cnt; i += gridDim.x) {
        int item = g_items[i];
        int r = item >> 5, jb = item & 31;
        if (tid < LAT) s_y[tid] = g_yhl[(size_t)i * LAT + tid];
        __syncthreads();
        float x = 0.f;
#pragma unroll 8
        for (int u = 0; u < LAT; ++u)
            x = fmaf(s_y[u], Wd[u * BSZ + tid], x);
        g_What[(size_t)r * NDIM + jb * BSZ + tid] = x;
        __syncthreads();
    }
}

// ---------------------------------------------------------------------------
// kernFillOut: out[b, m] = bias[m].
// ---------------------------------------------------------------------------
__global__ void kernFillOut(const float* __restrict__ bias, float* __restrict__ out) {
    size_t idx = ((size_t)blockIdx.x * 256 + threadIdx.x) * 4;
    int m = (int)(idx & (NDIM - 1));
    float4 bv = *reinterpret_cast<const float4*>(bias + m);
    *reinterpret_cast<float4*>(out + idx) = bv;
}

// ---------------------------------------------------------------------------
// kernSparse: out[:, r] += x[:, jb-block] @ (What[r, jb-block] * rn[r])
// Grid (32 jb, 64 b-tiles of 64), 128 threads, atomicAdd into bias-filled out.
// ---------------------------------------------------------------------------
__global__ void __launch_bounds__(128) kernSparse(const float* __restrict__ x,
                                                  const float* __restrict__ rn,
                                                  float* __restrict__ out) {
    int jb = blockIdx.x;
    int b0 = blockIdx.y * 64;
    int tid = threadIdx.x;
    __shared__ float xs[64][129];
    __shared__ float ws[128];
    __shared__ int s_any;

    int cnt = g_cnt;
    bool any = false;
    for (int i = tid; i < cnt; i += 128)
        if ((g_items[i] & 31) == jb) any = true;
    if (tid == 0) s_any = 0;
    __syncthreads();
    if (any) s_any = 1;
    __syncthreads();
    if (!s_any) return;

    for (int rr = 0; rr < 64; ++rr)
        xs[rr][tid] = x[(size_t)(b0 + rr) * NDIM + jb * BSZ + tid];
    __syncthreads();

    for (int i = 0; i < cnt; ++i) {
        int item = g_items[i];
        if ((item & 31) != jb) continue;
        int r = item >> 5;
        ws[tid] = g_What[(size_t)r * NDIM + jb * BSZ + tid] * rn[r];
        __syncthreads();
        if (tid < 64) {
            float acc = 0.f;
#pragma unroll 16
            for (int k = 0; k < BSZ; ++k)
                acc = fmaf(xs[tid][k], ws[k], acc);
            atomicAdd(&out[(size_t)(b0 + tid) * NDIM + r], acc);
        }
        __syncthreads();
    }
}

// ---------------------------------------------------------------------------
// kernel_launch: inputs (metadata order): x, weight, bias, row_norm, L, We, Wd
// ---------------------------------------------------------------------------
extern "C" void kernel_launch(void* const* d_in, const int* in_sizes, int n_in,
                              void* d_out, int out_size) {
    (void)in_sizes; (void)n_in; (void)out_size;
    const float* x      = (const float*)d_in[0];
    const float* weight = (const float*)d_in[1];
    const float* bias   = (const float*)d_in[2];
    const float* rn     = (const float*)d_in[3];
    const float* L      = (const float*)d_in[4];
    const float* We     = (const float*)d_in[5];
    const float* Wd     = (const float*)d_in[6];
    float* out          = (float*)d_out;

    static bool attr_set = false;
    if (!attr_set) {
        cudaFuncSetAttribute(kernGemmY, cudaFuncAttributeMaxDynamicSharedMemorySize, 3 * GY_STG);
        attr_set = true;
    }

    kernPrep<<<8224, 256>>>(weight, We);                  // [0] W->fp16 hi, WeT split
    kernG<<<dim3(32, 32), 128, 30720>>>(L, We);           // [1] full Mt (split fp16 HMMA)
    kernH<<<dim3(32, 32), 256>>>(Wd);                     // [2] latent H + cnt reset
    kernGemmY<<<dim3(32, 16), 256, 3 * GY_STG>>>();       // [3] Y (3-stage)  <- profiled
    kernSteps<<<1024, 256>>>(rn, weight);                 // [4] latent steps + guard
    kernWhat<<<1024, 128>>>(Wd);                          // [5] sparse W_hat blocks
    kernFillOut<<<16384, 256>>>(bias, out);               // [6] out = bias
    kernSparse<<<dim3(32, 64), 128>>>(x, rn, out);        // [7] sparse rank-updates
}

// round 14
// speedup vs baseline: 2.3270x; 1.0921x over previous
#include <cuda_runtime.h>
#include <cuda_fp16.h>
#include <cstdint>

#define NDIM 4096
#define NB   32
#define BSZ  128
#define LAT  64
#define NCOL (NB * LAT)   // 2048
#define MAXIT (NDIM * NB)

// Static device scratch.
__device__ __half g_Wh[(size_t)NDIM * NDIM];          // W fp16 hi (GEMM operand)
__device__ __half g_Mt[2][(size_t)NCOL * NDIM];       // Mt[n,k]=M[k,n]; hi/lo fp16
__device__ __half g_WeTh[2][LAT * BSZ];               // WeT[t,c]=We[c,t]; hi/lo
__device__ float g_Y[(size_t)NDIM * NCOL];
__device__ float g_H[(size_t)NB * NB * LAT * LAT];    // H[jb][jj][u][t] (jj>jb valid)
__device__ float g_What[(size_t)NDIM * NDIM];         // valid only where flag set
__device__ unsigned char g_flags[NDIM * NB];
__device__ int g_cnt;
__device__ int g_items[MAXIT];
__device__ float g_yhl[(size_t)MAXIT * LAT];

// ---------------------------------------------------------------------------
// Base-target helpers (sm_80+)
// ---------------------------------------------------------------------------
__device__ __forceinline__ uint32_t smem_u32(const void* p) {
    uint32_t a;
    asm("{ .reg .u64 t; cvta.to.shared.u64 t, %1; cvt.u32.u64 %0, t; }" : "=r"(a) : "l"(p));
    return a;
}
#define CP_ASYNC16(s, g) asm volatile("cp.async.cg.shared.global [%0], [%1], 16;" :: "r"(s), "l"(g))
#define CP_COMMIT()      asm volatile("cp.async.commit_group;" ::: "memory")
#define CP_WAIT(n)       asm volatile("cp.async.wait_group %0;" :: "n"(n) : "memory")

__device__ __forceinline__ void ldm_x4(uint32_t addr, uint32_t r[4]) {
    asm volatile("ldmatrix.sync.aligned.m8n8.x4.shared.b16 {%0,%1,%2,%3}, [%4];"
                 : "=r"(r[0]), "=r"(r[1]), "=r"(r[2]), "=r"(r[3]) : "r"(addr));
}
__device__ __forceinline__ void mma_f16(float* c, const uint32_t a[4], uint32_t b0, uint32_t b1) {
    asm volatile(
        "mma.sync.aligned.m16n8k16.row.col.f32.f16.f16.f32 "
        "{%0,%1,%2,%3}, {%4,%5,%6,%7}, {%8,%9}, {%0,%1,%2,%3};"
        : "+f"(c[0]), "+f"(c[1]), "+f"(c[2]), "+f"(c[3])
        : "r"(a[0]), "r"(a[1]), "r"(a[2]), "r"(a[3]), "r"(b0), "r"(b1));
}
__device__ __forceinline__ void split2h(float v, __half& hi, __half& lo) {
    hi = __float2half_rn(v);
    lo = __float2half_rn(v - __half2float(hi));
}

#define RS 80    // smem row stride for BK=32 tiles (64B + 16 pad)
#define RS2 144  // smem row stride for BK=64 tiles (128B + 16 pad)

// ---------------------------------------------------------------------------
// kernPrep: W fp32 -> fp16 hi (blocks 0..8191), WeT split (8192..8223).
// ---------------------------------------------------------------------------
__global__ void kernPrep(const float* __restrict__ W, const float* __restrict__ We) {
    int b = blockIdx.x;
    if (b < 8192) {
        size_t idx = (size_t)b * 256 + threadIdx.x;   // per 8 elems
        const float4* s = reinterpret_cast<const float4*>(W) + idx * 2;
        float4 a = s[0], c = s[1];
        float v[8] = {a.x, a.y, a.z, a.w, c.x, c.y, c.z, c.w};
        __half h[8];
#pragma unroll
        for (int q = 0; q < 8; ++q) h[q] = __float2half_rn(v[q]);
        *reinterpret_cast<uint4*>(g_Wh + idx * 8) = *reinterpret_cast<uint4*>(h);
    } else {
        int idx = (b - 8192) * 256 + threadIdx.x;     // 0..8191
        int t = idx >> 7, c = idx & 127;
        __half h, l;
        split2h(We[c * LAT + t], h, l);
        g_WeTh[0][idx] = h;
        g_WeTh[1][idx] = l;
    }
}

// ---------------------------------------------------------------------------
// kernG (FUSED with H): builds the FULL Mt (fp16 hi+lo) AND H[jb][jj].
//   kt > j : G block via 3-term split fp16 HMMA -> Mt; then H = Wd @ G
//            computed in-block from the fp32 register accumulators.
//   kt == j: diagonal We block (split).  kt < j : zero fill (+ g_cnt reset).
// Grid (32 kt, 32 j), 128 threads, dyn smem 33280 B.
// ---------------------------------------------------------------------------
__global__ void __launch_bounds__(128, 4) kernG(const float* __restrict__ L,
                                                const float* __restrict__ We,
                                                const float* __restrict__ Wd) {
    int kt = blockIdx.x, j = blockIdx.y;
    int tid = threadIdx.x;
    int jn = j * LAT, s = j * BSZ;

    if (kt < j) {
        if (kt == 0 && j == 1 && tid == 0) g_cnt = 0;
        uint4 z = make_uint4(0, 0, 0, 0);
        for (int i = tid; i < 64 * 16; i += 128) {
            int rr = i >> 4, c = i & 15;
            size_t o = (size_t)(jn + rr) * NDIM + kt * BSZ + c * 8;
            *reinterpret_cast<uint4*>(g_Mt[0] + o) = z;
            *reinterpret_cast<uint4*>(g_Mt[1] + o) = z;
        }
        return;
    }
    if (kt == j) {
        for (int n = 0; n < LAT; ++n) {
            __half h, l;
            split2h(We[tid * LAT + n], h, l);
            size_t o = (size_t)(jn + n) * NDIM + s + tid;
            g_Mt[0][o] = h;
            g_Mt[1][o] = l;
        }
        return;
    }

    extern __shared__ __align__(128) char sm[];
    uint32_t sb = smem_u32(sm);
    uint32_t sA[2] = {sb, sb + 5120};
    uint32_t sB[2] = {sb + 10240, sb + 20480};
    int wid = tid >> 5, lane = tid & 31;
    int k0g = kt * BSZ;
    int wm = (wid & 1) * 32, wn = (wid >> 1) * 64;

    float acc[2][8][4];
#pragma unroll
    for (int i = 0; i < 2; ++i)
#pragma unroll
        for (int q = 0; q < 8; ++q)
#pragma unroll
            for (int z = 0; z < 4; ++z) acc[i][q][z] = 0.f;

    for (int it = 0; it < 4; ++it) {            // K=128, BK=32
        int kk = it * 32;
#pragma unroll
        for (int q = 0; q < 4; ++q) {
            int id = tid + q * 128;
            int prec = id >> 8, rem = id & 255, row = rem >> 2, ch = rem & 3;
            CP_ASYNC16(sA[prec] + row * RS + ch * 16,
                       g_WeTh[prec] + row * BSZ + kk + ch * 8);
        }
        CP_COMMIT();
#pragma unroll
        for (int q = 0; q < 8; ++q) {           // B: L fp32 -> split fp16 in-reg
            int id = tid + q * 128;
            int row = id >> 3, c = (id & 7) * 4;
            float4 v = *reinterpret_cast<const float4*>(
                L + (size_t)(k0g + row) * NDIM + s + kk + c);
            __half h0, l0, h1, l1, h2, l2, h3, l3;
            split2h(v.x, h0, l0); split2h(v.y, h1, l1);
            split2h(v.z, h2, l2); split2h(v.w, h3, l3);
            __half2 hA = __halves2half2(h0, h1), hB = __halves2half2(h2, h3);
            __half2 lA = __halves2half2(l0, l1), lB = __halves2half2(l2, l3);
            uint2 uh, ul;
            uh.x = *reinterpret_cast<uint32_t*>(&hA); uh.y = *reinterpret_cast<uint32_t*>(&hB);
            ul.x = *reinterpret_cast<uint32_t*>(&lA); ul.y = *reinterpret_cast<uint32_t*>(&lB);
            *reinterpret_cast<uint2*>(sm + 10240 + row * RS + c * 2) = uh;
            *reinterpret_cast<uint2*>(sm + 20480 + row * RS + c * 2) = ul;
        }
        CP_WAIT(0);
        __syncthreads();

#pragma unroll
        for (int ks = 0; ks < 2; ++ks) {
            uint32_t ah[2][4];
#pragma unroll
            for (int mf = 0; mf < 2; ++mf)
                ldm_x4(sA[0] + (wm + mf * 16 + (lane & 15)) * RS + ks * 32 + (lane >> 4) * 16, ah[mf]);
            uint32_t bh[8][2];
#pragma unroll
            for (int p = 0; p < 4; ++p) {
                uint32_t r[4];
                int g = lane >> 3;
                int row = wn + p * 16 + ((g >> 1) << 3) + (lane & 7);
                ldm_x4(sB[0] + row * RS + ks * 32 + (g & 1) * 16, r);
                bh[p * 2][0] = r[0]; bh[p * 2][1] = r[1];
                bh[p * 2 + 1][0] = r[2]; bh[p * 2 + 1][1] = r[3];
            }
#pragma unroll
            for (int mf = 0; mf < 2; ++mf)
#pragma unroll
                for (int nf = 0; nf < 8; ++nf)
                    mma_f16(acc[mf][nf], ah[mf], bh[nf][0], bh[nf][1]);
            uint32_t al[2][4];
#pragma unroll
            for (int mf = 0; mf < 2; ++mf)
                ldm_x4(sA[1] + (wm + mf * 16 + (lane & 15)) * RS + ks * 32 + (lane >> 4) * 16, al[mf]);
#pragma unroll
            for (int mf = 0; mf < 2; ++mf)
#pragma unroll
                for (int nf = 0; nf < 8; ++nf)
                    mma_f16(acc[mf][nf], al[mf], bh[nf][0], bh[nf][1]);
            uint32_t bl[8][2];
#pragma unroll
            for (int p = 0; p < 4; ++p) {
                uint32_t r[4];
                int g = lane >> 3;
                int row = wn + p * 16 + ((g >> 1) << 3) + (lane & 7);
                ldm_x4(sB[1] + row * RS + ks * 32 + (g & 1) * 16, r);
                bl[p * 2][0] = r[0]; bl[p * 2][1] = r[1];
                bl[p * 2 + 1][0] = r[2]; bl[p * 2 + 1][1] = r[3];
            }
#pragma unroll
            for (int mf = 0; mf < 2; ++mf)
#pragma unroll
                for (int nf = 0; nf < 8; ++nf)
                    mma_f16(acc[mf][nf], ah[mf], bl[nf][0], bl[nf][1]);
        }
        __syncthreads();
    }

    // Store split(G) -> Mt
#pragma unroll
    for (int mf = 0; mf < 2; ++mf) {
        int t0 = wm + mf * 16 + (lane >> 2);
#pragma unroll
        for (int nf = 0; nf < 8; ++nf) {
            int kr = wn + nf * 8 + 2 * (lane & 3);
            __half h0, l0, h1, l1, h2, l2, h3, l3;
            split2h(acc[mf][nf][0], h0, l0);
            split2h(acc[mf][nf][1], h1, l1);
            split2h(acc[mf][nf][2], h2, l2);
            split2h(acc[mf][nf][3], h3, l3);
            size_t o0 = (size_t)(jn + t0) * NDIM + k0g + kr;
            size_t o1 = (size_t)(jn + t0 + 8) * NDIM + k0g + kr;
            *reinterpret_cast<__half2*>(g_Mt[0] + o0) = __halves2half2(h0, h1);
            *reinterpret_cast<__half2*>(g_Mt[1] + o0) = __halves2half2(l0, l1);
            *reinterpret_cast<__half2*>(g_Mt[0] + o1) = __halves2half2(h2, h3);
            *reinterpret_cast<__half2*>(g_Mt[1] + o1) = __halves2half2(l2, l3);
        }
    }

    // ---- Fused H phase: H[j][kt][u][t] = sum_c Wd[u][c] * G[c][t] ----
    // c processed in 2 chunks of 64 (kr range per warp pair). fp32 smem.
    float* Gs  = reinterpret_cast<float*>(sm);           // [64][65]
    float* Wds = reinterpret_cast<float*>(sm) + 64 * 65; // [64][65]
    int tu = tid >> 4, tt = tid & 15;
    float acc2[8][4];
#pragma unroll
    for (int i = 0; i < 8; ++i)
#pragma unroll
        for (int q = 0; q < 4; ++q) acc2[i][q] = 0.f;

    for (int cc = 0; cc < 2; ++cc) {
        __syncthreads();
        if (wn == cc * 64) {                  // the two warps owning this kr range
#pragma unroll
            for (int mf = 0; mf < 2; ++mf) {
                int t0 = wm + mf * 16 + (lane >> 2);
#pragma unroll
                for (int nf = 0; nf < 8; ++nf) {
                    int krl = nf * 8 + 2 * (lane & 3);
                    Gs[(krl)     * 65 + t0]     = acc[mf][nf][0];
                    Gs[(krl + 1) * 65 + t0]     = acc[mf][nf][1];
                    Gs[(krl)     * 65 + t0 + 8] = acc[mf][nf][2];
                    Gs[(krl + 1) * 65 + t0 + 8] = acc[mf][nf][3];
                }
            }
        }
#pragma unroll
        for (int i = 0; i < 8; ++i) {         // Wd chunk: 64u x 64c, float4
            int idx = i * 128 + tid;
            int u = idx >> 4, cq = (idx & 15) * 4;
            float4 wv = *reinterpret_cast<const float4*>(Wd + u * BSZ + cc * 64 + cq);
            Wds[u * 65 + cq + 0] = wv.x; Wds[u * 65 + cq + 1] = wv.y;
            Wds[u * 65 + cq + 2] = wv.z; Wds[u * 65 + cq + 3] = wv.w;
        }
        __syncthreads();
#pragma unroll 4
        for (int c = 0; c < 64; ++c) {
            float w[8], g[4];
#pragma unroll
            for (int i = 0; i < 8; ++i) w[i] = Wds[(tu * 8 + i) * 65 + c];
#pragma unroll
            for (int q = 0; q < 4; ++q) g[q] = Gs[c * 65 + tt * 4 + q];
#pragma unroll
            for (int i = 0; i < 8; ++i)
#pragma unroll
                for (int q = 0; q < 4; ++q)
                    acc2[i][q] = fmaf(w[i], g[q], acc2[i][q]);
        }
    }

    size_t hb = (((size_t)j * NB + kt) * LAT) * LAT;
#pragma unroll
    for (int i = 0; i < 8; ++i)
#pragma unroll
        for (int q = 0; q < 4; ++q)
            g_H[hb + (size_t)(tu * 8 + i) * LAT + tt * 4 + q] = acc2[i][q];
}

// ---------------------------------------------------------------------------
// kernGemmY: Y = W @ M^T, SINGLE fp16 hh HMMA pass, fp32 accum. BK=64.
// Double-buffered cp.async (2 x 36864 = 73728 B dyn smem, attr opt-in;
// 2 CTAs/SM = 147KB < 228KB). Guarded by kernSteps boundary-recompute.
// BM=128 BN=128, 256 thr. k starts at n0*2 (triangular M).
// ---------------------------------------------------------------------------
#define GY2_TSZ (128 * RS2)          // 18432
#define GY2_STG (2 * GY2_TSZ)        // 36864
__global__ void __launch_bounds__(256, 2) kernGemmY() {
    extern __shared__ __align__(128) char sm[];
    uint32_t sb = smem_u32(sm);
    int tid = threadIdx.x, wid = tid >> 5, lane = tid & 31;
    int m0 = blockIdx.x * 128, n0 = blockIdx.y * 128;
    int kst = n0 * 2;                  // multiple of 256 -> divisible by 64
    int niter = (NDIM - kst) / 64;     // >= 4
    int wm = (wid & 1) * 64, wn = (wid >> 1) * 32;

    float acc[4][4][4];
#pragma unroll
    for (int i = 0; i < 4; ++i)
#pragma unroll
        for (int q = 0; q < 4; ++q)
#pragma unroll
            for (int z = 0; z < 4; ++z) acc[i][q][z] = 0.f;

    auto issue = [&](int it) {
        int k0 = kst + it * 64;
        uint32_t s_a = sb + (it & 1) * GY2_STG, s_b = s_a + GY2_TSZ;
#pragma unroll
        for (int q = 0; q < 4; ++q) {
            int id = tid + q * 256, row = id >> 3, ch = id & 7;
            CP_ASYNC16(s_a + row * RS2 + ch * 16, g_Wh + (size_t)(m0 + row) * NDIM + k0 + ch * 8);
            CP_ASYNC16(s_b + row * RS2 + ch * 16, g_Mt[0] + (size_t)(n0 + row) * NDIM + k0 + ch * 8);
        }
        CP_COMMIT();
    };

    issue(0);
    for (int it = 0; it < niter; ++it) {
        if (it + 1 < niter) { issue(it + 1); CP_WAIT(1); }
        else                { CP_WAIT(0); }
        __syncthreads();
        uint32_t s_a = sb + (it & 1) * GY2_STG, s_b = s_a + GY2_TSZ;
#pragma unroll
        for (int ks = 0; ks < 4; ++ks) {
            uint32_t a[4][4];
#pragma unroll
            for (int mf = 0; mf < 4; ++mf)
                ldm_x4(s_a + (wm + mf * 16 + (lane & 15)) * RS2 + ks * 32 + (lane >> 4) * 16, a[mf]);
            uint32_t b[4][2];
#pragma unroll
            for (int p = 0; p < 2; ++p) {
                uint32_t r[4];
                int g = lane >> 3;
                int row = wn + p * 16 + ((g >> 1) << 3) + (lane & 7);
                ldm_x4(s_b + row * RS2 + ks * 32 + (g & 1) * 16, r);
                b[p * 2][0] = r[0]; b[p * 2][1] = r[1];
                b[p * 2 + 1][0] = r[2]; b[p * 2 + 1][1] = r[3];
            }
#pragma unroll
            for (int mf = 0; mf < 4; ++mf)
#pragma unroll
                for (int nf = 0; nf < 4; ++nf)
                    mma_f16(acc[mf][nf], a[mf], b[nf][0], b[nf][1]);
        }
        __syncthreads();
    }

#pragma unroll
    for (int mf = 0; mf < 4; ++mf) {
        int row = m0 + wm + mf * 16 + (lane >> 2);
#pragma unroll
        for (int nf = 0; nf < 4; ++nf) {
            int col = n0 + wn + nf * 8 + 2 * (lane & 3);
            *reinterpret_cast<float2*>(g_Y + (size_t)row * NCOL + col) =
                make_float2(acc[mf][nf][0], acc[mf][nf][1]);
            *reinterpret_cast<float2*>(g_Y + (size_t)(row + 8) * NCOL + col) =
                make_float2(acc[mf][nf][2], acc[mf][nf][3]);
        }
    }
}

// ---------------------------------------------------------------------------
// kernSteps: 32 fused sequential steps in latent space.
//  - feedback reads ONLY the nonzero rows of H (ballot masks)
//  - boundary guard (window 1e-3) with exact fp64 block-cooperative recompute
// Block = 4 rows x 64 threads, grid 1024.
// ---------------------------------------------------------------------------
__global__ void kernSteps(const float* __restrict__ rn, const float* __restrict__ W) {
    int tid = threadIdx.x;
    int rloc = tid >> 6, t = tid & 63;
    int r = blockIdx.x * 4 + rloc;

    __shared__ float yh[4][NB][LAT];          // 32KB
    __shared__ uint32_t msk[4][NB][2];        // nonzero-u masks
    __shared__ unsigned char fl[4][NB];
    __shared__ int s_nz[4], s_idx[4];
    __shared__ int ntrigB;
    __shared__ short s_trig[256];
    __shared__ double redd[256];              // 2KB

    float rnv = rn[r];
    if (t < NB) fl[rloc][t] = 0;

    for (int jb = NB - 1; jb >= 0; --jb) {
        __syncthreads();
        if (tid == 0) ntrigB = 0;
        if (t == 0) { s_nz[rloc] = 0; s_idx[rloc] = -1; }
        __syncthreads();

        float y0 = g_Y[(size_t)r * NCOL + jb * LAT + t];
        float fb = 0.f;
        for (int jj = jb + 1; jj < NB; ++jj) {
            if (fl[rloc][jj]) {
                const float* hb = g_H + ((size_t)(jb * NB + jj) * LAT) * LAT + t;
                const float* yv = yh[rloc][jj];
                uint32_t m = msk[rloc][jj][0];
                while (m) { int u = __ffs(m) - 1; m &= m - 1; fb = fmaf(yv[u], hb[(size_t)u * LAT], fb); }
                m = msk[rloc][jj][1];
                while (m) { int u = __ffs(m) + 31; m &= m - 1; fb = fmaf(yv[u], hb[(size_t)u * LAT], fb); }
            }
        }
        float y = (y0 - fb) / rnv;
        if (fabsf(fabsf(y - rintf(y)) - 0.5f) < 1e-3f) {
            int slot = atomicAdd(&ntrigB, 1);
            s_trig[slot] = (short)tid;
        }
        __syncthreads();
        int nt = ntrigB;
        for (int i = 0; i < nt; ++i) {
            int who = s_trig[i];
            int rr = blockIdx.x * 4 + (who >> 6);
            int n = jb * LAT + (who & 63);
            const float* wr = W + (size_t)rr * NDIM;
            size_t mo = (size_t)n * NDIM;
            double part = 0.0;
            for (int k = jb * BSZ + tid; k < NDIM; k += 256) {
                float mv = __half2float(g_Mt[0][mo + k]) + __half2float(g_Mt[1][mo + k]);
                part += (double)wr[k] * (double)mv;
            }
            redd[tid] = part;
            __syncthreads();
            for (int s2 = 128; s2 > 0; s2 >>= 1) {
                if (tid < s2) redd[tid] += redd[tid + s2];
                __syncthreads();
            }
            if (tid == who) y0 = (float)redd[0];
            __syncthreads();
        }
        if (nt) y = (y0 - fb) / rnv;
        float yhv = rintf(y);
        yh[rloc][jb][t] = yhv;
        uint32_t bal = __ballot_sync(0xFFFFFFFFu, yhv != 0.f);
        if ((t & 31) == 0) {
            msk[rloc][jb][t >> 5] = bal;
            if (bal) s_nz[rloc] = 1;
        }
        __syncthreads();

        int nz = s_nz[rloc];
        if (t == 0) {
            fl[rloc][jb] = (unsigned char)nz;
            g_flags[r * NB + jb] = (unsigned char)nz;
            if (nz) s_idx[rloc] = atomicAdd(&g_cnt, 1);
        }
        __syncthreads();
        if (nz) {
            int idx = s_idx[rloc];
            if (t == 0) g_items[idx] = (r << 5) | jb;
            g_yhl[(size_t)idx * LAT + t] = yhv;
        }
    }
}

// ---------------------------------------------------------------------------
// kernWhat: materialize W_hat blocks for flagged items only.
// ---------------------------------------------------------------------------
__global__ void kernWhat(const float* __restrict__ Wd) {
    __shared__ float s_y[LAT];
    int tid = threadIdx.x;
    int cnt = g_cnt;
    for (int i = blockIdx.x; i < cnt; i += gridDim.x) {
        int item = g_items[i];
        int r = item >> 5, jb = item & 31;
        if (tid < LAT) s_y[tid] = g_yhl[(size_t)i * LAT + tid];
        __syncthreads();
        float x = 0.f;
#pragma unroll 8
        for (int u = 0; u < LAT; ++u)
            x = fmaf(s_y[u], Wd[u * BSZ + tid], x);
        g_What[(size_t)r * NDIM + jb * BSZ + tid] = x;
        __syncthreads();
    }
}

// ---------------------------------------------------------------------------
// kernFillOut: out[b, m] = bias[m].
// ---------------------------------------------------------------------------
__global__ void kernFillOut(const float* __restrict__ bias, float* __restrict__ out) {
    size_t idx = ((size_t)blockIdx.x * 256 + threadIdx.x) * 4;
    int m = (int)(idx & (NDIM - 1));
    float4 bv = *reinterpret_cast<const float4*>(bias + m);
    *reinterpret_cast<float4*>(out + idx) = bv;
}

// ---------------------------------------------------------------------------
// kernSparse: out[:, r] += x[:, jb-block] @ (What[r, jb-block] * rn[r])
// Grid (32 jb, 64 b-tiles of 64), 128 threads, atomicAdd into bias-filled out.
// ---------------------------------------------------------------------------
__global__ void __launch_bounds__(128) kernSparse(const float* __restrict__ x,
                                                  const float* __restrict__ rn,
                                                  float* __restrict__ out) {
    int jb = blockIdx.x;
    int b0 = blockIdx.y * 64;
    int tid = threadIdx.x;
    __shared__ float xs[64][129];
    __shared__ float ws[128];
    __shared__ int s_any;

    int cnt = g_cnt;
    bool any = false;
    for (int i = tid; i < cnt; i += 128)
        if ((g_items[i] & 31) == jb) any = true;
    if (tid == 0) s_any = 0;
    __syncthreads();
    if (any) s_any = 1;
    __syncthreads();
    if (!s_any) return;

    for (int rr = 0; rr < 64; ++rr)
        xs[rr][tid] = x[(size_t)(b0 + rr) * NDIM + jb * BSZ + tid];
    __syncthreads();

    for (int i = 0; i < cnt; ++i) {
        int item = g_items[i];
        if ((item & 31) != jb) continue;
        int r = item >> 5;
        ws[tid] = g_What[(size_t)r * NDIM + jb * BSZ + tid] * rn[r];
        __syncthreads();
        if (tid < 64) {
            float acc = 0.f;
#pragma unroll 16
            for (int k = 0; k < BSZ; ++k)
                acc = fmaf(xs[tid][k], ws[k], acc);
            atomicAdd(&out[(size_t)(b0 + tid) * NDIM + r], acc);
        }
        __syncthreads();
    }
}

// ---------------------------------------------------------------------------
// kernel_launch: inputs (metadata order): x, weight, bias, row_norm, L, We, Wd
// ---------------------------------------------------------------------------
extern "C" void kernel_launch(void* const* d_in, const int* in_sizes, int n_in,
                              void* d_out, int out_size) {
    (void)in_sizes; (void)n_in; (void)out_size;
    const float* x      = (const float*)d_in[0];
    const float* weight = (const float*)d_in[1];
    const float* bias   = (const float*)d_in[2];
    const float* rn     = (const float*)d_in[3];
    const float* L      = (const float*)d_in[4];
    const float* We     = (const float*)d_in[5];
    const float* Wd     = (const float*)d_in[6];
    float* out          = (float*)d_out;

    static bool attr_set = false;
    if (!attr_set) {
        cudaFuncSetAttribute(kernGemmY, cudaFuncAttributeMaxDynamicSharedMemorySize, 2 * GY2_STG);
        attr_set = true;
    }

    kernPrep<<<8224, 256>>>(weight, We);                  // [0] W->fp16 hi, WeT split
    kernG<<<dim3(32, 32), 128, 33280>>>(L, We, Wd);       // [1] Mt + H fused
    kernGemmY<<<dim3(32, 16), 256, 2 * GY2_STG>>>();      // [2] Y (BK=64, 2-stage)
    kernSteps<<<1024, 256>>>(rn, weight);                 // [3] latent steps  <- profiled
    kernWhat<<<1024, 128>>>(Wd);                          // [4] sparse W_hat blocks
    kernFillOut<<<16384, 256>>>(bias, out);               // [5] out = bias
    kernSparse<<<dim3(32, 64), 128>>>(x, rn, out);        // [6] sparse rank-updates
}

// round 15
// speedup vs baseline: 2.5253x; 1.0852x over previous
#include <cuda_runtime.h>
#include <cuda_fp16.h>
#include <cstdint>

#define NDIM 4096
#define NB   32
#define BSZ  128
#define LAT  64
#define NCOL (NB * LAT)   // 2048
#define MAXIT (NDIM * NB)

// Static device scratch.
__device__ __half g_Wh[(size_t)NDIM * NDIM];          // W fp16 hi (GEMM operand)
__device__ __half g_Mt[2][(size_t)NCOL * NDIM];       // Mt[n,k]=M[k,n]; hi/lo fp16
__device__ __half g_WeTh[2][LAT * BSZ];               // WeT[t,c]=We[c,t]; hi/lo
__device__ float g_Y[(size_t)NDIM * NCOL];
__device__ float g_H[(size_t)NB * NB * LAT * LAT];    // H[jb][jj][u][t] (jj>jb valid)
__device__ float g_What[(size_t)NDIM * NDIM];         // valid only for emitted items
__device__ int g_cnt;
__device__ int g_items[MAXIT];
__device__ float g_yhl[(size_t)MAXIT * LAT];

// ---------------------------------------------------------------------------
// Base-target helpers (sm_80+)
// ---------------------------------------------------------------------------
__device__ __forceinline__ uint32_t smem_u32(const void* p) {
    uint32_t a;
    asm("{ .reg .u64 t; cvta.to.shared.u64 t, %1; cvt.u32.u64 %0, t; }" : "=r"(a) : "l"(p));
    return a;
}
#define CP_ASYNC16(s, g) asm volatile("cp.async.cg.shared.global [%0], [%1], 16;" :: "r"(s), "l"(g))
#define CP_COMMIT()      asm volatile("cp.async.commit_group;" ::: "memory")
#define CP_WAIT(n)       asm volatile("cp.async.wait_group %0;" :: "n"(n) : "memory")

__device__ __forceinline__ void ldm_x4(uint32_t addr, uint32_t r[4]) {
    asm volatile("ldmatrix.sync.aligned.m8n8.x4.shared.b16 {%0,%1,%2,%3}, [%4];"
                 : "=r"(r[0]), "=r"(r[1]), "=r"(r[2]), "=r"(r[3]) : "r"(addr));
}
__device__ __forceinline__ void mma_f16(float* c, const uint32_t a[4], uint32_t b0, uint32_t b1) {
    asm volatile(
        "mma.sync.aligned.m16n8k16.row.col.f32.f16.f16.f32 "
        "{%0,%1,%2,%3}, {%4,%5,%6,%7}, {%8,%9}, {%0,%1,%2,%3};"
        : "+f"(c[0]), "+f"(c[1]), "+f"(c[2]), "+f"(c[3])
        : "r"(a[0]), "r"(a[1]), "r"(a[2]), "r"(a[3]), "r"(b0), "r"(b1));
}
__device__ __forceinline__ void split2h(float v, __half& hi, __half& lo) {
    hi = __float2half_rn(v);
    lo = __float2half_rn(v - __half2float(hi));
}

#define RS 80    // smem row stride for BK=32 tiles (64B + 16 pad)
#define RS2 144  // smem row stride for BK=64 tiles (128B + 16 pad)

// ---------------------------------------------------------------------------
// kernPrep: W fp32 -> fp16 hi (blocks 0..8191), WeT split (8192..8223).
// ---------------------------------------------------------------------------
__global__ void kernPrep(const float* __restrict__ W, const float* __restrict__ We) {
    int b = blockIdx.x;
    if (b < 8192) {
        size_t idx = (size_t)b * 256 + threadIdx.x;   // per 8 elems
        const float4* s = reinterpret_cast<const float4*>(W) + idx * 2;
        float4 a = s[0], c = s[1];
        float v[8] = {a.x, a.y, a.z, a.w, c.x, c.y, c.z, c.w};
        __half h[8];
#pragma unroll
        for (int q = 0; q < 8; ++q) h[q] = __float2half_rn(v[q]);
        *reinterpret_cast<uint4*>(g_Wh + idx * 8) = *reinterpret_cast<uint4*>(h);
    } else {
        int idx = (b - 8192) * 256 + threadIdx.x;     // 0..8191
        int t = idx >> 7, c = idx & 127;
        __half h, l;
        split2h(We[c * LAT + t], h, l);
        g_WeTh[0][idx] = h;
        g_WeTh[1][idx] = l;
    }
}

// ---------------------------------------------------------------------------
// kernG (FUSED with H): builds the FULL Mt (fp16 hi+lo) AND H[jb][jj].
//   kt > j : G block via 3-term split fp16 HMMA -> Mt; then H = Wd @ G.
//   kt == j: diagonal We block (split).  kt < j : zero fill (+ g_cnt reset).
// Grid (32 kt, 32 j), 128 threads, dyn smem 33280 B.
// ---------------------------------------------------------------------------
__global__ void __launch_bounds__(128, 4) kernG(const float* __restrict__ L,
                                                const float* __restrict__ We,
                                                const float* __restrict__ Wd) {
    int kt = blockIdx.x, j = blockIdx.y;
    int tid = threadIdx.x;
    int jn = j * LAT, s = j * BSZ;

    if (kt < j) {
        if (kt == 0 && j == 1 && tid == 0) g_cnt = 0;
        uint4 z = make_uint4(0, 0, 0, 0);
        for (int i = tid; i < 64 * 16; i += 128) {
            int rr = i >> 4, c = i & 15;
            size_t o = (size_t)(jn + rr) * NDIM + kt * BSZ + c * 8;
            *reinterpret_cast<uint4*>(g_Mt[0] + o) = z;
            *reinterpret_cast<uint4*>(g_Mt[1] + o) = z;
        }
        return;
    }
    if (kt == j) {
        for (int n = 0; n < LAT; ++n) {
            __half h, l;
            split2h(We[tid * LAT + n], h, l);
            size_t o = (size_t)(jn + n) * NDIM + s + tid;
            g_Mt[0][o] = h;
            g_Mt[1][o] = l;
        }
        return;
    }

    extern __shared__ __align__(128) char sm[];
    uint32_t sb = smem_u32(sm);
    uint32_t sA[2] = {sb, sb + 5120};
    uint32_t sB[2] = {sb + 10240, sb + 20480};
    int wid = tid >> 5, lane = tid & 31;
    int k0g = kt * BSZ;
    int wm = (wid & 1) * 32, wn = (wid >> 1) * 64;

    float acc[2][8][4];
#pragma unroll
    for (int i = 0; i < 2; ++i)
#pragma unroll
        for (int q = 0; q < 8; ++q)
#pragma unroll
            for (int z = 0; z < 4; ++z) acc[i][q][z] = 0.f;

    for (int it = 0; it < 4; ++it) {            // K=128, BK=32
        int kk = it * 32;
#pragma unroll
        for (int q = 0; q < 4; ++q) {
            int id = tid + q * 128;
            int prec = id >> 8, rem = id & 255, row = rem >> 2, ch = rem & 3;
            CP_ASYNC16(sA[prec] + row * RS + ch * 16,
                       g_WeTh[prec] + row * BSZ + kk + ch * 8);
        }
        CP_COMMIT();
#pragma unroll
        for (int q = 0; q < 8; ++q) {           // B: L fp32 -> split fp16 in-reg
            int id = tid + q * 128;
            int row = id >> 3, c = (id & 7) * 4;
            float4 v = *reinterpret_cast<const float4*>(
                L + (size_t)(k0g + row) * NDIM + s + kk + c);
            __half h0, l0, h1, l1, h2, l2, h3, l3;
            split2h(v.x, h0, l0); split2h(v.y, h1, l1);
            split2h(v.z, h2, l2); split2h(v.w, h3, l3);
            __half2 hA = __halves2half2(h0, h1), hB = __halves2half2(h2, h3);
            __half2 lA = __halves2half2(l0, l1), lB = __halves2half2(l2, l3);
            uint2 uh, ul;
            uh.x = *reinterpret_cast<uint32_t*>(&hA); uh.y = *reinterpret_cast<uint32_t*>(&hB);
            ul.x = *reinterpret_cast<uint32_t*>(&lA); ul.y = *reinterpret_cast<uint32_t*>(&lB);
            *reinterpret_cast<uint2*>(sm + 10240 + row * RS + c * 2) = uh;
            *reinterpret_cast<uint2*>(sm + 20480 + row * RS + c * 2) = ul;
        }
        CP_WAIT(0);
        __syncthreads();

#pragma unroll
        for (int ks = 0; ks < 2; ++ks) {
            uint32_t ah[2][4];
#pragma unroll
            for (int mf = 0; mf < 2; ++mf)
                ldm_x4(sA[0] + (wm + mf * 16 + (lane & 15)) * RS + ks * 32 + (lane >> 4) * 16, ah[mf]);
            uint32_t bh[8][2];
#pragma unroll
            for (int p = 0; p < 4; ++p) {
                uint32_t r[4];
                int g = lane >> 3;
                int row = wn + p * 16 + ((g >> 1) << 3) + (lane & 7);
                ldm_x4(sB[0] + row * RS + ks * 32 + (g & 1) * 16, r);
                bh[p * 2][0] = r[0]; bh[p * 2][1] = r[1];
                bh[p * 2 + 1][0] = r[2]; bh[p * 2 + 1][1] = r[3];
            }
#pragma unroll
            for (int mf = 0; mf < 2; ++mf)
#pragma unroll
                for (int nf = 0; nf < 8; ++nf)
                    mma_f16(acc[mf][nf], ah[mf], bh[nf][0], bh[nf][1]);
            uint32_t al[2][4];
#pragma unroll
            for (int mf = 0; mf < 2; ++mf)
                ldm_x4(sA[1] + (wm + mf * 16 + (lane & 15)) * RS + ks * 32 + (lane >> 4) * 16, al[mf]);
#pragma unroll
            for (int mf = 0; mf < 2; ++mf)
#pragma unroll
                for (int nf = 0; nf < 8; ++nf)
                    mma_f16(acc[mf][nf], al[mf], bh[nf][0], bh[nf][1]);
            uint32_t bl[8][2];
#pragma unroll
            for (int p = 0; p < 4; ++p) {
                uint32_t r[4];
                int g = lane >> 3;
                int row = wn + p * 16 + ((g >> 1) << 3) + (lane & 7);
                ldm_x4(sB[1] + row * RS + ks * 32 + (g & 1) * 16, r);
                bl[p * 2][0] = r[0]; bl[p * 2][1] = r[1];
                bl[p * 2 + 1][0] = r[2]; bl[p * 2 + 1][1] = r[3];
            }
#pragma unroll
            for (int mf = 0; mf < 2; ++mf)
#pragma unroll
                for (int nf = 0; nf < 8; ++nf)
                    mma_f16(acc[mf][nf], ah[mf], bl[nf][0], bl[nf][1]);
        }
        __syncthreads();
    }

    // Store split(G) -> Mt
#pragma unroll
    for (int mf = 0; mf < 2; ++mf) {
        int t0 = wm + mf * 16 + (lane >> 2);
#pragma unroll
        for (int nf = 0; nf < 8; ++nf) {
            int kr = wn + nf * 8 + 2 * (lane & 3);
            __half h0, l0, h1, l1, h2, l2, h3, l3;
            split2h(acc[mf][nf][0], h0, l0);
            split2h(acc[mf][nf][1], h1, l1);
            split2h(acc[mf][nf][2], h2, l2);
            split2h(acc[mf][nf][3], h3, l3);
            size_t o0 = (size_t)(jn + t0) * NDIM + k0g + kr;
            size_t o1 = (size_t)(jn + t0 + 8) * NDIM + k0g + kr;
            *reinterpret_cast<__half2*>(g_Mt[0] + o0) = __halves2half2(h0, h1);
            *reinterpret_cast<__half2*>(g_Mt[1] + o0) = __halves2half2(l0, l1);
            *reinterpret_cast<__half2*>(g_Mt[0] + o1) = __halves2half2(h2, h3);
            *reinterpret_cast<__half2*>(g_Mt[1] + o1) = __halves2half2(l2, l3);
        }
    }

    // ---- Fused H phase: H[j][kt][u][t] = sum_c Wd[u][c] * G[c][t] ----
    float* Gs  = reinterpret_cast<float*>(sm);           // [64][65]
    float* Wds = reinterpret_cast<float*>(sm) + 64 * 65; // [64][65]
    int tu = tid >> 4, tt = tid & 15;
    float acc2[8][4];
#pragma unroll
    for (int i = 0; i < 8; ++i)
#pragma unroll
        for (int q = 0; q < 4; ++q) acc2[i][q] = 0.f;

    for (int cc = 0; cc < 2; ++cc) {
        __syncthreads();
        if (wn == cc * 64) {
#pragma unroll
            for (int mf = 0; mf < 2; ++mf) {
                int t0 = wm + mf * 16 + (lane >> 2);
#pragma unroll
                for (int nf = 0; nf < 8; ++nf) {
                    int krl = nf * 8 + 2 * (lane & 3);
                    Gs[(krl)     * 65 + t0]     = acc[mf][nf][0];
                    Gs[(krl + 1) * 65 + t0]     = acc[mf][nf][1];
                    Gs[(krl)     * 65 + t0 + 8] = acc[mf][nf][2];
                    Gs[(krl + 1) * 65 + t0 + 8] = acc[mf][nf][3];
                }
            }
        }
#pragma unroll
        for (int i = 0; i < 8; ++i) {
            int idx = i * 128 + tid;
            int u = idx >> 4, cq = (idx & 15) * 4;
            float4 wv = *reinterpret_cast<const float4*>(Wd + u * BSZ + cc * 64 + cq);
            Wds[u * 65 + cq + 0] = wv.x; Wds[u * 65 + cq + 1] = wv.y;
            Wds[u * 65 + cq + 2] = wv.z; Wds[u * 65 + cq + 3] = wv.w;
        }
        __syncthreads();
#pragma unroll 4
        for (int c = 0; c < 64; ++c) {
            float w[8], g[4];
#pragma unroll
            for (int i = 0; i < 8; ++i) w[i] = Wds[(tu * 8 + i) * 65 + c];
#pragma unroll
            for (int q = 0; q < 4; ++q) g[q] = Gs[c * 65 + tt * 4 + q];
#pragma unroll
            for (int i = 0; i < 8; ++i)
#pragma unroll
                for (int q = 0; q < 4; ++q)
                    acc2[i][q] = fmaf(w[i], g[q], acc2[i][q]);
        }
    }

    size_t hb = (((size_t)j * NB + kt) * LAT) * LAT;
#pragma unroll
    for (int i = 0; i < 8; ++i)
#pragma unroll
        for (int q = 0; q < 4; ++q)
            g_H[hb + (size_t)(tu * 8 + i) * LAT + tt * 4 + q] = acc2[i][q];
}

// ---------------------------------------------------------------------------
// kernGemmY: Y = W @ M^T, SINGLE fp16 hh HMMA pass, fp32 accum. BK=64.
// Double-buffered cp.async (2 x 36864 B dyn smem). Guarded by kernSteps.
// ---------------------------------------------------------------------------
#define GY2_TSZ (128 * RS2)          // 18432
#define GY2_STG (2 * GY2_TSZ)        // 36864
__global__ void __launch_bounds__(256, 2) kernGemmY() {
    extern __shared__ __align__(128) char sm[];
    uint32_t sb = smem_u32(sm);
    int tid = threadIdx.x, wid = tid >> 5, lane = tid & 31;
    int m0 = blockIdx.x * 128, n0 = blockIdx.y * 128;
    int kst = n0 * 2;
    int niter = (NDIM - kst) / 64;
    int wm = (wid & 1) * 64, wn = (wid >> 1) * 32;

    float acc[4][4][4];
#pragma unroll
    for (int i = 0; i < 4; ++i)
#pragma unroll
        for (int q = 0; q < 4; ++q)
#pragma unroll
            for (int z = 0; z < 4; ++z) acc[i][q][z] = 0.f;

    auto issue = [&](int it) {
        int k0 = kst + it * 64;
        uint32_t s_a = sb + (it & 1) * GY2_STG, s_b = s_a + GY2_TSZ;
#pragma unroll
        for (int q = 0; q < 4; ++q) {
            int id = tid + q * 256, row = id >> 3, ch = id & 7;
            CP_ASYNC16(s_a + row * RS2 + ch * 16, g_Wh + (size_t)(m0 + row) * NDIM + k0 + ch * 8);
            CP_ASYNC16(s_b + row * RS2 + ch * 16, g_Mt[0] + (size_t)(n0 + row) * NDIM + k0 + ch * 8);
        }
        CP_COMMIT();
    };

    issue(0);
    for (int it = 0; it < niter; ++it) {
        if (it + 1 < niter) { issue(it + 1); CP_WAIT(1); }
        else                { CP_WAIT(0); }
        __syncthreads();
        uint32_t s_a = sb + (it & 1) * GY2_STG, s_b = s_a + GY2_TSZ;
#pragma unroll
        for (int ks = 0; ks < 4; ++ks) {
            uint32_t a[4][4];
#pragma unroll
            for (int mf = 0; mf < 4; ++mf)
                ldm_x4(s_a + (wm + mf * 16 + (lane & 15)) * RS2 + ks * 32 + (lane >> 4) * 16, a[mf]);
            uint32_t b[4][2];
#pragma unroll
            for (int p = 0; p < 2; ++p) {
                uint32_t r[4];
                int g = lane >> 3;
                int row = wn + p * 16 + ((g >> 1) << 3) + (lane & 7);
                ldm_x4(s_b + row * RS2 + ks * 32 + (g & 1) * 16, r);
                b[p * 2][0] = r[0]; b[p * 2][1] = r[1];
                b[p * 2 + 1][0] = r[2]; b[p * 2 + 1][1] = r[3];
            }
#pragma unroll
            for (int mf = 0; mf < 4; ++mf)
#pragma unroll
                for (int nf = 0; nf < 4; ++nf)
                    mma_f16(acc[mf][nf], a[mf], b[nf][0], b[nf][1]);
        }
        __syncthreads();
    }

#pragma unroll
    for (int mf = 0; mf < 4; ++mf) {
        int row = m0 + wm + mf * 16 + (lane >> 2);
#pragma unroll
        for (int nf = 0; nf < 4; ++nf) {
            int col = n0 + wn + nf * 8 + 2 * (lane & 3);
            *reinterpret_cast<float2*>(g_Y + (size_t)row * NCOL + col) =
                make_float2(acc[mf][nf][0], acc[mf][nf][1]);
            *reinterpret_cast<float2*>(g_Y + (size_t)(row + 8) * NCOL + col) =
                make_float2(acc[mf][nf][2], acc[mf][nf][3]);
        }
    }
}

// ---------------------------------------------------------------------------
// kernSteps v4: WARP-PER-ROW latent recurrence. Zero block barriers.
// Each warp owns one row; lane handles t = lane and t+32. Flagged-block set
// is a warp-uniform register bitmask; feedback bit-scans only flagged blocks.
// Boundary guard (1e-3) -> warp-level exact fp64 recompute.
// Grid 1024, block 128 (4 warps = 4 rows).
// ---------------------------------------------------------------------------
__global__ void __launch_bounds__(128) kernSteps(const float* __restrict__ rn,
                                                 const float* __restrict__ W) {
    int wid = threadIdx.x >> 5, lane = threadIdx.x & 31;
    int r = blockIdx.x * 4 + wid;

    __shared__ float yh[4][NB][LAT];        // 32KB
    __shared__ uint32_t msk[4][NB][2];

    float rnv = rn[r];
    uint32_t flmask = 0;                    // warp-uniform: flagged jj set (all > current jb)

    for (int jb = NB - 1; jb >= 0; --jb) {
        float y0a = g_Y[(size_t)r * NCOL + jb * LAT + lane];
        float y0b = g_Y[(size_t)r * NCOL + jb * LAT + lane + 32];
        float fba = 0.f, fbb = 0.f;

        uint32_t fm = flmask;
        while (fm) {
            int jj = __ffs(fm) - 1; fm &= fm - 1;
            const float* hb = g_H + ((size_t)(jb * NB + jj) * LAT) * LAT;
            const float* yv = yh[wid][jj];
            uint32_t m = msk[wid][jj][0];
            while (m) {
                int u = __ffs(m) - 1; m &= m - 1;
                float yu = yv[u];
                fba = fmaf(yu, hb[(size_t)u * LAT + lane], fba);
                fbb = fmaf(yu, hb[(size_t)u * LAT + lane + 32], fbb);
            }
            m = msk[wid][jj][1];
            while (m) {
                int u = __ffs(m) + 31; m &= m - 1;
                float yu = yv[u];
                fba = fmaf(yu, hb[(size_t)u * LAT + lane], fba);
                fbb = fmaf(yu, hb[(size_t)u * LAT + lane + 32], fbb);
            }
        }

        float ya = (y0a - fba) / rnv;
        float yb = (y0b - fbb) / rnv;

        // Boundary guard (fp16-hh GEMM error < ~1.5e-4; window 1e-3).
        bool ta = fabsf(fabsf(ya - rintf(ya)) - 0.5f) < 1e-3f;
        bool tb = fabsf(fabsf(yb - rintf(yb)) - 0.5f) < 1e-3f;
        uint32_t ballots[2] = {__ballot_sync(0xFFFFFFFFu, ta), __ballot_sync(0xFFFFFFFFu, tb)};
#pragma unroll
        for (int h = 0; h < 2; ++h) {
            uint32_t tm = ballots[h];
            while (tm) {
                int who = __ffs(tm) - 1; tm &= tm - 1;
                int n = jb * LAT + who + h * 32;
                const float* wr = W + (size_t)r * NDIM;
                size_t mo = (size_t)n * NDIM;
                double part = 0.0;
                for (int k = jb * BSZ + lane; k < NDIM; k += 32) {
                    float mv = __half2float(g_Mt[0][mo + k]) + __half2float(g_Mt[1][mo + k]);
                    part += (double)wr[k] * (double)mv;
                }
#pragma unroll
                for (int o = 16; o; o >>= 1)
                    part += __shfl_xor_sync(0xFFFFFFFFu, part, o);
                if (lane == who) {
                    if (h == 0) y0a = (float)part; else y0b = (float)part;
                }
            }
        }
        if (ballots[0]) ya = (y0a - fba) / rnv;
        if (ballots[1]) yb = (y0b - fbb) / rnv;

        float yha = rintf(ya), yhb = rintf(yb);
        yh[wid][jb][lane] = yha;
        yh[wid][jb][lane + 32] = yhb;
        uint32_t b0 = __ballot_sync(0xFFFFFFFFu, yha != 0.f);
        uint32_t b1 = __ballot_sync(0xFFFFFFFFu, yhb != 0.f);
        if (lane == 0) {
            msk[wid][jb][0] = b0;
            msk[wid][jb][1] = b1;
        }
        if (b0 | b1) {
            flmask |= (1u << jb);
            int idx = 0;
            if (lane == 0) {
                idx = atomicAdd(&g_cnt, 1);
                g_items[idx] = (r << 5) | jb;
            }
            idx = __shfl_sync(0xFFFFFFFFu, idx, 0);
            g_yhl[(size_t)idx * LAT + lane] = yha;
            g_yhl[(size_t)idx * LAT + lane + 32] = yhb;
        }
        __syncwarp();
    }
}

// ---------------------------------------------------------------------------
// kernWhat: materialize W_hat blocks for emitted items only.
// ---------------------------------------------------------------------------
__global__ void kernWhat(const float* __restrict__ Wd) {
    __shared__ float s_y[LAT];
    int tid = threadIdx.x;
    int cnt = g_cnt;
    for (int i = blockIdx.x; i < cnt; i += gridDim.x) {
        int item = g_items[i];
        int r = item >> 5, jb = item & 31;
        if (tid < LAT) s_y[tid] = g_yhl[(size_t)i * LAT + tid];
        __syncthreads();
        float x = 0.f;
#pragma unroll 8
        for (int u = 0; u < LAT; ++u)
            x = fmaf(s_y[u], Wd[u * BSZ + tid], x);
        g_What[(size_t)r * NDIM + jb * BSZ + tid] = x;
        __syncthreads();
    }
}

// ---------------------------------------------------------------------------
// kernFillOut: out[b, m] = bias[m].
// ---------------------------------------------------------------------------
__global__ void kernFillOut(const float* __restrict__ bias, float* __restrict__ out) {
    size_t idx = ((size_t)blockIdx.x * 256 + threadIdx.x) * 4;
    int m = (int)(idx & (NDIM - 1));
    float4 bv = *reinterpret_cast<const float4*>(bias + m);
    *reinterpret_cast<float4*>(out + idx) = bv;
}

// ---------------------------------------------------------------------------
// kernSparse: out[:, r] += x[:, jb-block] @ (What[r, jb-block] * rn[r])
// Grid (32 jb, 64 b-tiles of 64), 128 threads, atomicAdd into bias-filled out.
// ---------------------------------------------------------------------------
__global__ void __launch_bounds__(128) kernSparse(const float* __restrict__ x,
                                                  const float* __restrict__ rn,
                                                  float* __restrict__ out) {
    int jb = blockIdx.x;
    int b0 = blockIdx.y * 64;
    int tid = threadIdx.x;
    __shared__ float xs[64][129];
    __shared__ float ws[128];
    __shared__ int s_any;

    int cnt = g_cnt;
    bool any = false;
    for (int i = tid; i < cnt; i += 128)
        if ((g_items[i] & 31) == jb) any = true;
    if (tid == 0) s_any = 0;
    __syncthreads();
    if (any) s_any = 1;
    __syncthreads();
    if (!s_any) return;

    for (int rr = 0; rr < 64; ++rr)
        xs[rr][tid] = x[(size_t)(b0 + rr) * NDIM + jb * BSZ + tid];
    __syncthreads();

    for (int i = 0; i < cnt; ++i) {
        int item = g_items[i];
        if ((item & 31) != jb) continue;
        int r = item >> 5;
        ws[tid] = g_What[(size_t)r * NDIM + jb * BSZ + tid] * rn[r];
        __syncthreads();
        if (tid < 64) {
            float acc = 0.f;
#pragma unroll 16
            for (int k = 0; k < BSZ; ++k)
                acc = fmaf(xs[tid][k], ws[k], acc);
            atomicAdd(&out[(size_t)(b0 + tid) * NDIM + r], acc);
        }
        __syncthreads();
    }
}

// ---------------------------------------------------------------------------
// kernel_launch: inputs (metadata order): x, weight, bias, row_norm, L, We, Wd
// ---------------------------------------------------------------------------
extern "C" void kernel_launch(void* const* d_in, const int* in_sizes, int n_in,
                              void* d_out, int out_size) {
    (void)in_sizes; (void)n_in; (void)out_size;
    const float* x      = (const float*)d_in[0];
    const float* weight = (const float*)d_in[1];
    const float* bias   = (const float*)d_in[2];
    const float* rn     = (const float*)d_in[3];
    const float* L      = (const float*)d_in[4];
    const float* We     = (const float*)d_in[5];
    const float* Wd     = (const float*)d_in[6];
    float* out          = (float*)d_out;

    static bool attr_set = false;
    if (!attr_set) {
        cudaFuncSetAttribute(kernGemmY, cudaFuncAttributeMaxDynamicSharedMemorySize, 2 * GY2_STG);
        attr_set = true;
    }

    kernPrep<<<8224, 256>>>(weight, We);                  // [0] W->fp16 hi, WeT split
    kernG<<<dim3(32, 32), 128, 33280>>>(L, We, Wd);       // [1] Mt + H fused
    kernGemmY<<<dim3(32, 16), 256, 2 * GY2_STG>>>();      // [2] Y (BK=64, 2-stage)
    kernSteps<<<1024, 128>>>(rn, weight);                 // [3] warp-per-row  <- profiled
    kernWhat<<<1024, 128>>>(Wd);                          // [4] sparse W_hat blocks
    kernFillOut<<<16384, 256>>>(bias, out);               // [5] out = bias
    kernSparse<<<dim3(32, 64), 128>>>(x, rn, out);        // [6] sparse rank-updates
}

// round 16
// speedup vs baseline: 2.5701x; 1.0177x over previous
#include <cuda_runtime.h>
#include <cuda_fp16.h>
#include <cstdint>

#define NDIM 4096
#define NB   32
#define BSZ  128
#define LAT  64
#define NCOL (NB * LAT)   // 2048
#define MAXIT (NDIM * NB)

// Static device scratch.
__device__ __half g_Wh[(size_t)NDIM * NDIM];          // W fp16 hi (GEMM operand)
__device__ __half g_Mt[2][(size_t)NCOL * NDIM];       // Mt[n,k]=M[k,n]; hi/lo fp16
__device__ __half g_WeTh[2][LAT * BSZ];               // WeT[t,c]=We[c,t]; hi/lo
__device__ float g_Y[(size_t)NDIM * NCOL];
__device__ float g_H[(size_t)NB * NB * LAT * LAT];    // H[jb][jj][u][t] (jj>jb valid)
__device__ float g_What[(size_t)NDIM * NDIM];         // valid only for emitted items
__device__ int g_cnt;
__device__ int g_items[MAXIT];
__device__ float g_yhl[(size_t)MAXIT * LAT];

// ---------------------------------------------------------------------------
// Base-target helpers (sm_80+)
// ---------------------------------------------------------------------------
__device__ __forceinline__ uint32_t smem_u32(const void* p) {
    uint32_t a;
    asm("{ .reg .u64 t; cvta.to.shared.u64 t, %1; cvt.u32.u64 %0, t; }" : "=r"(a) : "l"(p));
    return a;
}
#define CP_ASYNC16(s, g) asm volatile("cp.async.cg.shared.global [%0], [%1], 16;" :: "r"(s), "l"(g))
#define CP_COMMIT()      asm volatile("cp.async.commit_group;" ::: "memory")
#define CP_WAIT(n)       asm volatile("cp.async.wait_group %0;" :: "n"(n) : "memory")

__device__ __forceinline__ void ldm_x4(uint32_t addr, uint32_t r[4]) {
    asm volatile("ldmatrix.sync.aligned.m8n8.x4.shared.b16 {%0,%1,%2,%3}, [%4];"
                 : "=r"(r[0]), "=r"(r[1]), "=r"(r[2]), "=r"(r[3]) : "r"(addr));
}
__device__ __forceinline__ void mma_f16(float* c, const uint32_t a[4], uint32_t b0, uint32_t b1) {
    asm volatile(
        "mma.sync.aligned.m16n8k16.row.col.f32.f16.f16.f32 "
        "{%0,%1,%2,%3}, {%4,%5,%6,%7}, {%8,%9}, {%0,%1,%2,%3};"
        : "+f"(c[0]), "+f"(c[1]), "+f"(c[2]), "+f"(c[3])
        : "r"(a[0]), "r"(a[1]), "r"(a[2]), "r"(a[3]), "r"(b0), "r"(b1));
}
__device__ __forceinline__ void split2h(float v, __half& hi, __half& lo) {
    hi = __float2half_rn(v);
    lo = __float2half_rn(v - __half2float(hi));
}

#define RS 80    // smem row stride for BK=32 tiles (64B + 16 pad)
#define RS2 144  // smem row stride for BK=64 tiles (128B + 16 pad)

// ---------------------------------------------------------------------------
// kernPrep: W fp32 -> fp16 hi (blocks 0..8191), WeT split (8192..8223).
// ---------------------------------------------------------------------------
__global__ void kernPrep(const float* __restrict__ W, const float* __restrict__ We) {
    int b = blockIdx.x;
    if (b < 8192) {
        size_t idx = (size_t)b * 256 + threadIdx.x;   // per 8 elems
        const float4* s = reinterpret_cast<const float4*>(W) + idx * 2;
        float4 a = s[0], c = s[1];
        float v[8] = {a.x, a.y, a.z, a.w, c.x, c.y, c.z, c.w};
        __half h[8];
#pragma unroll
        for (int q = 0; q < 8; ++q) h[q] = __float2half_rn(v[q]);
        *reinterpret_cast<uint4*>(g_Wh + idx * 8) = *reinterpret_cast<uint4*>(h);
    } else {
        int idx = (b - 8192) * 256 + threadIdx.x;     // 0..8191
        int t = idx >> 7, c = idx & 127;
        __half h, l;
        split2h(We[c * LAT + t], h, l);
        g_WeTh[0][idx] = h;
        g_WeTh[1][idx] = l;
    }
}

// ---------------------------------------------------------------------------
// kernG (FUSED with H): builds the FULL Mt (fp16 hi+lo) AND H[jb][jj].
//   kt > j : G block via 3-term split fp16 HMMA -> Mt; then H = Wd @ G.
//   kt == j: diagonal We block (split).  kt < j : zero fill (+ g_cnt reset).
// Grid (32 kt, 32 j), 128 threads, dyn smem 33280 B.
// ---------------------------------------------------------------------------
__global__ void __launch_bounds__(128, 4) kernG(const float* __restrict__ L,
                                                const float* __restrict__ We,
                                                const float* __restrict__ Wd) {
    int kt = blockIdx.x, j = blockIdx.y;
    int tid = threadIdx.x;
    int jn = j * LAT, s = j * BSZ;

    if (kt < j) {
        if (kt == 0 && j == 1 && tid == 0) g_cnt = 0;
        uint4 z = make_uint4(0, 0, 0, 0);
        for (int i = tid; i < 64 * 16; i += 128) {
            int rr = i >> 4, c = i & 15;
            size_t o = (size_t)(jn + rr) * NDIM + kt * BSZ + c * 8;
            *reinterpret_cast<uint4*>(g_Mt[0] + o) = z;
            *reinterpret_cast<uint4*>(g_Mt[1] + o) = z;
        }
        return;
    }
    if (kt == j) {
        for (int n = 0; n < LAT; ++n) {
            __half h, l;
            split2h(We[tid * LAT + n], h, l);
            size_t o = (size_t)(jn + n) * NDIM + s + tid;
            g_Mt[0][o] = h;
            g_Mt[1][o] = l;
        }
        return;
    }

    extern __shared__ __align__(128) char sm[];
    uint32_t sb = smem_u32(sm);
    uint32_t sA[2] = {sb, sb + 5120};
    uint32_t sB[2] = {sb + 10240, sb + 20480};
    int wid = tid >> 5, lane = tid & 31;
    int k0g = kt * BSZ;
    int wm = (wid & 1) * 32, wn = (wid >> 1) * 64;

    float acc[2][8][4];
#pragma unroll
    for (int i = 0; i < 2; ++i)
#pragma unroll
        for (int q = 0; q < 8; ++q)
#pragma unroll
            for (int z = 0; z < 4; ++z) acc[i][q][z] = 0.f;

    for (int it = 0; it < 4; ++it) {            // K=128, BK=32
        int kk = it * 32;
#pragma unroll
        for (int q = 0; q < 4; ++q) {
            int id = tid + q * 128;
            int prec = id >> 8, rem = id & 255, row = rem >> 2, ch = rem & 3;
            CP_ASYNC16(sA[prec] + row * RS + ch * 16,
                       g_WeTh[prec] + row * BSZ + kk + ch * 8);
        }
        CP_COMMIT();
#pragma unroll
        for (int q = 0; q < 8; ++q) {           // B: L fp32 -> split fp16 in-reg
            int id = tid + q * 128;
            int row = id >> 3, c = (id & 7) * 4;
            float4 v = *reinterpret_cast<const float4*>(
                L + (size_t)(k0g + row) * NDIM + s + kk + c);
            __half h0, l0, h1, l1, h2, l2, h3, l3;
            split2h(v.x, h0, l0); split2h(v.y, h1, l1);
            split2h(v.z, h2, l2); split2h(v.w, h3, l3);
            __half2 hA = __halves2half2(h0, h1), hB = __halves2half2(h2, h3);
            __half2 lA = __halves2half2(l0, l1), lB = __halves2half2(l2, l3);
            uint2 uh, ul;
            uh.x = *reinterpret_cast<uint32_t*>(&hA); uh.y = *reinterpret_cast<uint32_t*>(&hB);
            ul.x = *reinterpret_cast<uint32_t*>(&lA); ul.y = *reinterpret_cast<uint32_t*>(&lB);
            *reinterpret_cast<uint2*>(sm + 10240 + row * RS + c * 2) = uh;
            *reinterpret_cast<uint2*>(sm + 20480 + row * RS + c * 2) = ul;
        }
        CP_WAIT(0);
        __syncthreads();

#pragma unroll
        for (int ks = 0; ks < 2; ++ks) {
            uint32_t ah[2][4];
#pragma unroll
            for (int mf = 0; mf < 2; ++mf)
                ldm_x4(sA[0] + (wm + mf * 16 + (lane & 15)) * RS + ks * 32 + (lane >> 4) * 16, ah[mf]);
            uint32_t bh[8][2];
#pragma unroll
            for (int p = 0; p < 4; ++p) {
                uint32_t r[4];
                int g = lane >> 3;
                int row = wn + p * 16 + ((g >> 1) << 3) + (lane & 7);
                ldm_x4(sB[0] + row * RS + ks * 32 + (g & 1) * 16, r);
                bh[p * 2][0] = r[0]; bh[p * 2][1] = r[1];
                bh[p * 2 + 1][0] = r[2]; bh[p * 2 + 1][1] = r[3];
            }
#pragma unroll
            for (int mf = 0; mf < 2; ++mf)
#pragma unroll
                for (int nf = 0; nf < 8; ++nf)
                    mma_f16(acc[mf][nf], ah[mf], bh[nf][0], bh[nf][1]);
            uint32_t al[2][4];
#pragma unroll
            for (int mf = 0; mf < 2; ++mf)
                ldm_x4(sA[1] + (wm + mf * 16 + (lane & 15)) * RS + ks * 32 + (lane >> 4) * 16, al[mf]);
#pragma unroll
            for (int mf = 0; mf < 2; ++mf)
#pragma unroll
                for (int nf = 0; nf < 8; ++nf)
                    mma_f16(acc[mf][nf], al[mf], bh[nf][0], bh[nf][1]);
            uint32_t bl[8][2];
#pragma unroll
            for (int p = 0; p < 4; ++p) {
                uint32_t r[4];
                int g = lane >> 3;
                int row = wn + p * 16 + ((g >> 1) << 3) + (lane & 7);
                ldm_x4(sB[1] + row * RS + ks * 32 + (g & 1) * 16, r);
                bl[p * 2][0] = r[0]; bl[p * 2][1] = r[1];
                bl[p * 2 + 1][0] = r[2]; bl[p * 2 + 1][1] = r[3];
            }
#pragma unroll
            for (int mf = 0; mf < 2; ++mf)
#pragma unroll
                for (int nf = 0; nf < 8; ++nf)
                    mma_f16(acc[mf][nf], ah[mf], bl[nf][0], bl[nf][1]);
        }
        __syncthreads();
    }

    // Store split(G) -> Mt
#pragma unroll
    for (int mf = 0; mf < 2; ++mf) {
        int t0 = wm + mf * 16 + (lane >> 2);
#pragma unroll
        for (int nf = 0; nf < 8; ++nf) {
            int kr = wn + nf * 8 + 2 * (lane & 3);
            __half h0, l0, h1, l1, h2, l2, h3, l3;
            split2h(acc[mf][nf][0], h0, l0);
            split2h(acc[mf][nf][1], h1, l1);
            split2h(acc[mf][nf][2], h2, l2);
            split2h(acc[mf][nf][3], h3, l3);
            size_t o0 = (size_t)(jn + t0) * NDIM + k0g + kr;
            size_t o1 = (size_t)(jn + t0 + 8) * NDIM + k0g + kr;
            *reinterpret_cast<__half2*>(g_Mt[0] + o0) = __halves2half2(h0, h1);
            *reinterpret_cast<__half2*>(g_Mt[1] + o0) = __halves2half2(l0, l1);
            *reinterpret_cast<__half2*>(g_Mt[0] + o1) = __halves2half2(h2, h3);
            *reinterpret_cast<__half2*>(g_Mt[1] + o1) = __halves2half2(l2, l3);
        }
    }

    // ---- Fused H phase: H[j][kt][u][t] = sum_c Wd[u][c] * G[c][t] ----
    float* Gs  = reinterpret_cast<float*>(sm);           // [64][65]
    float* Wds = reinterpret_cast<float*>(sm) + 64 * 65; // [64][65]
    int tu = tid >> 4, tt = tid & 15;
    float acc2[8][4];
#pragma unroll
    for (int i = 0; i < 8; ++i)
#pragma unroll
        for (int q = 0; q < 4; ++q) acc2[i][q] = 0.f;

    for (int cc = 0; cc < 2; ++cc) {
        __syncthreads();
        if (wn == cc * 64) {
#pragma unroll
            for (int mf = 0; mf < 2; ++mf) {
                int t0 = wm + mf * 16 + (lane >> 2);
#pragma unroll
                for (int nf = 0; nf < 8; ++nf) {
                    int krl = nf * 8 + 2 * (lane & 3);
                    Gs[(krl)     * 65 + t0]     = acc[mf][nf][0];
                    Gs[(krl + 1) * 65 + t0]     = acc[mf][nf][1];
                    Gs[(krl)     * 65 + t0 + 8] = acc[mf][nf][2];
                    Gs[(krl + 1) * 65 + t0 + 8] = acc[mf][nf][3];
                }
            }
        }
#pragma unroll
        for (int i = 0; i < 8; ++i) {
            int idx = i * 128 + tid;
            int u = idx >> 4, cq = (idx & 15) * 4;
            float4 wv = *reinterpret_cast<const float4*>(Wd + u * BSZ + cc * 64 + cq);
            Wds[u * 65 + cq + 0] = wv.x; Wds[u * 65 + cq + 1] = wv.y;
            Wds[u * 65 + cq + 2] = wv.z; Wds[u * 65 + cq + 3] = wv.w;
        }
        __syncthreads();
#pragma unroll 4
        for (int c = 0; c < 64; ++c) {
            float w[8], g[4];
#pragma unroll
            for (int i = 0; i < 8; ++i) w[i] = Wds[(tu * 8 + i) * 65 + c];
#pragma unroll
            for (int q = 0; q < 4; ++q) g[q] = Gs[c * 65 + tt * 4 + q];
#pragma unroll
            for (int i = 0; i < 8; ++i)
#pragma unroll
                for (int q = 0; q < 4; ++q)
                    acc2[i][q] = fmaf(w[i], g[q], acc2[i][q]);
        }
    }

    size_t hb = (((size_t)j * NB + kt) * LAT) * LAT;
#pragma unroll
    for (int i = 0; i < 8; ++i)
#pragma unroll
        for (int q = 0; q < 4; ++q)
            g_H[hb + (size_t)(tu * 8 + i) * LAT + tt * 4 + q] = acc2[i][q];
}

// ---------------------------------------------------------------------------
// kernGemmY: Y = W @ M^T, SINGLE fp16 hh HMMA pass, fp32 accum. BK=64.
// Double-buffered cp.async (2 x 36864 B dyn smem). Guarded by kernSteps.
// ---------------------------------------------------------------------------
#define GY2_TSZ (128 * RS2)          // 18432
#define GY2_STG (2 * GY2_TSZ)        // 36864
__global__ void __launch_bounds__(256, 2) kernGemmY() {
    extern __shared__ __align__(128) char sm[];
    uint32_t sb = smem_u32(sm);
    int tid = threadIdx.x, wid = tid >> 5, lane = tid & 31;
    int m0 = blockIdx.x * 128, n0 = blockIdx.y * 128;
    int kst = n0 * 2;
    int niter = (NDIM - kst) / 64;
    int wm = (wid & 1) * 64, wn = (wid >> 1) * 32;

    float acc[4][4][4];
#pragma unroll
    for (int i = 0; i < 4; ++i)
#pragma unroll
        for (int q = 0; q < 4; ++q)
#pragma unroll
            for (int z = 0; z < 4; ++z) acc[i][q][z] = 0.f;

    auto issue = [&](int it) {
        int k0 = kst + it * 64;
        uint32_t s_a = sb + (it & 1) * GY2_STG, s_b = s_a + GY2_TSZ;
#pragma unroll
        for (int q = 0; q < 4; ++q) {
            int id = tid + q * 256, row = id >> 3, ch = id & 7;
            CP_ASYNC16(s_a + row * RS2 + ch * 16, g_Wh + (size_t)(m0 + row) * NDIM + k0 + ch * 8);
            CP_ASYNC16(s_b + row * RS2 + ch * 16, g_Mt[0] + (size_t)(n0 + row) * NDIM + k0 + ch * 8);
        }
        CP_COMMIT();
    };

    issue(0);
    for (int it = 0; it < niter; ++it) {
        if (it + 1 < niter) { issue(it + 1); CP_WAIT(1); }
        else                { CP_WAIT(0); }
        __syncthreads();
        uint32_t s_a = sb + (it & 1) * GY2_STG, s_b = s_a + GY2_TSZ;
#pragma unroll
        for (int ks = 0; ks < 4; ++ks) {
            uint32_t a[4][4];
#pragma unroll
            for (int mf = 0; mf < 4; ++mf)
                ldm_x4(s_a + (wm + mf * 16 + (lane & 15)) * RS2 + ks * 32 + (lane >> 4) * 16, a[mf]);
            uint32_t b[4][2];
#pragma unroll
            for (int p = 0; p < 2; ++p) {
                uint32_t r[4];
                int g = lane >> 3;
                int row = wn + p * 16 + ((g >> 1) << 3) + (lane & 7);
                ldm_x4(s_b + row * RS2 + ks * 32 + (g & 1) * 16, r);
                b[p * 2][0] = r[0]; b[p * 2][1] = r[1];
                b[p * 2 + 1][0] = r[2]; b[p * 2 + 1][1] = r[3];
            }
#pragma unroll
            for (int mf = 0; mf < 4; ++mf)
#pragma unroll
                for (int nf = 0; nf < 4; ++nf)
                    mma_f16(acc[mf][nf], a[mf], b[nf][0], b[nf][1]);
        }
        __syncthreads();
    }

#pragma unroll
    for (int mf = 0; mf < 4; ++mf) {
        int row = m0 + wm + mf * 16 + (lane >> 2);
#pragma unroll
        for (int nf = 0; nf < 4; ++nf) {
            int col = n0 + wn + nf * 8 + 2 * (lane & 3);
            *reinterpret_cast<float2*>(g_Y + (size_t)row * NCOL + col) =
                make_float2(acc[mf][nf][0], acc[mf][nf][1]);
            *reinterpret_cast<float2*>(g_Y + (size_t)(row + 8) * NCOL + col) =
                make_float2(acc[mf][nf][2], acc[mf][nf][3]);
        }
    }
}

// ---------------------------------------------------------------------------
// kernSteps v5: warp-per-row latent recurrence with FULL-ROW SMEM PREFETCH.
// The 4 rows' Y (4x8KB) are cp.async'ed into shared up front (bandwidth-
// bound, not latency-bound); the 32-step loop then runs entirely out of
// shared, with yhat overwriting Y in place (Y[jb] is dead after step jb).
// Global loads in the loop only for rare flagged-H rows / boundary guards.
// Grid 1024, block 128 (4 warps = 4 rows). smem 33KB static.
// ---------------------------------------------------------------------------
__global__ void __launch_bounds__(128) kernSteps(const float* __restrict__ rn,
                                                 const float* __restrict__ W) {
    __shared__ float sY[4][NCOL];           // 32KB: Y -> (overwritten) yhat
    __shared__ uint32_t msk[4][NB][2];

    int tid = threadIdx.x, wid = tid >> 5, lane = tid & 31;
    int rbase = blockIdx.x * 4;
    int r = rbase + wid;

    // Prefetch all 4 rows of Y: 2048 chunks of 16B, 16 per thread.
    {
        uint32_t sbase = smem_u32(&sY[0][0]);
#pragma unroll
        for (int q = 0; q < 16; ++q) {
            int id = tid + q * 128;             // 0..2047
            int row = id >> 9, ch = id & 511;   // 512 chunks per row
            CP_ASYNC16(sbase + id * 16, g_Y + (size_t)(rbase + row) * NCOL + ch * 4);
        }
        CP_COMMIT();
        CP_WAIT(0);
        __syncthreads();
    }

    float rnv = rn[r];
    float* sy = sY[wid];
    uint32_t flmask = 0;                    // warp-uniform flagged-jj set

    for (int jb = NB - 1; jb >= 0; --jb) {
        float y0a = sy[jb * LAT + lane];
        float y0b = sy[jb * LAT + lane + 32];
        float fba = 0.f, fbb = 0.f;

        uint32_t fm = flmask;
        while (fm) {
            int jj = __ffs(fm) - 1; fm &= fm - 1;
            const float* hb = g_H + ((size_t)(jb * NB + jj) * LAT) * LAT;
            const float* yv = &sy[jj * LAT];      // holds yhat for block jj
            uint32_t m = msk[wid][jj][0];
            while (m) {
                int u = __ffs(m) - 1; m &= m - 1;
                float yu = yv[u];
                fba = fmaf(yu, hb[(size_t)u * LAT + lane], fba);
                fbb = fmaf(yu, hb[(size_t)u * LAT + lane + 32], fbb);
            }
            m = msk[wid][jj][1];
            while (m) {
                int u = __ffs(m) + 31; m &= m - 1;
                float yu = yv[u];
                fba = fmaf(yu, hb[(size_t)u * LAT + lane], fba);
                fbb = fmaf(yu, hb[(size_t)u * LAT + lane + 32], fbb);
            }
        }

        float ya = (y0a - fba) / rnv;
        float yb = (y0b - fbb) / rnv;

        // Boundary guard (fp16-hh GEMM error < ~1.5e-4; window 1e-3).
        bool ta = fabsf(fabsf(ya - rintf(ya)) - 0.5f) < 1e-3f;
        bool tb = fabsf(fabsf(yb - rintf(yb)) - 0.5f) < 1e-3f;
        uint32_t ballots[2] = {__ballot_sync(0xFFFFFFFFu, ta), __ballot_sync(0xFFFFFFFFu, tb)};
#pragma unroll
        for (int h = 0; h < 2; ++h) {
            uint32_t tm = ballots[h];
            while (tm) {
                int who = __ffs(tm) - 1; tm &= tm - 1;
                int n = jb * LAT + who + h * 32;
                const float* wr = W + (size_t)r * NDIM;
                size_t mo = (size_t)n * NDIM;
                double part = 0.0;
                for (int k = jb * BSZ + lane; k < NDIM; k += 32) {
                    float mv = __half2float(g_Mt[0][mo + k]) + __half2float(g_Mt[1][mo + k]);
                    part += (double)wr[k] * (double)mv;
                }
#pragma unroll
                for (int o = 16; o; o >>= 1)
                    part += __shfl_xor_sync(0xFFFFFFFFu, part, o);
                if (lane == who) {
                    if (h == 0) y0a = (float)part; else y0b = (float)part;
                }
            }
        }
        if (ballots[0]) ya = (y0a - fba) / rnv;
        if (ballots[1]) yb = (y0b - fbb) / rnv;

        float yha = rintf(ya), yhb = rintf(yb);
        sy[jb * LAT + lane] = yha;              // overwrite Y in place
        sy[jb * LAT + lane + 32] = yhb;
        uint32_t b0 = __ballot_sync(0xFFFFFFFFu, yha != 0.f);
        uint32_t b1 = __ballot_sync(0xFFFFFFFFu, yhb != 0.f);
        if (lane == 0) {
            msk[wid][jb][0] = b0;
            msk[wid][jb][1] = b1;
        }
        if (b0 | b1) {
            flmask |= (1u << jb);
            int idx = 0;
            if (lane == 0) {
                idx = atomicAdd(&g_cnt, 1);
                g_items[idx] = (r << 5) | jb;
            }
            idx = __shfl_sync(0xFFFFFFFFu, idx, 0);
            g_yhl[(size_t)idx * LAT + lane] = yha;
            g_yhl[(size_t)idx * LAT + lane + 32] = yhb;
        }
        __syncwarp();
    }
}

// ---------------------------------------------------------------------------
// kernWhat: materialize W_hat blocks for emitted items only.
// ---------------------------------------------------------------------------
__global__ void kernWhat(const float* __restrict__ Wd) {
    __shared__ float s_y[LAT];
    int tid = threadIdx.x;
    int cnt = g_cnt;
    for (int i = blockIdx.x; i < cnt; i += gridDim.x) {
        int item = g_items[i];
        int r = item >> 5, jb = item & 31;
        if (tid < LAT) s_y[tid] = g_yhl[(size_t)i * LAT + tid];
        __syncthreads();
        float x = 0.f;
#pragma unroll 8
        for (int u = 0; u < LAT; ++u)
            x = fmaf(s_y[u], Wd[u * BSZ + tid], x);
        g_What[(size_t)r * NDIM + jb * BSZ + tid] = x;
        __syncthreads();
    }
}

// ---------------------------------------------------------------------------
// kernFillOut: out[b, m] = bias[m].
// ---------------------------------------------------------------------------
__global__ void kernFillOut(const float* __restrict__ bias, float* __restrict__ out) {
    size_t idx = ((size_t)blockIdx.x * 256 + threadIdx.x) * 4;
    int m = (int)(idx & (NDIM - 1));
    float4 bv = *reinterpret_cast<const float4*>(bias + m);
    *reinterpret_cast<float4*>(out + idx) = bv;
}

// ---------------------------------------------------------------------------
// kernSparse: out[:, r] += x[:, jb-block] @ (What[r, jb-block] * rn[r])
// Grid (32 jb, 64 b-tiles of 64), 128 threads, atomicAdd into bias-filled out.
// ---------------------------------------------------------------------------
__global__ void __launch_bounds__(128) kernSparse(const float* __restrict__ x,
                                                  const float* __restrict__ rn,
                                                  float* __restrict__ out) {
    int jb = blockIdx.x;
    int b0 = blockIdx.y * 64;
    int tid = threadIdx.x;
    __shared__ float xs[64][129];
    __shared__ float ws[128];
    __shared__ int s_any;

    int cnt = g_cnt;
    bool any = false;
    for (int i = tid; i < cnt; i += 128)
        if ((g_items[i] & 31) == jb) any = true;
    if (tid == 0) s_any = 0;
    __syncthreads();
    if (any) s_any = 1;
    __syncthreads();
    if (!s_any) return;

    for (int rr = 0; rr < 64; ++rr)
        xs[rr][tid] = x[(size_t)(b0 + rr) * NDIM + jb * BSZ + tid];
    __syncthreads();

    for (int i = 0; i < cnt; ++i) {
        int item = g_items[i];
        if ((item & 31) != jb) continue;
        int r = item >> 5;
        ws[tid] = g_What[(size_t)r * NDIM + jb * BSZ + tid] * rn[r];
        __syncthreads();
        if (tid < 64) {
            float acc = 0.f;
#pragma unroll 16
            for (int k = 0; k < BSZ; ++k)
                acc = fmaf(xs[tid][k], ws[k], acc);
            atomicAdd(&out[(size_t)(b0 + tid) * NDIM + r], acc);
        }
        __syncthreads();
    }
}

// ---------------------------------------------------------------------------
// kernel_launch: inputs (metadata order): x, weight, bias, row_norm, L, We, Wd
// ---------------------------------------------------------------------------
extern "C" void kernel_launch(void* const* d_in, const int* in_sizes, int n_in,
                              void* d_out, int out_size) {
    (void)in_sizes; (void)n_in; (void)out_size;
    const float* x      = (const float*)d_in[0];
    const float* weight = (const float*)d_in[1];
    const float* bias   = (const float*)d_in[2];
    const float* rn     = (const float*)d_in[3];
    const float* L      = (const float*)d_in[4];
    const float* We     = (const float*)d_in[5];
    const float* Wd     = (const float*)d_in[6];
    float* out          = (float*)d_out;

    static bool attr_set = false;
    if (!attr_set) {
        cudaFuncSetAttribute(kernGemmY, cudaFuncAttributeMaxDynamicSharedMemorySize, 2 * GY2_STG);
        attr_set = true;
    }

    kernPrep<<<8224, 256>>>(weight, We);                  // [0] W->fp16 hi, WeT split
    kernG<<<dim3(32, 32), 128, 33280>>>(L, We, Wd);       // [1] Mt + H fused
    kernGemmY<<<dim3(32, 16), 256, 2 * GY2_STG>>>();      // [2] Y (BK=64, 2-stage)
    kernSteps<<<1024, 128>>>(rn, weight);                 // [3] prefetched steps <- profiled
    kernWhat<<<1024, 128>>>(Wd);                          // [4] sparse W_hat blocks
    kernFillOut<<<16384, 256>>>(bias, out);               // [5] out = bias
    kernSparse<<<dim3(32, 64), 128>>>(x, rn, out);        // [6] sparse rank-updates
}

// round 17
// speedup vs baseline: 2.6860x; 1.0451x over previous
#include <cuda_runtime.h>
#include <cuda_fp16.h>
#include <cstdint>

#define NDIM 4096
#define NB   32
#define BSZ  128
#define LAT  64
#define NCOL (NB * LAT)   // 2048
#define MAXIT (NDIM * NB)

// Static device scratch.
__device__ __half g_Wh[(size_t)NDIM * NDIM];          // W fp16 hi (GEMM operand)
__device__ __half g_Mt[2][(size_t)NCOL * NDIM];       // Mt[n,k]=M[k,n]; hi/lo fp16
__device__ __half g_WeTh[2][LAT * BSZ];               // WeT[t,c]=We[c,t]; hi/lo
__device__ float g_Y[(size_t)NDIM * NCOL];
__device__ float g_H[(size_t)NB * NB * LAT * LAT];    // H[jb][jj][u][t] (jj>jb valid)
__device__ float g_What[(size_t)NDIM * NDIM];         // valid only for emitted items
__device__ int g_cnt;
__device__ int g_items[MAXIT];
__device__ float g_yhl[(size_t)MAXIT * LAT];

// ---------------------------------------------------------------------------
// Base-target helpers (sm_80+)
// ---------------------------------------------------------------------------
__device__ __forceinline__ uint32_t smem_u32(const void* p) {
    uint32_t a;
    asm("{ .reg .u64 t; cvta.to.shared.u64 t, %1; cvt.u32.u64 %0, t; }" : "=r"(a) : "l"(p));
    return a;
}
#define CP_ASYNC16(s, g) asm volatile("cp.async.cg.shared.global [%0], [%1], 16;" :: "r"(s), "l"(g))
#define CP_COMMIT()      asm volatile("cp.async.commit_group;" ::: "memory")
#define CP_WAIT(n)       asm volatile("cp.async.wait_group %0;" :: "n"(n) : "memory")

__device__ __forceinline__ void ldm_x4(uint32_t addr, uint32_t r[4]) {
    asm volatile("ldmatrix.sync.aligned.m8n8.x4.shared.b16 {%0,%1,%2,%3}, [%4];"
                 : "=r"(r[0]), "=r"(r[1]), "=r"(r[2]), "=r"(r[3]) : "r"(addr));
}
__device__ __forceinline__ void mma_f16(float* c, const uint32_t a[4], uint32_t b0, uint32_t b1) {
    asm volatile(
        "mma.sync.aligned.m16n8k16.row.col.f32.f16.f16.f32 "
        "{%0,%1,%2,%3}, {%4,%5,%6,%7}, {%8,%9}, {%0,%1,%2,%3};"
        : "+f"(c[0]), "+f"(c[1]), "+f"(c[2]), "+f"(c[3])
        : "r"(a[0]), "r"(a[1]), "r"(a[2]), "r"(a[3]), "r"(b0), "r"(b1));
}
__device__ __forceinline__ void split2h(float v, __half& hi, __half& lo) {
    hi = __float2half_rn(v);
    lo = __float2half_rn(v - __half2float(hi));
}

#define RS 80    // smem row stride for BK=32 tiles (64B + 16 pad)
#define RS2 144  // smem row stride for BK=64 tiles (128B + 16 pad)

// ---------------------------------------------------------------------------
// kernPrep: W fp32 -> fp16 hi (blocks 0..8191), WeT split (8192..8223).
// ---------------------------------------------------------------------------
__global__ void kernPrep(const float* __restrict__ W, const float* __restrict__ We) {
    int b = blockIdx.x;
    if (b < 8192) {
        size_t idx = (size_t)b * 256 + threadIdx.x;   // per 8 elems
        const float4* s = reinterpret_cast<const float4*>(W) + idx * 2;
        float4 a = s[0], c = s[1];
        float v[8] = {a.x, a.y, a.z, a.w, c.x, c.y, c.z, c.w};
        __half h[8];
#pragma unroll
        for (int q = 0; q < 8; ++q) h[q] = __float2half_rn(v[q]);
        *reinterpret_cast<uint4*>(g_Wh + idx * 8) = *reinterpret_cast<uint4*>(h);
    } else {
        int idx = (b - 8192) * 256 + threadIdx.x;     // 0..8191
        int t = idx >> 7, c = idx & 127;
        __half h, l;
        split2h(We[c * LAT + t], h, l);
        g_WeTh[0][idx] = h;
        g_WeTh[1][idx] = l;
    }
}

// ---------------------------------------------------------------------------
// kernG (FUSED with H): builds the FULL Mt (fp16 hi+lo) AND H[jb][jj].
//   kt > j : G block via 3-term split fp16 HMMA -> Mt; then H = Wd @ G.
//   kt == j: diagonal We block (split).  kt < j : zero fill (+ g_cnt reset).
// Grid (32 kt, 32 j), 128 threads, dyn smem 33280 B.
// ---------------------------------------------------------------------------
__global__ void __launch_bounds__(128, 4) kernG(const float* __restrict__ L,
                                                const float* __restrict__ We,
                                                const float* __restrict__ Wd) {
    int kt = blockIdx.x, j = blockIdx.y;
    int tid = threadIdx.x;
    int jn = j * LAT, s = j * BSZ;

    if (kt < j) {
        if (kt == 0 && j == 1 && tid == 0) g_cnt = 0;
        uint4 z = make_uint4(0, 0, 0, 0);
        for (int i = tid; i < 64 * 16; i += 128) {
            int rr = i >> 4, c = i & 15;
            size_t o = (size_t)(jn + rr) * NDIM + kt * BSZ + c * 8;
            *reinterpret_cast<uint4*>(g_Mt[0] + o) = z;
            *reinterpret_cast<uint4*>(g_Mt[1] + o) = z;
        }
        return;
    }
    if (kt == j) {
        for (int n = 0; n < LAT; ++n) {
            __half h, l;
            split2h(We[tid * LAT + n], h, l);
            size_t o = (size_t)(jn + n) * NDIM + s + tid;
            g_Mt[0][o] = h;
            g_Mt[1][o] = l;
        }
        return;
    }

    extern __shared__ __align__(128) char sm[];
    uint32_t sb = smem_u32(sm);
    uint32_t sA[2] = {sb, sb + 5120};
    uint32_t sB[2] = {sb + 10240, sb + 20480};
    int wid = tid >> 5, lane = tid & 31;
    int k0g = kt * BSZ;
    int wm = (wid & 1) * 32, wn = (wid >> 1) * 64;

    float acc[2][8][4];
#pragma unroll
    for (int i = 0; i < 2; ++i)
#pragma unroll
        for (int q = 0; q < 8; ++q)
#pragma unroll
            for (int z = 0; z < 4; ++z) acc[i][q][z] = 0.f;

    for (int it = 0; it < 4; ++it) {            // K=128, BK=32
        int kk = it * 32;
#pragma unroll
        for (int q = 0; q < 4; ++q) {
            int id = tid + q * 128;
            int prec = id >> 8, rem = id & 255, row = rem >> 2, ch = rem & 3;
            CP_ASYNC16(sA[prec] + row * RS + ch * 16,
                       g_WeTh[prec] + row * BSZ + kk + ch * 8);
        }
        CP_COMMIT();
#pragma unroll
        for (int q = 0; q < 8; ++q) {           // B: L fp32 -> split fp16 in-reg
            int id = tid + q * 128;
            int row = id >> 3, c = (id & 7) * 4;
            float4 v = *reinterpret_cast<const float4*>(
                L + (size_t)(k0g + row) * NDIM + s + kk + c);
            __half h0, l0, h1, l1, h2, l2, h3, l3;
            split2h(v.x, h0, l0); split2h(v.y, h1, l1);
            split2h(v.z, h2, l2); split2h(v.w, h3, l3);
            __half2 hA = __halves2half2(h0, h1), hB = __halves2half2(h2, h3);
            __half2 lA = __halves2half2(l0, l1), lB = __halves2half2(l2, l3);
            uint2 uh, ul;
            uh.x = *reinterpret_cast<uint32_t*>(&hA); uh.y = *reinterpret_cast<uint32_t*>(&hB);
            ul.x = *reinterpret_cast<uint32_t*>(&lA); ul.y = *reinterpret_cast<uint32_t*>(&lB);
            *reinterpret_cast<uint2*>(sm + 10240 + row * RS + c * 2) = uh;
            *reinterpret_cast<uint2*>(sm + 20480 + row * RS + c * 2) = ul;
        }
        CP_WAIT(0);
        __syncthreads();

#pragma unroll
        for (int ks = 0; ks < 2; ++ks) {
            uint32_t ah[2][4];
#pragma unroll
            for (int mf = 0; mf < 2; ++mf)
                ldm_x4(sA[0] + (wm + mf * 16 + (lane & 15)) * RS + ks * 32 + (lane >> 4) * 16, ah[mf]);
            uint32_t bh[8][2];
#pragma unroll
            for (int p = 0; p < 4; ++p) {
                uint32_t r[4];
                int g = lane >> 3;
                int row = wn + p * 16 + ((g >> 1) << 3) + (lane & 7);
                ldm_x4(sB[0] + row * RS + ks * 32 + (g & 1) * 16, r);
                bh[p * 2][0] = r[0]; bh[p * 2][1] = r[1];
                bh[p * 2 + 1][0] = r[2]; bh[p * 2 + 1][1] = r[3];
            }
#pragma unroll
            for (int mf = 0; mf < 2; ++mf)
#pragma unroll
                for (int nf = 0; nf < 8; ++nf)
                    mma_f16(acc[mf][nf], ah[mf], bh[nf][0], bh[nf][1]);
            uint32_t al[2][4];
#pragma unroll
            for (int mf = 0; mf < 2; ++mf)
                ldm_x4(sA[1] + (wm + mf * 16 + (lane & 15)) * RS + ks * 32 + (lane >> 4) * 16, al[mf]);
#pragma unroll
            for (int mf = 0; mf < 2; ++mf)
#pragma unroll
                for (int nf = 0; nf < 8; ++nf)
                    mma_f16(acc[mf][nf], al[mf], bh[nf][0], bh[nf][1]);
            uint32_t bl[8][2];
#pragma unroll
            for (int p = 0; p < 4; ++p) {
                uint32_t r[4];
                int g = lane >> 3;
                int row = wn + p * 16 + ((g >> 1) << 3) + (lane & 7);
                ldm_x4(sB[1] + row * RS + ks * 32 + (g & 1) * 16, r);
                bl[p * 2][0] = r[0]; bl[p * 2][1] = r[1];
                bl[p * 2 + 1][0] = r[2]; bl[p * 2 + 1][1] = r[3];
            }
#pragma unroll
            for (int mf = 0; mf < 2; ++mf)
#pragma unroll
                for (int nf = 0; nf < 8; ++nf)
                    mma_f16(acc[mf][nf], ah[mf], bl[nf][0], bl[nf][1]);
        }
        __syncthreads();
    }

    // Store split(G) -> Mt
#pragma unroll
    for (int mf = 0; mf < 2; ++mf) {
        int t0 = wm + mf * 16 + (lane >> 2);
#pragma unroll
        for (int nf = 0; nf < 8; ++nf) {
            int kr = wn + nf * 8 + 2 * (lane & 3);
            __half h0, l0, h1, l1, h2, l2, h3, l3;
            split2h(acc[mf][nf][0], h0, l0);
            split2h(acc[mf][nf][1], h1, l1);
            split2h(acc[mf][nf][2], h2, l2);
            split2h(acc[mf][nf][3], h3, l3);
            size_t o0 = (size_t)(jn + t0) * NDIM + k0g + kr;
            size_t o1 = (size_t)(jn + t0 + 8) * NDIM + k0g + kr;
            *reinterpret_cast<__half2*>(g_Mt[0] + o0) = __halves2half2(h0, h1);
            *reinterpret_cast<__half2*>(g_Mt[1] + o0) = __halves2half2(l0, l1);
            *reinterpret_cast<__half2*>(g_Mt[0] + o1) = __halves2half2(h2, h3);
            *reinterpret_cast<__half2*>(g_Mt[1] + o1) = __halves2half2(l2, l3);
        }
    }

    // ---- Fused H phase: H[j][kt][u][t] = sum_c Wd[u][c] * G[c][t] ----
    float* Gs  = reinterpret_cast<float*>(sm);           // [64][65]
    float* Wds = reinterpret_cast<float*>(sm) + 64 * 65; // [64][65]
    int tu = tid >> 4, tt = tid & 15;
    float acc2[8][4];
#pragma unroll
    for (int i = 0; i < 8; ++i)
#pragma unroll
        for (int q = 0; q < 4; ++q) acc2[i][q] = 0.f;

    for (int cc = 0; cc < 2; ++cc) {
        __syncthreads();
        if (wn == cc * 64) {
#pragma unroll
            for (int mf = 0; mf < 2; ++mf) {
                int t0 = wm + mf * 16 + (lane >> 2);
#pragma unroll
                for (int nf = 0; nf < 8; ++nf) {
                    int krl = nf * 8 + 2 * (lane & 3);
                    Gs[(krl)     * 65 + t0]     = acc[mf][nf][0];
                    Gs[(krl + 1) * 65 + t0]     = acc[mf][nf][1];
                    Gs[(krl)     * 65 + t0 + 8] = acc[mf][nf][2];
                    Gs[(krl + 1) * 65 + t0 + 8] = acc[mf][nf][3];
                }
            }
        }
#pragma unroll
        for (int i = 0; i < 8; ++i) {
            int idx = i * 128 + tid;
            int u = idx >> 4, cq = (idx & 15) * 4;
            float4 wv = *reinterpret_cast<const float4*>(Wd + u * BSZ + cc * 64 + cq);
            Wds[u * 65 + cq + 0] = wv.x; Wds[u * 65 + cq + 1] = wv.y;
            Wds[u * 65 + cq + 2] = wv.z; Wds[u * 65 + cq + 3] = wv.w;
        }
        __syncthreads();
#pragma unroll 4
        for (int c = 0; c < 64; ++c) {
            float w[8], g[4];
#pragma unroll
            for (int i = 0; i < 8; ++i) w[i] = Wds[(tu * 8 + i) * 65 + c];
#pragma unroll
            for (int q = 0; q < 4; ++q) g[q] = Gs[c * 65 + tt * 4 + q];
#pragma unroll
            for (int i = 0; i < 8; ++i)
#pragma unroll
                for (int q = 0; q < 4; ++q)
                    acc2[i][q] = fmaf(w[i], g[q], acc2[i][q]);
        }
    }

    size_t hb = (((size_t)j * NB + kt) * LAT) * LAT;
#pragma unroll
    for (int i = 0; i < 8; ++i)
#pragma unroll
        for (int q = 0; q < 4; ++q)
            g_H[hb + (size_t)(tu * 8 + i) * LAT + tt * 4 + q] = acc2[i][q];
}

// ---------------------------------------------------------------------------
// kernGemmY: Y = W @ M^T, SINGLE fp16 hh HMMA pass, fp32 accum. BK=64.
// Double-buffered cp.async (2 x 36864 B dyn smem). Guarded by kernSteps.
// ---------------------------------------------------------------------------
#define GY2_TSZ (128 * RS2)          // 18432
#define GY2_STG (2 * GY2_TSZ)        // 36864
__global__ void __launch_bounds__(256, 2) kernGemmY() {
    extern __shared__ __align__(128) char sm[];
    uint32_t sb = smem_u32(sm);
    int tid = threadIdx.x, wid = tid >> 5, lane = tid & 31;
    int m0 = blockIdx.x * 128, n0 = blockIdx.y * 128;
    int kst = n0 * 2;
    int niter = (NDIM - kst) / 64;
    int wm = (wid & 1) * 64, wn = (wid >> 1) * 32;

    float acc[4][4][4];
#pragma unroll
    for (int i = 0; i < 4; ++i)
#pragma unroll
        for (int q = 0; q < 4; ++q)
#pragma unroll
            for (int z = 0; z < 4; ++z) acc[i][q][z] = 0.f;

    auto issue = [&](int it) {
        int k0 = kst + it * 64;
        uint32_t s_a = sb + (it & 1) * GY2_STG, s_b = s_a + GY2_TSZ;
#pragma unroll
        for (int q = 0; q < 4; ++q) {
            int id = tid + q * 256, row = id >> 3, ch = id & 7;
            CP_ASYNC16(s_a + row * RS2 + ch * 16, g_Wh + (size_t)(m0 + row) * NDIM + k0 + ch * 8);
            CP_ASYNC16(s_b + row * RS2 + ch * 16, g_Mt[0] + (size_t)(n0 + row) * NDIM + k0 + ch * 8);
        }
        CP_COMMIT();
    };

    issue(0);
    for (int it = 0; it < niter; ++it) {
        if (it + 1 < niter) { issue(it + 1); CP_WAIT(1); }
        else                { CP_WAIT(0); }
        __syncthreads();
        uint32_t s_a = sb + (it & 1) * GY2_STG, s_b = s_a + GY2_TSZ;
#pragma unroll
        for (int ks = 0; ks < 4; ++ks) {
            uint32_t a[4][4];
#pragma unroll
            for (int mf = 0; mf < 4; ++mf)
                ldm_x4(s_a + (wm + mf * 16 + (lane & 15)) * RS2 + ks * 32 + (lane >> 4) * 16, a[mf]);
            uint32_t b[4][2];
#pragma unroll
            for (int p = 0; p < 2; ++p) {
                uint32_t r[4];
                int g = lane >> 3;
                int row = wn + p * 16 + ((g >> 1) << 3) + (lane & 7);
                ldm_x4(s_b + row * RS2 + ks * 32 + (g & 1) * 16, r);
                b[p * 2][0] = r[0]; b[p * 2][1] = r[1];
                b[p * 2 + 1][0] = r[2]; b[p * 2 + 1][1] = r[3];
            }
#pragma unroll
            for (int mf = 0; mf < 4; ++mf)
#pragma unroll
                for (int nf = 0; nf < 4; ++nf)
                    mma_f16(acc[mf][nf], a[mf], b[nf][0], b[nf][1]);
        }
        __syncthreads();
    }

#pragma unroll
    for (int mf = 0; mf < 4; ++mf) {
        int row = m0 + wm + mf * 16 + (lane >> 2);
#pragma unroll
        for (int nf = 0; nf < 4; ++nf) {
            int col = n0 + wn + nf * 8 + 2 * (lane & 3);
            *reinterpret_cast<float2*>(g_Y + (size_t)row * NCOL + col) =
                make_float2(acc[mf][nf][0], acc[mf][nf][1]);
            *reinterpret_cast<float2*>(g_Y + (size_t)(row + 8) * NCOL + col) =
                make_float2(acc[mf][nf][2], acc[mf][nf][3]);
        }
    }
}

// ---------------------------------------------------------------------------
// kernSteps v6: warp-per-row latent recurrence, FORWARD-SUBSTITUTION form.
// Y prefetched to shared; when step jb emits nonzero yhat, its feedback is
// immediately scattered into sy[jjb] for all jjb < jb (independent loads,
// MLP-pipelined). Common path per step: zero global loads, zero chains.
// Guard (1e-3): gather fb from masks (rare) + warp fp64 exact dot.
// Grid 1024, block 128 (4 warps = 4 rows). smem ~33KB.
// ---------------------------------------------------------------------------
__global__ void __launch_bounds__(128) kernSteps(const float* __restrict__ rn,
                                                 const float* __restrict__ W) {
    __shared__ float sY[4][NCOL];           // Y -> (overwritten) yhat
    __shared__ uint32_t msk[4][NB][2];

    int tid = threadIdx.x, wid = tid >> 5, lane = tid & 31;
    int rbase = blockIdx.x * 4;
    int r = rbase + wid;

    {   // prefetch 4 rows of Y (32KB) via cp.async burst
        uint32_t sbase = smem_u32(&sY[0][0]);
#pragma unroll
        for (int q = 0; q < 16; ++q) {
            int id = tid + q * 128;
            int row = id >> 9, ch = id & 511;
            CP_ASYNC16(sbase + id * 16, g_Y + (size_t)(rbase + row) * NCOL + ch * 4);
        }
        CP_COMMIT();
        CP_WAIT(0);
        __syncthreads();
    }

    float rnv = rn[r];
    float* sy = sY[wid];
    uint32_t flmask = 0;

    for (int jb = NB - 1; jb >= 0; --jb) {
        float ya = sy[jb * LAT + lane] / rnv;        // feedback already applied
        float yb = sy[jb * LAT + lane + 32] / rnv;

        // Boundary guard (rare): exact fp64 recompute + fb gather from masks.
        bool ta = fabsf(fabsf(ya - rintf(ya)) - 0.5f) < 1e-3f;
        bool tb = fabsf(fabsf(yb - rintf(yb)) - 0.5f) < 1e-3f;
        uint32_t tba = __ballot_sync(0xFFFFFFFFu, ta);
        uint32_t tbb = __ballot_sync(0xFFFFFFFFu, tb);
        if (tba | tbb) {
            // gather full feedback for all lanes (as in the gather formulation)
            float fba = 0.f, fbb = 0.f;
            uint32_t fm = flmask;
            while (fm) {
                int jj = __ffs(fm) - 1; fm &= fm - 1;
                const float* hb = g_H + ((size_t)(jb * NB + jj) * LAT) * LAT;
                const float* yv = &sy[jj * LAT];
                uint32_t m = msk[wid][jj][0];
                while (m) {
                    int u = __ffs(m) - 1; m &= m - 1;
                    float yu = yv[u];
                    fba = fmaf(yu, hb[(size_t)u * LAT + lane], fba);
                    fbb = fmaf(yu, hb[(size_t)u * LAT + lane + 32], fbb);
                }
                m = msk[wid][jj][1];
                while (m) {
                    int u = __ffs(m) + 31; m &= m - 1;
                    float yu = yv[u];
                    fba = fmaf(yu, hb[(size_t)u * LAT + lane], fba);
                    fbb = fmaf(yu, hb[(size_t)u * LAT + lane + 32], fbb);
                }
            }
            uint32_t ballots[2] = {tba, tbb};
#pragma unroll
            for (int h = 0; h < 2; ++h) {
                uint32_t tm = ballots[h];
                while (tm) {
                    int who = __ffs(tm) - 1; tm &= tm - 1;
                    int n = jb * LAT + who + h * 32;
                    const float* wr = W + (size_t)r * NDIM;
                    size_t mo = (size_t)n * NDIM;
                    double p0 = 0.0, p1 = 0.0;
                    for (int k = jb * BSZ + lane; k < NDIM; k += 64) {
                        float m1 = __half2float(g_Mt[0][mo + k]) + __half2float(g_Mt[1][mo + k]);
                        float m2 = __half2float(g_Mt[0][mo + k + 32]) + __half2float(g_Mt[1][mo + k + 32]);
                        p0 += (double)wr[k] * (double)m1;
                        p1 += (double)wr[k + 32] * (double)m2;
                    }
                    double part = p0 + p1;
#pragma unroll
                    for (int o = 16; o; o >>= 1)
                        part += __shfl_xor_sync(0xFFFFFFFFu, part, o);
                    if (lane == who) {
                        float yex = ((float)part - (h == 0 ? fba : fbb)) / rnv;
                        if (h == 0) ya = yex; else yb = yex;
                    }
                }
            }
        }

        float yha = rintf(ya), yhb = rintf(yb);
        sy[jb * LAT + lane] = yha;                   // overwrite Y with yhat
        sy[jb * LAT + lane + 32] = yhb;
        uint32_t b0 = __ballot_sync(0xFFFFFFFFu, yha != 0.f);
        uint32_t b1 = __ballot_sync(0xFFFFFFFFu, yhb != 0.f);
        if (b0 | b1) {
            flmask |= (1u << jb);
            if (lane == 0) {
                msk[wid][jb][0] = b0;
                msk[wid][jb][1] = b1;
            }
            int idx = 0;
            if (lane == 0) {
                idx = atomicAdd(&g_cnt, 1);
                g_items[idx] = (r << 5) | jb;
            }
            idx = __shfl_sync(0xFFFFFFFFu, idx, 0);
            g_yhl[(size_t)idx * LAT + lane] = yha;
            g_yhl[(size_t)idx * LAT + lane + 32] = yhb;
            __syncwarp();
            // Forward-scatter: sy[jjb] -= sum_u yhat_u * H[jjb][jb][u][:], jjb < jb.
            uint32_t um = b0;
            while (um) {
                int u = __ffs(um) - 1; um &= um - 1;
                float yu = sy[jb * LAT + u];
                const float* hu = g_H + ((size_t)jb * LAT + u) * LAT;   // + jjb*NB*LAT*LAT
#pragma unroll 4
                for (int jjb = 0; jjb < jb; ++jjb) {
                    const float* hp = hu + (size_t)jjb * (NB * LAT * LAT);
                    float hA = hp[lane], hB = hp[lane + 32];
                    sy[jjb * LAT + lane]      -= yu * hA;
                    sy[jjb * LAT + lane + 32] -= yu * hB;
                }
            }
            um = b1;
            while (um) {
                int u = __ffs(um) + 31; um &= um - 1;
                float yu = sy[jb * LAT + u];
                const float* hu = g_H + ((size_t)jb * LAT + u) * LAT;
#pragma unroll 4
                for (int jjb = 0; jjb < jb; ++jjb) {
                    const float* hp = hu + (size_t)jjb * (NB * LAT * LAT);
                    float hA = hp[lane], hB = hp[lane + 32];
                    sy[jjb * LAT + lane]      -= yu * hA;
                    sy[jjb * LAT + lane + 32] -= yu * hB;
                }
            }
        }
        __syncwarp();
    }
}

// ---------------------------------------------------------------------------
// kernWhat: materialize W_hat blocks for emitted items only.
// ---------------------------------------------------------------------------
__global__ void kernWhat(const float* __restrict__ Wd) {
    __shared__ float s_y[LAT];
    int tid = threadIdx.x;
    int cnt = g_cnt;
    for (int i = blockIdx.x; i < cnt; i += gridDim.x) {
        int item = g_items[i];
        int r = item >> 5, jb = item & 31;
        if (tid < LAT) s_y[tid] = g_yhl[(size_t)i * LAT + tid];
        __syncthreads();
        float x = 0.f;
#pragma unroll 8
        for (int u = 0; u < LAT; ++u)
            x = fmaf(s_y[u], Wd[u * BSZ + tid], x);
        g_What[(size_t)r * NDIM + jb * BSZ + tid] = x;
        __syncthreads();
    }
}

// ---------------------------------------------------------------------------
// kernFillOut: out[b, m] = bias[m].
// ---------------------------------------------------------------------------
__global__ void kernFillOut(const float* __restrict__ bias, float* __restrict__ out) {
    size_t idx = ((size_t)blockIdx.x * 256 + threadIdx.x) * 4;
    int m = (int)(idx & (NDIM - 1));
    float4 bv = *reinterpret_cast<const float4*>(bias + m);
    *reinterpret_cast<float4*>(out + idx) = bv;
}

// ---------------------------------------------------------------------------
// kernSparse: out[:, r] += x[:, jb-block] @ (What[r, jb-block] * rn[r])
// Grid (32 jb, 64 b-tiles of 64), 128 threads, atomicAdd into bias-filled out.
// ---------------------------------------------------------------------------
__global__ void __launch_bounds__(128) kernSparse(const float* __restrict__ x,
                                                  const float* __restrict__ rn,
                                                  float* __restrict__ out) {
    int jb = blockIdx.x;
    int b0 = blockIdx.y * 64;
    int tid = threadIdx.x;
    __shared__ float xs[64][129];
    __shared__ float ws[128];
    __shared__ int s_any;

    int cnt = g_cnt;
    bool any = false;
    for (int i = tid; i < cnt; i += 128)
        if ((g_items[i] & 31) == jb) any = true;
    if (tid == 0) s_any = 0;
    __syncthreads();
    if (any) s_any = 1;
    __syncthreads();
    if (!s_any) return;

    for (int rr = 0; rr < 64; ++rr)
        xs[rr][tid] = x[(size_t)(b0 + rr) * NDIM + jb * BSZ + tid];
    __syncthreads();

    for (int i = 0; i < cnt; ++i) {
        int item = g_items[i];
        if ((item & 31) != jb) continue;
        int r = item >> 5;
        ws[tid] = g_What[(size_t)r * NDIM + jb * BSZ + tid] * rn[r];
        __syncthreads();
        if (tid < 64) {
            float acc = 0.f;
#pragma unroll 16
            for (int k = 0; k < BSZ; ++k)
                acc = fmaf(xs[tid][k], ws[k], acc);
            atomicAdd(&out[(size_t)(b0 + tid) * NDIM + r], acc);
        }
        __syncthreads();
    }
}

// ---------------------------------------------------------------------------
// kernel_launch: inputs (metadata order): x, weight, bias, row_norm, L, We, Wd
// ---------------------------------------------------------------------------
extern "C" void kernel_launch(void* const* d_in, const int* in_sizes, int n_in,
                              void* d_out, int out_size) {
    (void)in_sizes; (void)n_in; (void)out_size;
    const float* x      = (const float*)d_in[0];
    const float* weight = (const float*)d_in[1];
    const float* bias   = (const float*)d_in[2];
    const float* rn     = (const float*)d_in[3];
    const float* L      = (const float*)d_in[4];
    const float* We     = (const float*)d_in[5];
    const float* Wd     = (const float*)d_in[6];
    float* out          = (float*)d_out;

    static bool attr_set = false;
    if (!attr_set) {
        cudaFuncSetAttribute(kernGemmY, cudaFuncAttributeMaxDynamicSharedMemorySize, 2 * GY2_STG);
        attr_set = true;
    }

    kernPrep<<<8224, 256>>>(weight, We);                  // [0] W->fp16 hi, WeT split
    kernG<<<dim3(32, 32), 128, 33280>>>(L, We, Wd);       // [1] Mt + H fused
    kernGemmY<<<dim3(32, 16), 256, 2 * GY2_STG>>>();      // [2] Y (BK=64, 2-stage)
    kernSteps<<<1024, 128>>>(rn, weight);                 // [3] forward-subst  <- profiled
    kernWhat<<<1024, 128>>>(Wd);                          // [4] sparse W_hat blocks
    kernFillOut<<<16384, 256>>>(bias, out);               // [5] out = bias
    kernSparse<<<dim3(32, 64), 128>>>(x, rn, out);        // [6] sparse rank-updates
}